// round 1
// baseline (speedup 1.0000x reference)
#include <cuda_runtime.h>
#include <math.h>

#define TOK   8192      // 4 * 2048 tokens
#define DM    1024
#define DFF   4096
#define NH    16
#define DK    64
#define SEQ   2048
#define BATCH 4

// ---------------- scratch (static device globals; no allocation) ----------------
__device__ float g_h  [TOK * DM];
__device__ float g_q  [TOK * DM];
__device__ float g_k  [TOK * DM];
__device__ float g_v  [TOK * DM];
__device__ float g_ctx[TOK * DM];
__device__ float g_x1 [TOK * DM];
__device__ float g_h2 [TOK * DM];
__device__ float g_ff [TOK * DFF];

// ---------------- LayerNorm: one block per row of 1024 ----------------
__global__ void __launch_bounds__(256) ln_kernel(const float* __restrict__ x,
                                                 const float* __restrict__ g,
                                                 const float* __restrict__ b,
                                                 float* __restrict__ out)
{
    const int row = blockIdx.x;
    const int tid = threadIdx.x;   // 256 threads, 4 floats each
    const float4 v = ((const float4*)(x + (size_t)row * DM))[tid];

    float s  = v.x + v.y + v.z + v.w;
    float ss = v.x * v.x + v.y * v.y + v.z * v.z + v.w * v.w;
    #pragma unroll
    for (int o = 16; o; o >>= 1) {
        s  += __shfl_xor_sync(0xffffffffu, s,  o);
        ss += __shfl_xor_sync(0xffffffffu, ss, o);
    }
    __shared__ float sb[8], sb2[8];
    if ((tid & 31) == 0) { sb[tid >> 5] = s; sb2[tid >> 5] = ss; }
    __syncthreads();
    float ts = 0.f, ts2 = 0.f;
    #pragma unroll
    for (int i = 0; i < 8; i++) { ts += sb[i]; ts2 += sb2[i]; }

    const float mu  = ts * (1.0f / DM);
    const float var = ts2 * (1.0f / DM) - mu * mu;
    const float inv = rsqrtf(var + 1e-5f);

    const float4 gg = ((const float4*)g)[tid];
    const float4 bb = ((const float4*)b)[tid];
    float4 o;
    o.x = (v.x - mu) * inv * gg.x + bb.x;
    o.y = (v.y - mu) * inv * gg.y + bb.y;
    o.z = (v.z - mu) * inv * gg.z + bb.z;
    o.w = (v.w - mu) * inv * gg.w + bb.w;
    ((float4*)(out + (size_t)row * DM))[tid] = o;
}

// ---------------- SGEMM 128x128x8, TM=TN=8, 256 threads ----------------
// EPI: 0 = C = A*B + bias
//      1 = C = res + (A*B + bias)
//      2 = C = gelu_exact(A*B + bias)
__device__ __forceinline__ float gelu_exact(float v) {
    return 0.5f * v * (1.0f + erff(v * 0.70710678118654752440f));
}

template <int EPI>
__global__ void __launch_bounds__(256) sgemm_kernel(
    const float* __restrict__ A, const float* __restrict__ B,
    const float* __restrict__ bias, const float* __restrict__ res,
    float* __restrict__ C, int M, int N, int K)
{
    __shared__ float As[8 * 128];   // transposed: As[k][m]
    __shared__ float Bs[8 * 128];   // Bs[k][n]

    const int tid = threadIdx.x;
    const int bx = blockIdx.x, by = blockIdx.y;

    const int rowA = tid >> 1;            // 0..127
    const int colA = (tid & 1) << 2;      // 0 or 4
    const int rowB = tid >> 5;            // 0..7
    const int colB = (tid & 31) << 2;     // 0..124

    const float* Aptr = A + (size_t)(by * 128 + rowA) * K + colA;
    const float* Bptr = B + (size_t)rowB * N + bx * 128 + colB;

    const int tx = tid & 15, ty = tid >> 4;
    float acc[8][8] = {};

    for (int kt = 0; kt < K; kt += 8) {
        const float4 a4 = *(const float4*)(Aptr + kt);
        const float4 b4 = *(const float4*)(Bptr + (size_t)kt * N);
        As[(colA + 0) * 128 + rowA] = a4.x;
        As[(colA + 1) * 128 + rowA] = a4.y;
        As[(colA + 2) * 128 + rowA] = a4.z;
        As[(colA + 3) * 128 + rowA] = a4.w;
        *(float4*)&Bs[rowB * 128 + colB] = b4;
        __syncthreads();

        #pragma unroll
        for (int k = 0; k < 8; k++) {
            float ra[8], rb[8];
            *(float4*)&ra[0] = *(float4*)&As[k * 128 + ty * 8];
            *(float4*)&ra[4] = *(float4*)&As[k * 128 + ty * 8 + 4];
            *(float4*)&rb[0] = *(float4*)&Bs[k * 128 + tx * 8];
            *(float4*)&rb[4] = *(float4*)&Bs[k * 128 + tx * 8 + 4];
            #pragma unroll
            for (int i = 0; i < 8; i++)
                #pragma unroll
                for (int j = 0; j < 8; j++)
                    acc[i][j] += ra[i] * rb[j];
        }
        __syncthreads();
    }

    // epilogue
    const int col0 = bx * 128 + tx * 8;
    const float4 bv0 = *(const float4*)(bias + col0);
    const float4 bv1 = *(const float4*)(bias + col0 + 4);
    #pragma unroll
    for (int i = 0; i < 8; i++) {
        const int row = by * 128 + ty * 8 + i;
        float4 o0, o1;
        o0.x = acc[i][0] + bv0.x; o0.y = acc[i][1] + bv0.y;
        o0.z = acc[i][2] + bv0.z; o0.w = acc[i][3] + bv0.w;
        o1.x = acc[i][4] + bv1.x; o1.y = acc[i][5] + bv1.y;
        o1.z = acc[i][6] + bv1.z; o1.w = acc[i][7] + bv1.w;
        if (EPI == 2) {
            o0.x = gelu_exact(o0.x); o0.y = gelu_exact(o0.y);
            o0.z = gelu_exact(o0.z); o0.w = gelu_exact(o0.w);
            o1.x = gelu_exact(o1.x); o1.y = gelu_exact(o1.y);
            o1.z = gelu_exact(o1.z); o1.w = gelu_exact(o1.w);
        }
        if (EPI == 1) {
            const float4 r0 = *(const float4*)(res + (size_t)row * N + col0);
            const float4 r1 = *(const float4*)(res + (size_t)row * N + col0 + 4);
            o0.x += r0.x; o0.y += r0.y; o0.z += r0.z; o0.w += r0.w;
            o1.x += r1.x; o1.y += r1.y; o1.z += r1.z; o1.w += r1.w;
        }
        *(float4*)(C + (size_t)row * N + col0)     = o0;
        *(float4*)(C + (size_t)row * N + col0 + 4) = o1;
    }
}

// ---------------- Flash attention: one block per (b, h, 64-row q-tile) ----------------
// q/k/v layout: [B*S, H*DK] row-major (head h occupies cols h*64..h*64+63)
#define ATTN_SMEM_FLOATS (64*64 + 64*65 + 64*64 + 64*65)

__global__ void __launch_bounds__(256) attn_kernel(const float* __restrict__ q,
                                                   const float* __restrict__ k,
                                                   const float* __restrict__ v,
                                                   float* __restrict__ out)
{
    extern __shared__ float sm[];
    float* Qs = sm;                 // [64][64] (broadcast reads; no pad needed)
    float* Ks = Qs + 64 * 64;       // [64][65]
    float* Vs = Ks + 64 * 65;       // [64][64]
    float* Ps = Vs + 64 * 64;       // [64][65]

    const int tid = threadIdx.x;
    const int qt = blockIdx.x, h = blockIdx.y, b = blockIdx.z;
    const int tx = tid & 15, ty = tid >> 4;
    const float scale = 0.125f;     // 1/sqrt(64)

    // load + scale Q tile
    const float* qbase = q + ((size_t)(b * SEQ + qt * 64)) * DM + h * DK;
    for (int i = tid; i < 64 * 16; i += 256) {
        const int r = i >> 4, c4 = (i & 15) << 2;
        const float4 t = *(const float4*)(qbase + (size_t)r * DM + c4);
        Qs[r * 64 + c4 + 0] = t.x * scale;
        Qs[r * 64 + c4 + 1] = t.y * scale;
        Qs[r * 64 + c4 + 2] = t.z * scale;
        Qs[r * 64 + c4 + 3] = t.w * scale;
    }

    float m[4], l[4], acc[4][4];
    #pragma unroll
    for (int r = 0; r < 4; r++) {
        m[r] = -1e30f; l[r] = 0.f;
        #pragma unroll
        for (int c = 0; c < 4; c++) acc[r][c] = 0.f;
    }

    const float* kb = k + ((size_t)(b * SEQ)) * DM + h * DK;
    const float* vb = v + ((size_t)(b * SEQ)) * DM + h * DK;

    for (int kt = 0; kt < SEQ / 64; kt++) {
        __syncthreads();
        const float* kp = kb + (size_t)kt * 64 * DM;
        const float* vp = vb + (size_t)kt * 64 * DM;
        for (int i = tid; i < 64 * 16; i += 256) {
            const int r = i >> 4, c4 = (i & 15) << 2;
            const float4 t = *(const float4*)(kp + (size_t)r * DM + c4);
            Ks[r * 65 + c4 + 0] = t.x;
            Ks[r * 65 + c4 + 1] = t.y;
            Ks[r * 65 + c4 + 2] = t.z;
            Ks[r * 65 + c4 + 3] = t.w;
            const float4 u = *(const float4*)(vp + (size_t)r * DM + c4);
            *(float4*)&Vs[r * 64 + c4] = u;
        }
        __syncthreads();

        // S = Qs @ Ks^T  (4x4 per thread)
        float s[4][4] = {};
        #pragma unroll 4
        for (int d = 0; d < DK; d++) {
            float qr[4], kc[4];
            #pragma unroll
            for (int r = 0; r < 4; r++) qr[r] = Qs[(ty * 4 + r) * 64 + d];
            #pragma unroll
            for (int c = 0; c < 4; c++) kc[c] = Ks[(tx * 4 + c) * 65 + d];
            #pragma unroll
            for (int r = 0; r < 4; r++)
                #pragma unroll
                for (int c = 0; c < 4; c++)
                    s[r][c] += qr[r] * kc[c];
        }

        // online softmax update per row (rows replicated across the 16 tx lanes)
        #pragma unroll
        for (int r = 0; r < 4; r++) {
            float mx = fmaxf(fmaxf(s[r][0], s[r][1]), fmaxf(s[r][2], s[r][3]));
            #pragma unroll
            for (int o = 8; o; o >>= 1) mx = fmaxf(mx, __shfl_xor_sync(0xffffffffu, mx, o));
            const float mnew = fmaxf(m[r], mx);
            const float alpha = __expf(m[r] - mnew);
            float rs = 0.f;
            #pragma unroll
            for (int c = 0; c < 4; c++) {
                const float p = __expf(s[r][c] - mnew);
                s[r][c] = p; rs += p;
            }
            #pragma unroll
            for (int o = 8; o; o >>= 1) rs += __shfl_xor_sync(0xffffffffu, rs, o);
            l[r] = l[r] * alpha + rs;
            m[r] = mnew;
            #pragma unroll
            for (int c = 0; c < 4; c++) acc[r][c] *= alpha;
            #pragma unroll
            for (int c = 0; c < 4; c++) Ps[(ty * 4 + r) * 65 + tx * 4 + c] = s[r][c];
        }
        __syncthreads();

        // acc += P @ V
        #pragma unroll 4
        for (int kk = 0; kk < 64; kk++) {
            float pv[4], vr[4];
            #pragma unroll
            for (int r = 0; r < 4; r++) pv[r] = Ps[(ty * 4 + r) * 65 + kk];
            #pragma unroll
            for (int c = 0; c < 4; c++) vr[c] = Vs[kk * 64 + tx * 4 + c];
            #pragma unroll
            for (int r = 0; r < 4; r++)
                #pragma unroll
                for (int c = 0; c < 4; c++)
                    acc[r][c] += pv[r] * vr[c];
        }
    }

    // epilogue: normalize and store
    float* ob = out + ((size_t)(b * SEQ + qt * 64)) * DM + h * DK;
    #pragma unroll
    for (int r = 0; r < 4; r++) {
        const float inv = 1.0f / l[r];
        float4 o;
        o.x = acc[r][0] * inv; o.y = acc[r][1] * inv;
        o.z = acc[r][2] * inv; o.w = acc[r][3] * inv;
        *(float4*)(ob + (size_t)(ty * 4 + r) * DM + tx * 4) = o;
    }
}

// ---------------- host launcher ----------------
extern "C" void kernel_launch(void* const* d_in, const int* in_sizes, int n_in,
                              void* d_out, int out_size)
{
    (void)in_sizes; (void)n_in; (void)out_size;
    const float* x     = (const float*)d_in[0];
    const float* Wq    = (const float*)d_in[1];
    const float* bq    = (const float*)d_in[2];
    const float* Wk    = (const float*)d_in[3];
    const float* bk    = (const float*)d_in[4];
    const float* Wv    = (const float*)d_in[5];
    const float* bv    = (const float*)d_in[6];
    const float* Wo    = (const float*)d_in[7];
    const float* bo    = (const float*)d_in[8];
    const float* ln1_g = (const float*)d_in[9];
    const float* ln1_b = (const float*)d_in[10];
    const float* W1    = (const float*)d_in[11];
    const float* b1    = (const float*)d_in[12];
    const float* W2    = (const float*)d_in[13];
    const float* b2    = (const float*)d_in[14];
    const float* ln2_g = (const float*)d_in[15];
    const float* ln2_b = (const float*)d_in[16];
    float* out = (float*)d_out;

    float *h, *q, *k, *v, *ctx, *x1, *h2, *ff;
    cudaGetSymbolAddress((void**)&h,   g_h);
    cudaGetSymbolAddress((void**)&q,   g_q);
    cudaGetSymbolAddress((void**)&k,   g_k);
    cudaGetSymbolAddress((void**)&v,   g_v);
    cudaGetSymbolAddress((void**)&ctx, g_ctx);
    cudaGetSymbolAddress((void**)&x1,  g_x1);
    cudaGetSymbolAddress((void**)&h2,  g_h2);
    cudaGetSymbolAddress((void**)&ff,  g_ff);

    const int attn_smem = ATTN_SMEM_FLOATS * (int)sizeof(float);
    cudaFuncSetAttribute(attn_kernel, cudaFuncAttributeMaxDynamicSharedMemorySize, attn_smem);

    const dim3 gProj(DM / 128, TOK / 128);   // 8 x 64
    const dim3 gFF1(DFF / 128, TOK / 128);   // 32 x 64

    // 1) h = LN1(x)
    ln_kernel<<<TOK, 256>>>(x, ln1_g, ln1_b, h);
    // 2) q/k/v projections
    sgemm_kernel<0><<<gProj, 256>>>(h, Wq, bq, nullptr, q, TOK, DM, DM);
    sgemm_kernel<0><<<gProj, 256>>>(h, Wk, bk, nullptr, k, TOK, DM, DM);
    sgemm_kernel<0><<<gProj, 256>>>(h, Wv, bv, nullptr, v, TOK, DM, DM);
    // 3) attention
    attn_kernel<<<dim3(SEQ / 64, NH, BATCH), 256, attn_smem>>>(q, k, v, ctx);
    // 4) x1 = x + ctx @ Wo + bo
    sgemm_kernel<1><<<gProj, 256>>>(ctx, Wo, bo, x, x1, TOK, DM, DM);
    // 5) h2 = LN2(x1)
    ln_kernel<<<TOK, 256>>>(x1, ln2_g, ln2_b, h2);
    // 6) ff = gelu(h2 @ W1 + b1)
    sgemm_kernel<2><<<gFF1, 256>>>(h2, W1, b1, nullptr, ff, TOK, DFF, DM);
    // 7) out = x1 + ff @ W2 + b2
    sgemm_kernel<1><<<gProj, 256>>>(ff, W2, b2, x1, out, TOK, DM, DFF);
}

// round 3
// speedup vs baseline: 2.0180x; 2.0180x over previous
#include <cuda_runtime.h>
#include <math.h>
#include <stdint.h>

#define TOK   8192      // 4 * 2048 tokens
#define DM    1024
#define DFF   4096
#define NH    16
#define DK    64
#define SEQ   2048
#define BATCH 4

// ---------------- scratch (static device globals; no allocation) ----------------
__device__ float g_h  [TOK * DM];
__device__ float g_q  [TOK * DM];
__device__ float g_k  [TOK * DM];
__device__ float g_v  [TOK * DM];
__device__ float g_ctx[TOK * DM];
__device__ float g_x1 [TOK * DM];
__device__ float g_h2 [TOK * DM];
__device__ float g_ff [TOK * DFF];
// tf32-rounded weights
__device__ float g_wq [DM * DM];
__device__ float g_wk [DM * DM];
__device__ float g_wv [DM * DM];
__device__ float g_wo [DM * DM];
__device__ float g_w1 [DM * DFF];
__device__ float g_w2 [DFF * DM];

// ---------------- helpers ----------------
__device__ __forceinline__ float to_tf32(float x) {
    uint32_t r;
    asm("cvt.rna.tf32.f32 %0, %1;" : "=r"(r) : "f"(x));
    return __uint_as_float(r);
}
__device__ __forceinline__ uint32_t smem_u32(const void* p) {
    uint32_t a;
    asm("{ .reg .u64 t; cvta.to.shared.u64 t, %1; cvt.u32.u64 %0, t; }" : "=r"(a) : "l"(p));
    return a;
}
__device__ __forceinline__ void cp_async16(uint32_t dst, const void* src) {
    asm volatile("cp.async.cg.shared.global [%0], [%1], 16;" :: "r"(dst), "l"(src));
}
__device__ __forceinline__ void cp_commit() {
    asm volatile("cp.async.commit_group;" ::: "memory");
}
__device__ __forceinline__ void mma_tf32_16x8x8(float* d, const uint32_t* a, const uint32_t* b) {
    asm volatile(
        "mma.sync.aligned.m16n8k8.row.col.f32.tf32.tf32.f32 "
        "{%0,%1,%2,%3}, {%4,%5,%6,%7}, {%8,%9}, {%0,%1,%2,%3};"
        : "+f"(d[0]), "+f"(d[1]), "+f"(d[2]), "+f"(d[3])
        : "r"(a[0]), "r"(a[1]), "r"(a[2]), "r"(a[3]), "r"(b[0]), "r"(b[1]));
}

// ---------------- weight pre-round (fp32 -> tf32 bits, rna) ----------------
__global__ void __launch_bounds__(256) round_tf32_kernel(const float* __restrict__ in,
                                                         float* __restrict__ out, int n4)
{
    const int i = blockIdx.x * blockDim.x + threadIdx.x;
    if (i < n4) {
        float4 v = ((const float4*)in)[i];
        v.x = to_tf32(v.x); v.y = to_tf32(v.y);
        v.z = to_tf32(v.z); v.w = to_tf32(v.w);
        ((float4*)out)[i] = v;
    }
}

// ---------------- LayerNorm (ROUND=1: round output to tf32 for GEMM consumption) ----------------
template <int ROUND>
__global__ void __launch_bounds__(256) ln_kernel(const float* __restrict__ x,
                                                 const float* __restrict__ g,
                                                 const float* __restrict__ b,
                                                 float* __restrict__ out)
{
    const int row = blockIdx.x;
    const int tid = threadIdx.x;
    const float4 v = ((const float4*)(x + (size_t)row * DM))[tid];

    float s  = v.x + v.y + v.z + v.w;
    float ss = v.x * v.x + v.y * v.y + v.z * v.z + v.w * v.w;
    #pragma unroll
    for (int o = 16; o; o >>= 1) {
        s  += __shfl_xor_sync(0xffffffffu, s,  o);
        ss += __shfl_xor_sync(0xffffffffu, ss, o);
    }
    __shared__ float sb[8], sb2[8];
    if ((tid & 31) == 0) { sb[tid >> 5] = s; sb2[tid >> 5] = ss; }
    __syncthreads();
    float ts = 0.f, ts2 = 0.f;
    #pragma unroll
    for (int i = 0; i < 8; i++) { ts += sb[i]; ts2 += sb2[i]; }

    const float mu  = ts * (1.0f / DM);
    const float var = ts2 * (1.0f / DM) - mu * mu;
    const float inv = rsqrtf(var + 1e-5f);

    const float4 gg = ((const float4*)g)[tid];
    const float4 bb = ((const float4*)b)[tid];
    float4 o;
    o.x = (v.x - mu) * inv * gg.x + bb.x;
    o.y = (v.y - mu) * inv * gg.y + bb.y;
    o.z = (v.z - mu) * inv * gg.z + bb.z;
    o.w = (v.w - mu) * inv * gg.w + bb.w;
    if (ROUND) {
        o.x = to_tf32(o.x); o.y = to_tf32(o.y);
        o.z = to_tf32(o.z); o.w = to_tf32(o.w);
    }
    ((float4*)(out + (size_t)row * DM))[tid] = o;
}

// ---------------- tf32 mma.sync GEMM: 128x128 tile, BK=32, 4-stage cp.async ----------------
// EPI: 0 = bias; 1 = bias + residual; 2 = gelu(bias) rounded to tf32
__device__ __forceinline__ float gelu_exact(float v) {
    return 0.5f * v * (1.0f + erff(v * 0.70710678118654752440f));
}

#define BM 128
#define BN 128
#define BK 32
#define STAGES 4
#define AS_STRIDE 36            // floats per A smem row (bank-conflict-free: 4g+tig)
#define BS_STRIDE 136           // floats per B smem row (bank-conflict-free: 8tig+g)
#define A_ST_FLOATS (BM * AS_STRIDE)        // 4608
#define B_ST_FLOATS (BK * BS_STRIDE)        // 4352
#define STAGE_FLOATS (A_ST_FLOATS + B_ST_FLOATS)
#define GEMM_SMEM_BYTES (STAGES * STAGE_FLOATS * 4)   // 143360

template <int EPI>
__global__ void __launch_bounds__(256) gemm_tc(
    const float* __restrict__ A, const float* __restrict__ B,
    const float* __restrict__ bias, const float* __restrict__ res,
    float* __restrict__ C, int M, int N, int K)
{
    extern __shared__ float smf[];
    const uint32_t sbase = smem_u32(smf);

    const int tid = threadIdx.x;
    const int wid = tid >> 5;
    const int lane = tid & 31;
    const int g = lane >> 2;        // 0..7
    const int tig = lane & 3;       // 0..3
    const int wm = wid & 1;         // 0..1  (64-row half)
    const int wn = wid >> 1;        // 0..3  (32-col quarter)

    const int n0 = blockIdx.x * BN;
    const int m0 = blockIdx.y * BM;
    const int NT = K / BK;

    // global->smem load mapping (per stage: A 1024 float4, B 1024 float4)
    const int a_row = tid >> 3;           // +64*i later? no: f4 = i*256+tid
    (void)a_row;

    float acc[4][4][4];
    #pragma unroll
    for (int mt = 0; mt < 4; mt++)
        #pragma unroll
        for (int nt = 0; nt < 4; nt++)
            #pragma unroll
            for (int e = 0; e < 4; e++) acc[mt][nt][e] = 0.f;

    // ---- stage loader ----
    auto load_stage = [&](int st, int t) {
        const uint32_t aoff = sbase + (uint32_t)(st * STAGE_FLOATS) * 4u;
        const uint32_t boff = aoff + A_ST_FLOATS * 4u;
        #pragma unroll
        for (int i = 0; i < 4; i++) {
            const int f4 = i * 256 + tid;
            // A: row = f4>>3 (0..127), kc4 = f4&7
            const int ar = f4 >> 3, ac4 = f4 & 7;
            cp_async16(aoff + (uint32_t)(ar * AS_STRIDE + ac4 * 4) * 4u,
                       A + (size_t)(m0 + ar) * K + (size_t)t * BK + ac4 * 4);
            // B: krow = f4>>5 (0..31), n4 = f4&31
            const int bk = f4 >> 5, bn4 = f4 & 31;
            cp_async16(boff + (uint32_t)(bk * BS_STRIDE + bn4 * 4) * 4u,
                       B + (size_t)((size_t)t * BK + bk) * N + n0 + bn4 * 4);
        }
    };

    // prefetch STAGES-1 tiles
    #pragma unroll
    for (int t = 0; t < STAGES - 1; t++) {
        if (t < NT) load_stage(t, t);
        cp_commit();
    }

    for (int t = 0; t < NT; t++) {
        const int pf = t + STAGES - 1;
        if (pf < NT) load_stage(pf % STAGES, pf);
        cp_commit();
        asm volatile("cp.async.wait_group %0;" :: "n"(STAGES - 2) : "memory");
        __syncthreads();

        const int st = t % STAGES;
        const float* sA = smf + st * STAGE_FLOATS + (wm * 64) * AS_STRIDE;
        const float* sB = smf + st * STAGE_FLOATS + A_ST_FLOATS + wn * 32;

        #pragma unroll
        for (int k0 = 0; k0 < BK; k0 += 8) {
            uint32_t afr[4][4], bfr[4][2];
            #pragma unroll
            for (int mt = 0; mt < 4; mt++) {
                const uint32_t* p = (const uint32_t*)(sA + (mt * 16 + g) * AS_STRIDE + k0 + tig);
                afr[mt][0] = p[0];
                afr[mt][1] = p[8 * AS_STRIDE];
                afr[mt][2] = p[4];
                afr[mt][3] = p[8 * AS_STRIDE + 4];
            }
            #pragma unroll
            for (int nt = 0; nt < 4; nt++) {
                const uint32_t* p = (const uint32_t*)(sB + (k0 + tig) * BS_STRIDE + nt * 8 + g);
                bfr[nt][0] = p[0];
                bfr[nt][1] = p[4 * BS_STRIDE];
            }
            #pragma unroll
            for (int mt = 0; mt < 4; mt++)
                #pragma unroll
                for (int nt = 0; nt < 4; nt++)
                    mma_tf32_16x8x8(acc[mt][nt], afr[mt], bfr[nt]);
        }
        __syncthreads();
    }

    // ---- epilogue ----
    #pragma unroll
    for (int mt = 0; mt < 4; mt++) {
        const int r0 = m0 + wm * 64 + mt * 16 + g;
        float* c0 = C + (size_t)r0 * N;
        float* c1 = C + (size_t)(r0 + 8) * N;
        const float* rr0 = (EPI == 1) ? (res + (size_t)r0 * N) : nullptr;
        const float* rr1 = (EPI == 1) ? (res + (size_t)(r0 + 8) * N) : nullptr;
        #pragma unroll
        for (int nt = 0; nt < 4; nt++) {
            const int col = n0 + wn * 32 + nt * 8 + 2 * tig;
            const float bx = bias[col], by = bias[col + 1];
            float v0 = acc[mt][nt][0] + bx, v1 = acc[mt][nt][1] + by;
            float v2 = acc[mt][nt][2] + bx, v3 = acc[mt][nt][3] + by;
            if (EPI == 2) {
                v0 = to_tf32(gelu_exact(v0)); v1 = to_tf32(gelu_exact(v1));
                v2 = to_tf32(gelu_exact(v2)); v3 = to_tf32(gelu_exact(v3));
            }
            if (EPI == 1) {
                v0 += rr0[col]; v1 += rr0[col + 1];
                v2 += rr1[col]; v3 += rr1[col + 1];
            }
            *(float2*)(c0 + col) = make_float2(v0, v1);
            *(float2*)(c1 + col) = make_float2(v2, v3);
        }
    }
}

// ---------------- Flash attention (SIMT; ctx rounded to tf32 for Wo GEMM) ----------------
#define ATTN_SMEM_FLOATS (64*64 + 64*65 + 64*64 + 64*65)

__global__ void __launch_bounds__(256) attn_kernel(const float* __restrict__ q,
                                                   const float* __restrict__ k,
                                                   const float* __restrict__ v,
                                                   float* __restrict__ out)
{
    extern __shared__ float sm[];
    float* Qs = sm;
    float* Ks = Qs + 64 * 64;
    float* Vs = Ks + 64 * 65;
    float* Ps = Vs + 64 * 64;

    const int tid = threadIdx.x;
    const int qt = blockIdx.x, h = blockIdx.y, b = blockIdx.z;
    const int tx = tid & 15, ty = tid >> 4;
    const float scale = 0.125f;

    const float* qbase = q + ((size_t)(b * SEQ + qt * 64)) * DM + h * DK;
    for (int i = tid; i < 64 * 16; i += 256) {
        const int r = i >> 4, c4 = (i & 15) << 2;
        const float4 t = *(const float4*)(qbase + (size_t)r * DM + c4);
        Qs[r * 64 + c4 + 0] = t.x * scale;
        Qs[r * 64 + c4 + 1] = t.y * scale;
        Qs[r * 64 + c4 + 2] = t.z * scale;
        Qs[r * 64 + c4 + 3] = t.w * scale;
    }

    float m[4], l[4], acc[4][4];
    #pragma unroll
    for (int r = 0; r < 4; r++) {
        m[r] = -1e30f; l[r] = 0.f;
        #pragma unroll
        for (int c = 0; c < 4; c++) acc[r][c] = 0.f;
    }

    const float* kb = k + ((size_t)(b * SEQ)) * DM + h * DK;
    const float* vb = v + ((size_t)(b * SEQ)) * DM + h * DK;

    for (int kt = 0; kt < SEQ / 64; kt++) {
        __syncthreads();
        const float* kp = kb + (size_t)kt * 64 * DM;
        const float* vp = vb + (size_t)kt * 64 * DM;
        for (int i = tid; i < 64 * 16; i += 256) {
            const int r = i >> 4, c4 = (i & 15) << 2;
            const float4 t = *(const float4*)(kp + (size_t)r * DM + c4);
            Ks[r * 65 + c4 + 0] = t.x;
            Ks[r * 65 + c4 + 1] = t.y;
            Ks[r * 65 + c4 + 2] = t.z;
            Ks[r * 65 + c4 + 3] = t.w;
            const float4 u = *(const float4*)(vp + (size_t)r * DM + c4);
            *(float4*)&Vs[r * 64 + c4] = u;
        }
        __syncthreads();

        float s[4][4] = {};
        #pragma unroll 4
        for (int d = 0; d < DK; d++) {
            float qr[4], kc[4];
            #pragma unroll
            for (int r = 0; r < 4; r++) qr[r] = Qs[(ty * 4 + r) * 64 + d];
            #pragma unroll
            for (int c = 0; c < 4; c++) kc[c] = Ks[(tx * 4 + c) * 65 + d];
            #pragma unroll
            for (int r = 0; r < 4; r++)
                #pragma unroll
                for (int c = 0; c < 4; c++)
                    s[r][c] += qr[r] * kc[c];
        }

        #pragma unroll
        for (int r = 0; r < 4; r++) {
            float mx = fmaxf(fmaxf(s[r][0], s[r][1]), fmaxf(s[r][2], s[r][3]));
            #pragma unroll
            for (int o = 8; o; o >>= 1) mx = fmaxf(mx, __shfl_xor_sync(0xffffffffu, mx, o));
            const float mnew = fmaxf(m[r], mx);
            const float alpha = __expf(m[r] - mnew);
            float rs = 0.f;
            #pragma unroll
            for (int c = 0; c < 4; c++) {
                const float p = __expf(s[r][c] - mnew);
                s[r][c] = p; rs += p;
            }
            #pragma unroll
            for (int o = 8; o; o >>= 1) rs += __shfl_xor_sync(0xffffffffu, rs, o);
            l[r] = l[r] * alpha + rs;
            m[r] = mnew;
            #pragma unroll
            for (int c = 0; c < 4; c++) acc[r][c] *= alpha;
            #pragma unroll
            for (int c = 0; c < 4; c++) Ps[(ty * 4 + r) * 65 + tx * 4 + c] = s[r][c];
        }
        __syncthreads();

        #pragma unroll 4
        for (int kk = 0; kk < 64; kk++) {
            float pv[4], vr[4];
            #pragma unroll
            for (int r = 0; r < 4; r++) pv[r] = Ps[(ty * 4 + r) * 65 + kk];
            #pragma unroll
            for (int c = 0; c < 4; c++) vr[c] = Vs[kk * 64 + tx * 4 + c];
            #pragma unroll
            for (int r = 0; r < 4; r++)
                #pragma unroll
                for (int c = 0; c < 4; c++)
                    acc[r][c] += pv[r] * vr[c];
        }
    }

    float* ob = out + ((size_t)(b * SEQ + qt * 64)) * DM + h * DK;
    #pragma unroll
    for (int r = 0; r < 4; r++) {
        const float inv = 1.0f / l[r];
        float4 o;
        o.x = to_tf32(acc[r][0] * inv); o.y = to_tf32(acc[r][1] * inv);
        o.z = to_tf32(acc[r][2] * inv); o.w = to_tf32(acc[r][3] * inv);
        *(float4*)(ob + (size_t)(ty * 4 + r) * DM + tx * 4) = o;
    }
}

// ---------------- host launcher ----------------
extern "C" void kernel_launch(void* const* d_in, const int* in_sizes, int n_in,
                              void* d_out, int out_size)
{
    (void)in_sizes; (void)n_in; (void)out_size;
    const float* x     = (const float*)d_in[0];
    const float* Wq    = (const float*)d_in[1];
    const float* bq    = (const float*)d_in[2];
    const float* Wk    = (const float*)d_in[3];
    const float* bk    = (const float*)d_in[4];
    const float* Wv    = (const float*)d_in[5];
    const float* bv    = (const float*)d_in[6];
    const float* Wo    = (const float*)d_in[7];
    const float* bo    = (const float*)d_in[8];
    const float* ln1_g = (const float*)d_in[9];
    const float* ln1_b = (const float*)d_in[10];
    const float* W1    = (const float*)d_in[11];
    const float* b1    = (const float*)d_in[12];
    const float* W2    = (const float*)d_in[13];
    const float* b2    = (const float*)d_in[14];
    const float* ln2_g = (const float*)d_in[15];
    const float* ln2_b = (const float*)d_in[16];
    float* out = (float*)d_out;

    float *h, *q, *k, *v, *ctx, *x1, *h2, *ff;
    float *wq, *wk, *wv, *wo, *w1, *w2;
    cudaGetSymbolAddress((void**)&h,   g_h);
    cudaGetSymbolAddress((void**)&q,   g_q);
    cudaGetSymbolAddress((void**)&k,   g_k);
    cudaGetSymbolAddress((void**)&v,   g_v);
    cudaGetSymbolAddress((void**)&ctx, g_ctx);
    cudaGetSymbolAddress((void**)&x1,  g_x1);
    cudaGetSymbolAddress((void**)&h2,  g_h2);
    cudaGetSymbolAddress((void**)&ff,  g_ff);
    cudaGetSymbolAddress((void**)&wq,  g_wq);
    cudaGetSymbolAddress((void**)&wk,  g_wk);
    cudaGetSymbolAddress((void**)&wv,  g_wv);
    cudaGetSymbolAddress((void**)&wo,  g_wo);
    cudaGetSymbolAddress((void**)&w1,  g_w1);
    cudaGetSymbolAddress((void**)&w2,  g_w2);

    const int attn_smem = ATTN_SMEM_FLOATS * (int)sizeof(float);
    cudaFuncSetAttribute(attn_kernel, cudaFuncAttributeMaxDynamicSharedMemorySize, attn_smem);
    cudaFuncSetAttribute(gemm_tc<0>, cudaFuncAttributeMaxDynamicSharedMemorySize, GEMM_SMEM_BYTES);
    cudaFuncSetAttribute(gemm_tc<1>, cudaFuncAttributeMaxDynamicSharedMemorySize, GEMM_SMEM_BYTES);
    cudaFuncSetAttribute(gemm_tc<2>, cudaFuncAttributeMaxDynamicSharedMemorySize, GEMM_SMEM_BYTES);

    // 0) pre-round weights to tf32 (rna)
    round_tf32_kernel<<<(DM * DM / 4 + 255) / 256, 256>>>(Wq, wq, DM * DM / 4);
    round_tf32_kernel<<<(DM * DM / 4 + 255) / 256, 256>>>(Wk, wk, DM * DM / 4);
    round_tf32_kernel<<<(DM * DM / 4 + 255) / 256, 256>>>(Wv, wv, DM * DM / 4);
    round_tf32_kernel<<<(DM * DM / 4 + 255) / 256, 256>>>(Wo, wo, DM * DM / 4);
    round_tf32_kernel<<<(DM * DFF / 4 + 255) / 256, 256>>>(W1, w1, DM * DFF / 4);
    round_tf32_kernel<<<(DFF * DM / 4 + 255) / 256, 256>>>(W2, w2, DFF * DM / 4);

    const dim3 gProj(DM / BN, TOK / BM);    // (8, 64)
    const dim3 gFF1(DFF / BN, TOK / BM);    // (32, 64)

    // 1) h = LN1(x)   (rounded to tf32)
    ln_kernel<1><<<TOK, 256>>>(x, ln1_g, ln1_b, h);
    // 2) q/k/v projections (tf32 mma.sync)
    gemm_tc<0><<<gProj, 256, GEMM_SMEM_BYTES>>>(h, wq, bq, nullptr, q, TOK, DM, DM);
    gemm_tc<0><<<gProj, 256, GEMM_SMEM_BYTES>>>(h, wk, bk, nullptr, k, TOK, DM, DM);
    gemm_tc<0><<<gProj, 256, GEMM_SMEM_BYTES>>>(h, wv, bv, nullptr, v, TOK, DM, DM);
    // 3) attention (fp32 SIMT; ctx output rounded)
    attn_kernel<<<dim3(SEQ / 64, NH, BATCH), 256, attn_smem>>>(q, k, v, ctx);
    // 4) x1 = x + ctx @ Wo + bo
    gemm_tc<1><<<gProj, 256, GEMM_SMEM_BYTES>>>(ctx, wo, bo, x, x1, TOK, DM, DM);
    // 5) h2 = LN2(x1)  (rounded)
    ln_kernel<1><<<TOK, 256>>>(x1, ln2_g, ln2_b, h2);
    // 6) ff = gelu(h2 @ W1 + b1)  (rounded in epilogue)
    gemm_tc<2><<<gFF1, 256, GEMM_SMEM_BYTES>>>(h2, w1, b1, nullptr, ff, TOK, DFF, DM);
    // 7) out = x1 + ff @ W2 + b2
    gemm_tc<1><<<gProj, 256, GEMM_SMEM_BYTES>>>(ff, w2, b2, x1, out, TOK, DM, DFF);
}

// round 4
// speedup vs baseline: 3.2585x; 1.6147x over previous
#include <cuda_runtime.h>
#include <math.h>
#include <stdint.h>

#define TOK   8192      // 4 * 2048 tokens
#define DM    1024
#define DFF   4096
#define NH    16
#define DK    64
#define SEQ   2048
#define BATCH 4

// ---------------- scratch (static device globals; no allocation) ----------------
__device__ float g_h  [TOK * DM];
__device__ float g_q  [TOK * DM];
__device__ float g_k  [TOK * DM];
__device__ float g_kt [TOK * DM];     // K transposed: [(h*DK+dk)*BATCH + b][s]
__device__ float g_v  [TOK * DM];
__device__ float g_ctx[TOK * DM];
__device__ float g_x1 [TOK * DM];
__device__ float g_h2 [TOK * DM];
__device__ float g_ff [TOK * DFF];
// tf32-rounded weights
__device__ float g_wq [DM * DM];
__device__ float g_wk [DM * DM];
__device__ float g_wv [DM * DM];
__device__ float g_wo [DM * DM];
__device__ float g_w1 [DM * DFF];
__device__ float g_w2 [DFF * DM];

// ---------------- helpers ----------------
__device__ __forceinline__ float to_tf32(float x) {
    uint32_t r;
    asm("cvt.rna.tf32.f32 %0, %1;" : "=r"(r) : "f"(x));
    return __uint_as_float(r);
}
__device__ __forceinline__ uint32_t smem_u32(const void* p) {
    uint32_t a;
    asm("{ .reg .u64 t; cvta.to.shared.u64 t, %1; cvt.u32.u64 %0, t; }" : "=r"(a) : "l"(p));
    return a;
}
__device__ __forceinline__ void cp_async16(uint32_t dst, const void* src) {
    asm volatile("cp.async.cg.shared.global [%0], [%1], 16;" :: "r"(dst), "l"(src));
}
__device__ __forceinline__ void cp_commit() {
    asm volatile("cp.async.commit_group;" ::: "memory");
}
__device__ __forceinline__ void mma_tf32_16x8x8(float* d, const uint32_t* a, const uint32_t* b) {
    asm volatile(
        "mma.sync.aligned.m16n8k8.row.col.f32.tf32.tf32.f32 "
        "{%0,%1,%2,%3}, {%4,%5,%6,%7}, {%8,%9}, {%0,%1,%2,%3};"
        : "+f"(d[0]), "+f"(d[1]), "+f"(d[2]), "+f"(d[3])
        : "r"(a[0]), "r"(a[1]), "r"(a[2]), "r"(a[3]), "r"(b[0]), "r"(b[1]));
}

// ---------------- weight pre-round (fp32 -> tf32 bits, rna) ----------------
__global__ void __launch_bounds__(256) round_tf32_kernel(const float* __restrict__ in,
                                                         float* __restrict__ out, int n4)
{
    const int i = blockIdx.x * blockDim.x + threadIdx.x;
    if (i < n4) {
        float4 v = ((const float4*)in)[i];
        v.x = to_tf32(v.x); v.y = to_tf32(v.y);
        v.z = to_tf32(v.z); v.w = to_tf32(v.w);
        ((float4*)out)[i] = v;
    }
}

// ---------------- K transpose: k[b*SEQ+s][h*DK+dk] -> kt[(h*DK+dk)*BATCH+b][s] ----------------
__global__ void __launch_bounds__(256) transpose_k_kernel(const float* __restrict__ in,
                                                          float* __restrict__ out)
{
    __shared__ float tile[32][33];
    const int s0 = blockIdx.x * 32;
    const int d0 = blockIdx.y * 32;
    const int h  = blockIdx.z & (NH - 1);
    const int b  = blockIdx.z >> 4;
    const int txx = threadIdx.x, tyy = threadIdx.y;

    const float* ip = in + ((size_t)(b * SEQ + s0)) * DM + h * DK + d0;
    #pragma unroll
    for (int i = tyy; i < 32; i += 8)
        tile[i][txx] = ip[(size_t)i * DM + txx];
    __syncthreads();
    float* op = out + ((size_t)(h * DK + d0)) * (BATCH * SEQ) + (size_t)b * SEQ + s0;
    #pragma unroll
    for (int i = tyy; i < 32; i += 8)
        op[(size_t)i * (BATCH * SEQ) + txx] = tile[txx][i];
}

// ---------------- LayerNorm (ROUND=1: round output to tf32) ----------------
template <int ROUND>
__global__ void __launch_bounds__(256) ln_kernel(const float* __restrict__ x,
                                                 const float* __restrict__ g,
                                                 const float* __restrict__ b,
                                                 float* __restrict__ out)
{
    const int row = blockIdx.x;
    const int tid = threadIdx.x;
    const float4 v = ((const float4*)(x + (size_t)row * DM))[tid];

    float s  = v.x + v.y + v.z + v.w;
    float ss = v.x * v.x + v.y * v.y + v.z * v.z + v.w * v.w;
    #pragma unroll
    for (int o = 16; o; o >>= 1) {
        s  += __shfl_xor_sync(0xffffffffu, s,  o);
        ss += __shfl_xor_sync(0xffffffffu, ss, o);
    }
    __shared__ float sb[8], sb2[8];
    if ((tid & 31) == 0) { sb[tid >> 5] = s; sb2[tid >> 5] = ss; }
    __syncthreads();
    float ts = 0.f, ts2 = 0.f;
    #pragma unroll
    for (int i = 0; i < 8; i++) { ts += sb[i]; ts2 += sb2[i]; }

    const float mu  = ts * (1.0f / DM);
    const float var = ts2 * (1.0f / DM) - mu * mu;
    const float inv = rsqrtf(var + 1e-5f);

    const float4 gg = ((const float4*)g)[tid];
    const float4 bb = ((const float4*)b)[tid];
    float4 o;
    o.x = (v.x - mu) * inv * gg.x + bb.x;
    o.y = (v.y - mu) * inv * gg.y + bb.y;
    o.z = (v.z - mu) * inv * gg.z + bb.z;
    o.w = (v.w - mu) * inv * gg.w + bb.w;
    if (ROUND) {
        o.x = to_tf32(o.x); o.y = to_tf32(o.y);
        o.z = to_tf32(o.z); o.w = to_tf32(o.w);
    }
    ((float4*)(out + (size_t)row * DM))[tid] = o;
}

// ---------------- tf32 mma.sync GEMM: 128x128 tile, BK=32, 4-stage cp.async ----------------
// EPI: 0 = bias; 1 = bias + residual; 2 = gelu(bias) rounded to tf32
// ROUND: round output to tf32 (for GEMM/MMA consumers)
__device__ __forceinline__ float gelu_exact(float v) {
    return 0.5f * v * (1.0f + erff(v * 0.70710678118654752440f));
}

#define BM 128
#define BN 128
#define BK 32
#define STAGES 4
#define AS_STRIDE 36            // floats per A smem row (bank-conflict-free: 4g+tig)
#define BS_STRIDE 136           // floats per B smem row (bank-conflict-free: 8tig+g)
#define A_ST_FLOATS (BM * AS_STRIDE)        // 4608
#define B_ST_FLOATS (BK * BS_STRIDE)        // 4352
#define STAGE_FLOATS (A_ST_FLOATS + B_ST_FLOATS)
#define GEMM_SMEM_BYTES (STAGES * STAGE_FLOATS * 4)   // 143360

template <int EPI, int ROUND>
__global__ void __launch_bounds__(256) gemm_tc(
    const float* __restrict__ A, const float* __restrict__ B,
    const float* __restrict__ bias, const float* __restrict__ res,
    float* __restrict__ C, int M, int N, int K)
{
    extern __shared__ float smf[];
    const uint32_t sbase = smem_u32(smf);

    const int tid = threadIdx.x;
    const int wid = tid >> 5;
    const int lane = tid & 31;
    const int g = lane >> 2;        // 0..7
    const int tig = lane & 3;       // 0..3
    const int wm = wid & 1;         // 0..1  (64-row half)
    const int wn = wid >> 1;        // 0..3  (32-col quarter)

    const int n0 = blockIdx.x * BN;
    const int m0 = blockIdx.y * BM;
    const int NT = K / BK;

    float acc[4][4][4];
    #pragma unroll
    for (int mt = 0; mt < 4; mt++)
        #pragma unroll
        for (int nt = 0; nt < 4; nt++)
            #pragma unroll
            for (int e = 0; e < 4; e++) acc[mt][nt][e] = 0.f;

    auto load_stage = [&](int st, int t) {
        const uint32_t aoff = sbase + (uint32_t)(st * STAGE_FLOATS) * 4u;
        const uint32_t boff = aoff + A_ST_FLOATS * 4u;
        #pragma unroll
        for (int i = 0; i < 4; i++) {
            const int f4 = i * 256 + tid;
            const int ar = f4 >> 3, ac4 = f4 & 7;
            cp_async16(aoff + (uint32_t)(ar * AS_STRIDE + ac4 * 4) * 4u,
                       A + (size_t)(m0 + ar) * K + (size_t)t * BK + ac4 * 4);
            const int bk = f4 >> 5, bn4 = f4 & 31;
            cp_async16(boff + (uint32_t)(bk * BS_STRIDE + bn4 * 4) * 4u,
                       B + (size_t)((size_t)t * BK + bk) * N + n0 + bn4 * 4);
        }
    };

    #pragma unroll
    for (int t = 0; t < STAGES - 1; t++) {
        if (t < NT) load_stage(t, t);
        cp_commit();
    }

    for (int t = 0; t < NT; t++) {
        const int pf = t + STAGES - 1;
        if (pf < NT) load_stage(pf % STAGES, pf);
        cp_commit();
        asm volatile("cp.async.wait_group %0;" :: "n"(STAGES - 2) : "memory");
        __syncthreads();

        const int st = t % STAGES;
        const float* sA = smf + st * STAGE_FLOATS + (wm * 64) * AS_STRIDE;
        const float* sB = smf + st * STAGE_FLOATS + A_ST_FLOATS + wn * 32;

        #pragma unroll
        for (int k0 = 0; k0 < BK; k0 += 8) {
            uint32_t afr[4][4], bfr[4][2];
            #pragma unroll
            for (int mt = 0; mt < 4; mt++) {
                const uint32_t* p = (const uint32_t*)(sA + (mt * 16 + g) * AS_STRIDE + k0 + tig);
                afr[mt][0] = p[0];
                afr[mt][1] = p[8 * AS_STRIDE];
                afr[mt][2] = p[4];
                afr[mt][3] = p[8 * AS_STRIDE + 4];
            }
            #pragma unroll
            for (int nt = 0; nt < 4; nt++) {
                const uint32_t* p = (const uint32_t*)(sB + (k0 + tig) * BS_STRIDE + nt * 8 + g);
                bfr[nt][0] = p[0];
                bfr[nt][1] = p[4 * BS_STRIDE];
            }
            #pragma unroll
            for (int mt = 0; mt < 4; mt++)
                #pragma unroll
                for (int nt = 0; nt < 4; nt++)
                    mma_tf32_16x8x8(acc[mt][nt], afr[mt], bfr[nt]);
        }
        __syncthreads();
    }

    // ---- epilogue ----
    #pragma unroll
    for (int mt = 0; mt < 4; mt++) {
        const int r0 = m0 + wm * 64 + mt * 16 + g;
        float* c0 = C + (size_t)r0 * N;
        float* c1 = C + (size_t)(r0 + 8) * N;
        const float* rr0 = (EPI == 1) ? (res + (size_t)r0 * N) : nullptr;
        const float* rr1 = (EPI == 1) ? (res + (size_t)(r0 + 8) * N) : nullptr;
        #pragma unroll
        for (int nt = 0; nt < 4; nt++) {
            const int col = n0 + wn * 32 + nt * 8 + 2 * tig;
            const float bx = bias[col], by = bias[col + 1];
            float v0 = acc[mt][nt][0] + bx, v1 = acc[mt][nt][1] + by;
            float v2 = acc[mt][nt][2] + bx, v3 = acc[mt][nt][3] + by;
            if (EPI == 2) {
                v0 = to_tf32(gelu_exact(v0)); v1 = to_tf32(gelu_exact(v1));
                v2 = to_tf32(gelu_exact(v2)); v3 = to_tf32(gelu_exact(v3));
            }
            if (EPI == 1) {
                v0 += rr0[col]; v1 += rr0[col + 1];
                v2 += rr1[col]; v3 += rr1[col + 1];
            }
            if (ROUND) {
                v0 = to_tf32(v0); v1 = to_tf32(v1);
                v2 = to_tf32(v2); v3 = to_tf32(v3);
            }
            *(float2*)(c0 + col) = make_float2(v0, v1);
            *(float2*)(c1 + col) = make_float2(v2, v3);
        }
    }
}

// ---------------- tensor-core flash attention ----------------
// CTA: (qt, h, b); 128 Q rows, 8 warps x 16 rows; KV tiles of 128, cp.async double buffer.
// kT layout: [(h*DK+dk)][BATCH*SEQ] rows (b*SEQ + s).
#define KT_STRIDE 136
#define VS_STRIDE 72
#define PS_STRIDE 132
#define KT_FLOATS (64 * KT_STRIDE)        // 8704 per buf
#define VS_FLOATS (128 * VS_STRIDE)       // 9216 per buf
#define PS_FLOATS (128 * PS_STRIDE)       // 16896
#define ATTN_TC_FLOATS (2 * KT_FLOATS + 2 * VS_FLOATS + PS_FLOATS)
#define ATTN_TC_SMEM (ATTN_TC_FLOATS * 4) // 210944 bytes

__global__ void __launch_bounds__(256) attn_tc_kernel(const float* __restrict__ q,
                                                      const float* __restrict__ kT,
                                                      const float* __restrict__ v,
                                                      float* __restrict__ out)
{
    extern __shared__ float smf[];
    float* KTs = smf;                        // 2 x [64][136]
    float* VSs = KTs + 2 * KT_FLOATS;        // 2 x [128][72]
    float* PSs = VSs + 2 * VS_FLOATS;        // [128][132]
    const uint32_t sbase = smem_u32(smf);

    const int tid = threadIdx.x;
    const int w = tid >> 5;
    const int lane = tid & 31;
    const int g = lane >> 2;
    const int tig = lane & 3;

    const int qt = blockIdx.x, h = blockIdx.y, b = blockIdx.z;

    // ---- Q fragments in registers (rows qt*128 + w*16 + g/g+8, scaled by 1/8) ----
    uint32_t qa[8][4];
    {
        const float* qb = q + ((size_t)(b * SEQ + qt * 128 + w * 16)) * DM + h * DK;
        #pragma unroll
        for (int kt = 0; kt < 8; kt++) {
            const int c = kt * 8 + tig;
            qa[kt][0] = __float_as_uint(0.125f * qb[(size_t)g * DM + c]);
            qa[kt][1] = __float_as_uint(0.125f * qb[(size_t)(g + 8) * DM + c]);
            qa[kt][2] = __float_as_uint(0.125f * qb[(size_t)g * DM + c + 4]);
            qa[kt][3] = __float_as_uint(0.125f * qb[(size_t)(g + 8) * DM + c + 4]);
        }
    }

    float o[8][4];
    #pragma unroll
    for (int nt = 0; nt < 8; nt++)
        #pragma unroll
        for (int e = 0; e < 4; e++) o[nt][e] = 0.f;
    float m0 = -1e30f, m1 = -1e30f, l0 = 0.f, l1 = 0.f;

    // ---- KV tile loader (cp.async) ----
    auto load_kv = [&](int t, int buf) {
        const uint32_t kdst = sbase + (uint32_t)(buf * KT_FLOATS) * 4u;
        const uint32_t vdst = sbase + (uint32_t)(2 * KT_FLOATS + buf * VS_FLOATS) * 4u;
        const float* ksrc = kT + (size_t)(h * DK) * (BATCH * SEQ) + (size_t)b * SEQ + (size_t)t * 128;
        const float* vsrc = v + ((size_t)(b * SEQ + t * 128)) * DM + h * DK;
        #pragma unroll
        for (int i = 0; i < 8; i++) {
            const int c = i * 256 + tid;          // 0..2047
            const int kr = c >> 5, kc = c & 31;   // K: 64 rows x 32 chunks
            cp_async16(kdst + (uint32_t)(kr * KT_STRIDE + kc * 4) * 4u,
                       ksrc + (size_t)kr * (BATCH * SEQ) + kc * 4);
            const int vr = c >> 4, vc = c & 15;   // V: 128 rows x 16 chunks
            cp_async16(vdst + (uint32_t)(vr * VS_STRIDE + vc * 4) * 4u,
                       vsrc + (size_t)vr * DM + vc * 4);
        }
    };

    load_kv(0, 0);
    cp_commit();

    const int NKV = SEQ / 128;
    for (int t = 0; t < NKV; t++) {
        asm volatile("cp.async.wait_group 0;" ::: "memory");
        __syncthreads();
        if (t + 1 < NKV) { load_kv(t + 1, (t + 1) & 1); cp_commit(); }

        // ---- S = Q @ K^T (per warp: 16 x 128) ----
        float s[16][4];
        #pragma unroll
        for (int nt = 0; nt < 16; nt++)
            #pragma unroll
            for (int e = 0; e < 4; e++) s[nt][e] = 0.f;

        {
            const uint32_t* kp = (const uint32_t*)(KTs + (t & 1) * KT_FLOATS);
            #pragma unroll
            for (int k8 = 0; k8 < 8; k8++) {
                #pragma unroll
                for (int nt = 0; nt < 16; nt++) {
                    uint32_t bfr[2];
                    bfr[0] = kp[(k8 * 8 + tig) * KT_STRIDE + nt * 8 + g];
                    bfr[1] = kp[(k8 * 8 + tig + 4) * KT_STRIDE + nt * 8 + g];
                    mma_tf32_16x8x8(s[nt], qa[k8], bfr);
                }
            }
        }

        // ---- online softmax ----
        float rmax0 = -1e30f, rmax1 = -1e30f;
        #pragma unroll
        for (int nt = 0; nt < 16; nt++) {
            rmax0 = fmaxf(rmax0, fmaxf(s[nt][0], s[nt][1]));
            rmax1 = fmaxf(rmax1, fmaxf(s[nt][2], s[nt][3]));
        }
        rmax0 = fmaxf(rmax0, __shfl_xor_sync(0xffffffffu, rmax0, 1));
        rmax0 = fmaxf(rmax0, __shfl_xor_sync(0xffffffffu, rmax0, 2));
        rmax1 = fmaxf(rmax1, __shfl_xor_sync(0xffffffffu, rmax1, 1));
        rmax1 = fmaxf(rmax1, __shfl_xor_sync(0xffffffffu, rmax1, 2));

        const float mn0 = fmaxf(m0, rmax0);
        const float mn1 = fmaxf(m1, rmax1);
        const float al0 = __expf(m0 - mn0);
        const float al1 = __expf(m1 - mn1);
        m0 = mn0; m1 = mn1;

        float rs0 = 0.f, rs1 = 0.f;
        {
            float* ps0 = PSs + (size_t)(w * 16 + g) * PS_STRIDE + 2 * tig;
            float* ps1 = ps0 + 8 * PS_STRIDE;
            #pragma unroll
            for (int nt = 0; nt < 16; nt++) {
                const float p0 = to_tf32(__expf(s[nt][0] - mn0));
                const float p1 = to_tf32(__expf(s[nt][1] - mn0));
                const float p2 = to_tf32(__expf(s[nt][2] - mn1));
                const float p3 = to_tf32(__expf(s[nt][3] - mn1));
                rs0 += p0 + p1; rs1 += p2 + p3;
                *(float2*)(ps0 + nt * 8) = make_float2(p0, p1);
                *(float2*)(ps1 + nt * 8) = make_float2(p2, p3);
            }
        }
        rs0 += __shfl_xor_sync(0xffffffffu, rs0, 1);
        rs0 += __shfl_xor_sync(0xffffffffu, rs0, 2);
        rs1 += __shfl_xor_sync(0xffffffffu, rs1, 1);
        rs1 += __shfl_xor_sync(0xffffffffu, rs1, 2);
        l0 = l0 * al0 + rs0;
        l1 = l1 * al1 + rs1;

        #pragma unroll
        for (int nt = 0; nt < 8; nt++) {
            o[nt][0] *= al0; o[nt][1] *= al0;
            o[nt][2] *= al1; o[nt][3] *= al1;
        }
        __syncwarp();

        // ---- O += P @ V (per warp: 16 x 64, k = 128) ----
        {
            const uint32_t* pp = (const uint32_t*)PSs;
            const uint32_t* vp = (const uint32_t*)(VSs + (t & 1) * VS_FLOATS);
            #pragma unroll
            for (int k16 = 0; k16 < 16; k16++) {
                uint32_t a[4];
                a[0] = pp[(w * 16 + g) * PS_STRIDE + k16 * 8 + tig];
                a[1] = pp[(w * 16 + g + 8) * PS_STRIDE + k16 * 8 + tig];
                a[2] = pp[(w * 16 + g) * PS_STRIDE + k16 * 8 + tig + 4];
                a[3] = pp[(w * 16 + g + 8) * PS_STRIDE + k16 * 8 + tig + 4];
                #pragma unroll
                for (int nt = 0; nt < 8; nt++) {
                    uint32_t bfr[2];
                    bfr[0] = vp[(k16 * 8 + tig) * VS_STRIDE + nt * 8 + g];
                    bfr[1] = vp[(k16 * 8 + tig + 4) * VS_STRIDE + nt * 8 + g];
                    mma_tf32_16x8x8(o[nt], a, bfr);
                }
            }
        }
        __syncwarp();
    }

    // ---- epilogue: normalize, round to tf32 (feeds Wo GEMM), store ----
    {
        const float i0 = 1.0f / l0, i1 = 1.0f / l1;
        const int r0 = qt * 128 + w * 16 + g;
        float* ob0 = out + ((size_t)(b * SEQ + r0)) * DM + h * DK + 2 * tig;
        float* ob1 = ob0 + 8 * DM;
        #pragma unroll
        for (int nt = 0; nt < 8; nt++) {
            *(float2*)(ob0 + nt * 8) = make_float2(to_tf32(o[nt][0] * i0), to_tf32(o[nt][1] * i0));
            *(float2*)(ob1 + nt * 8) = make_float2(to_tf32(o[nt][2] * i1), to_tf32(o[nt][3] * i1));
        }
    }
}

// ---------------- host launcher ----------------
extern "C" void kernel_launch(void* const* d_in, const int* in_sizes, int n_in,
                              void* d_out, int out_size)
{
    (void)in_sizes; (void)n_in; (void)out_size;
    const float* x     = (const float*)d_in[0];
    const float* Wq    = (const float*)d_in[1];
    const float* bq    = (const float*)d_in[2];
    const float* Wk    = (const float*)d_in[3];
    const float* bk    = (const float*)d_in[4];
    const float* Wv    = (const float*)d_in[5];
    const float* bv    = (const float*)d_in[6];
    const float* Wo    = (const float*)d_in[7];
    const float* bo    = (const float*)d_in[8];
    const float* ln1_g = (const float*)d_in[9];
    const float* ln1_b = (const float*)d_in[10];
    const float* W1    = (const float*)d_in[11];
    const float* b1    = (const float*)d_in[12];
    const float* W2    = (const float*)d_in[13];
    const float* b2    = (const float*)d_in[14];
    const float* ln2_g = (const float*)d_in[15];
    const float* ln2_b = (const float*)d_in[16];
    float* out = (float*)d_out;

    float *h, *q, *k, *kt, *v, *ctx, *x1, *h2, *ff;
    float *wq, *wk, *wv, *wo, *w1, *w2;
    cudaGetSymbolAddress((void**)&h,   g_h);
    cudaGetSymbolAddress((void**)&q,   g_q);
    cudaGetSymbolAddress((void**)&k,   g_k);
    cudaGetSymbolAddress((void**)&kt,  g_kt);
    cudaGetSymbolAddress((void**)&v,   g_v);
    cudaGetSymbolAddress((void**)&ctx, g_ctx);
    cudaGetSymbolAddress((void**)&x1,  g_x1);
    cudaGetSymbolAddress((void**)&h2,  g_h2);
    cudaGetSymbolAddress((void**)&ff,  g_ff);
    cudaGetSymbolAddress((void**)&wq,  g_wq);
    cudaGetSymbolAddress((void**)&wk,  g_wk);
    cudaGetSymbolAddress((void**)&wv,  g_wv);
    cudaGetSymbolAddress((void**)&wo,  g_wo);
    cudaGetSymbolAddress((void**)&w1,  g_w1);
    cudaGetSymbolAddress((void**)&w2,  g_w2);

    cudaFuncSetAttribute(attn_tc_kernel, cudaFuncAttributeMaxDynamicSharedMemorySize, ATTN_TC_SMEM);
    cudaFuncSetAttribute(gemm_tc<0,1>, cudaFuncAttributeMaxDynamicSharedMemorySize, GEMM_SMEM_BYTES);
    cudaFuncSetAttribute(gemm_tc<1,0>, cudaFuncAttributeMaxDynamicSharedMemorySize, GEMM_SMEM_BYTES);
    cudaFuncSetAttribute(gemm_tc<2,0>, cudaFuncAttributeMaxDynamicSharedMemorySize, GEMM_SMEM_BYTES);

    // 0) pre-round weights to tf32 (rna)
    round_tf32_kernel<<<(DM * DM / 4 + 255) / 256, 256>>>(Wq, wq, DM * DM / 4);
    round_tf32_kernel<<<(DM * DM / 4 + 255) / 256, 256>>>(Wk, wk, DM * DM / 4);
    round_tf32_kernel<<<(DM * DM / 4 + 255) / 256, 256>>>(Wv, wv, DM * DM / 4);
    round_tf32_kernel<<<(DM * DM / 4 + 255) / 256, 256>>>(Wo, wo, DM * DM / 4);
    round_tf32_kernel<<<(DM * DFF / 4 + 255) / 256, 256>>>(W1, w1, DM * DFF / 4);
    round_tf32_kernel<<<(DFF * DM / 4 + 255) / 256, 256>>>(W2, w2, DFF * DM / 4);

    const dim3 gProj(DM / BN, TOK / BM);    // (8, 64)
    const dim3 gFF1(DFF / BN, TOK / BM);    // (32, 64)

    // 1) h = LN1(x)   (rounded to tf32)
    ln_kernel<1><<<TOK, 256>>>(x, ln1_g, ln1_b, h);
    // 2) q/k/v projections (outputs rounded to tf32 for the attention MMAs)
    gemm_tc<0,1><<<gProj, 256, GEMM_SMEM_BYTES>>>(h, wq, bq, nullptr, q, TOK, DM, DM);
    gemm_tc<0,1><<<gProj, 256, GEMM_SMEM_BYTES>>>(h, wk, bk, nullptr, k, TOK, DM, DM);
    gemm_tc<0,1><<<gProj, 256, GEMM_SMEM_BYTES>>>(h, wv, bv, nullptr, v, TOK, DM, DM);
    // 3) transpose K for B-fragment layout
    transpose_k_kernel<<<dim3(SEQ / 32, DK / 32, NH * BATCH), dim3(32, 8)>>>(k, kt);
    // 4) tensor-core flash attention (ctx rounded to tf32 internally)
    attn_tc_kernel<<<dim3(SEQ / 128, NH, BATCH), 256, ATTN_TC_SMEM>>>(q, kt, v, ctx);
    // 5) x1 = x + ctx @ Wo + bo
    gemm_tc<1,0><<<gProj, 256, GEMM_SMEM_BYTES>>>(ctx, wo, bo, x, x1, TOK, DM, DM);
    // 6) h2 = LN2(x1)  (rounded)
    ln_kernel<1><<<TOK, 256>>>(x1, ln2_g, ln2_b, h2);
    // 7) ff = gelu(h2 @ W1 + b1)  (rounded in epilogue)
    gemm_tc<2,0><<<gFF1, 256, GEMM_SMEM_BYTES>>>(h2, w1, b1, nullptr, ff, TOK, DFF, DM);
    // 8) out = x1 + ff @ W2 + b2
    gemm_tc<1,0><<<gProj, 256, GEMM_SMEM_BYTES>>>(ff, w2, b2, x1, out, TOK, DM, DFF);
}

// round 5
// speedup vs baseline: 3.5378x; 1.0857x over previous
#include <cuda_runtime.h>
#include <math.h>
#include <stdint.h>

#define TOK   8192      // 4 * 2048 tokens
#define DM    1024
#define DFF   4096
#define NH    16
#define DK    64
#define SEQ   2048
#define BATCH 4
#define QLD   (3 * DM)  // packed qkv row stride

// ---------------- scratch (static device globals; no allocation) ----------------
__device__ float g_h   [TOK * DM];
__device__ float g_qkv [TOK * QLD];
__device__ float g_kt  [TOK * DM];     // K transposed: [(h*DK+dk)][BATCH*SEQ]
__device__ float g_ctx [TOK * DM];
__device__ float g_x1  [TOK * DM];
__device__ float g_h2  [TOK * DM];
__device__ float g_ff  [TOK * DFF];
// tf32-rounded weights
__device__ float g_wqkv[DM * QLD];
__device__ float g_bqkv[QLD];
__device__ float g_wo  [DM * DM];
__device__ float g_w1  [DM * DFF];
__device__ float g_w2  [DFF * DM];

// ---------------- helpers ----------------
__device__ __forceinline__ float to_tf32(float x) {
    uint32_t r;
    asm("cvt.rna.tf32.f32 %0, %1;" : "=r"(r) : "f"(x));
    return __uint_as_float(r);
}
__device__ __forceinline__ uint32_t smem_u32(const void* p) {
    uint32_t a;
    asm("{ .reg .u64 t; cvta.to.shared.u64 t, %1; cvt.u32.u64 %0, t; }" : "=r"(a) : "l"(p));
    return a;
}
__device__ __forceinline__ void cp_async16(uint32_t dst, const void* src) {
    asm volatile("cp.async.cg.shared.global [%0], [%1], 16;" :: "r"(dst), "l"(src));
}
__device__ __forceinline__ void cp_commit() {
    asm volatile("cp.async.commit_group;" ::: "memory");
}
__device__ __forceinline__ void mma_tf32_16x8x8(float* d, const uint32_t* a, const uint32_t* b) {
    asm volatile(
        "mma.sync.aligned.m16n8k8.row.col.f32.tf32.tf32.f32 "
        "{%0,%1,%2,%3}, {%4,%5,%6,%7}, {%8,%9}, {%0,%1,%2,%3};"
        : "+f"(d[0]), "+f"(d[1]), "+f"(d[2]), "+f"(d[3])
        : "r"(a[0]), "r"(a[1]), "r"(a[2]), "r"(a[3]), "r"(b[0]), "r"(b[1]));
}

// ---------------- weight pre-round (contiguous) ----------------
__global__ void __launch_bounds__(256) round_tf32_kernel(const float* __restrict__ in,
                                                         float* __restrict__ out, int n4)
{
    const int i = blockIdx.x * blockDim.x + threadIdx.x;
    if (i < n4) {
        float4 v = ((const float4*)in)[i];
        v.x = to_tf32(v.x); v.y = to_tf32(v.y);
        v.z = to_tf32(v.z); v.w = to_tf32(v.w);
        ((float4*)out)[i] = v;
    }
}

// ---------------- weight pre-round + pack into [DM][QLD] at column offset ----------------
__global__ void __launch_bounds__(256) round_pack_kernel(const float* __restrict__ in,
                                                         float* __restrict__ out, int coloff)
{
    const int i = blockIdx.x * blockDim.x + threadIdx.x;   // over DM*DM/4
    const int k = i / (DM / 4);
    const int c4 = i % (DM / 4);
    float4 v = ((const float4*)in)[i];
    v.x = to_tf32(v.x); v.y = to_tf32(v.y);
    v.z = to_tf32(v.z); v.w = to_tf32(v.w);
    *(float4*)(out + (size_t)k * QLD + coloff + c4 * 4) = v;
}

// ---------------- bias pack (exact copy, no rounding) ----------------
__global__ void __launch_bounds__(256) pack_bias3_kernel(const float* __restrict__ b0,
                                                         const float* __restrict__ b1,
                                                         const float* __restrict__ b2,
                                                         float* __restrict__ out)
{
    const int i = blockIdx.x * blockDim.x + threadIdx.x;   // 0..767 float4s
    const int which = i >> 8, c4 = i & 255;
    const float* src = which == 0 ? b0 : (which == 1 ? b1 : b2);
    ((float4*)out)[which * 256 + c4] = ((const float4*)src)[c4];
}

// ---------------- K transpose: qkv[b*SEQ+s][DM + h*DK+dk] -> kt[(h*DK+dk)][b*SEQ+s] ----------------
__global__ void __launch_bounds__(256) transpose_k_kernel(const float* __restrict__ in,
                                                          float* __restrict__ out)
{
    __shared__ float tile[32][33];
    const int s0 = blockIdx.x * 32;
    const int d0 = blockIdx.y * 32;
    const int h  = blockIdx.z & (NH - 1);
    const int b  = blockIdx.z >> 4;
    const int txx = threadIdx.x, tyy = threadIdx.y;

    const float* ip = in + ((size_t)(b * SEQ + s0)) * QLD + DM + h * DK + d0;
    #pragma unroll
    for (int i = tyy; i < 32; i += 8)
        tile[i][txx] = ip[(size_t)i * QLD + txx];
    __syncthreads();
    float* op = out + ((size_t)(h * DK + d0)) * (BATCH * SEQ) + (size_t)b * SEQ + s0;
    #pragma unroll
    for (int i = tyy; i < 32; i += 8)
        op[(size_t)i * (BATCH * SEQ) + txx] = tile[txx][i];
}

// ---------------- LayerNorm (ROUND=1: round output to tf32) ----------------
template <int ROUND>
__global__ void __launch_bounds__(256) ln_kernel(const float* __restrict__ x,
                                                 const float* __restrict__ g,
                                                 const float* __restrict__ b,
                                                 float* __restrict__ out)
{
    const int row = blockIdx.x;
    const int tid = threadIdx.x;
    const float4 v = ((const float4*)(x + (size_t)row * DM))[tid];

    float s  = v.x + v.y + v.z + v.w;
    float ss = v.x * v.x + v.y * v.y + v.z * v.z + v.w * v.w;
    #pragma unroll
    for (int o = 16; o; o >>= 1) {
        s  += __shfl_xor_sync(0xffffffffu, s,  o);
        ss += __shfl_xor_sync(0xffffffffu, ss, o);
    }
    __shared__ float sb[8], sb2[8];
    if ((tid & 31) == 0) { sb[tid >> 5] = s; sb2[tid >> 5] = ss; }
    __syncthreads();
    float ts = 0.f, ts2 = 0.f;
    #pragma unroll
    for (int i = 0; i < 8; i++) { ts += sb[i]; ts2 += sb2[i]; }

    const float mu  = ts * (1.0f / DM);
    const float var = ts2 * (1.0f / DM) - mu * mu;
    const float inv = rsqrtf(var + 1e-5f);

    const float4 gg = ((const float4*)g)[tid];
    const float4 bb = ((const float4*)b)[tid];
    float4 o;
    o.x = (v.x - mu) * inv * gg.x + bb.x;
    o.y = (v.y - mu) * inv * gg.y + bb.y;
    o.z = (v.z - mu) * inv * gg.z + bb.z;
    o.w = (v.w - mu) * inv * gg.w + bb.w;
    if (ROUND) {
        o.x = to_tf32(o.x); o.y = to_tf32(o.y);
        o.z = to_tf32(o.z); o.w = to_tf32(o.w);
    }
    ((float4*)(out + (size_t)row * DM))[tid] = o;
}

// ---------------- tf32 mma.sync GEMM: 128x128 tile, BK=32, 3-stage, 2 CTAs/SM ----------------
// EPI: 0 = bias; 1 = bias + residual; 2 = gelu(bias) rounded
// ROUND: round output to tf32
__device__ __forceinline__ float gelu_exact(float v) {
    return 0.5f * v * (1.0f + erff(v * 0.70710678118654752440f));
}

#define BM 128
#define BN 128
#define BK 32
#define STAGES 3
#define AS_STRIDE 36
#define BS_STRIDE 136
#define A_ST_FLOATS (BM * AS_STRIDE)        // 4608
#define B_ST_FLOATS (BK * BS_STRIDE)        // 4352
#define STAGE_FLOATS (A_ST_FLOATS + B_ST_FLOATS)
#define GEMM_SMEM_BYTES (STAGES * STAGE_FLOATS * 4)   // 107520

template <int EPI, int ROUND>
__global__ void __launch_bounds__(256, 2) gemm_tc(
    const float* __restrict__ A, const float* __restrict__ B,
    const float* __restrict__ bias, const float* __restrict__ res,
    float* __restrict__ C, int M, int N, int K)
{
    extern __shared__ float smf[];
    const uint32_t sbase = smem_u32(smf);

    const int tid = threadIdx.x;
    const int wid = tid >> 5;
    const int lane = tid & 31;
    const int g = lane >> 2;        // 0..7
    const int tig = lane & 3;       // 0..3
    const int wm = wid & 1;         // 0..1
    const int wn = wid >> 1;        // 0..3

    const int n0 = blockIdx.x * BN;
    const int m0 = blockIdx.y * BM;
    const int NT = K / BK;

    float acc[4][4][4];
    #pragma unroll
    for (int mt = 0; mt < 4; mt++)
        #pragma unroll
        for (int nt = 0; nt < 4; nt++)
            #pragma unroll
            for (int e = 0; e < 4; e++) acc[mt][nt][e] = 0.f;

    auto load_stage = [&](int st, int t) {
        const uint32_t aoff = sbase + (uint32_t)(st * STAGE_FLOATS) * 4u;
        const uint32_t boff = aoff + A_ST_FLOATS * 4u;
        #pragma unroll
        for (int i = 0; i < 4; i++) {
            const int f4 = i * 256 + tid;
            const int ar = f4 >> 3, ac4 = f4 & 7;
            cp_async16(aoff + (uint32_t)(ar * AS_STRIDE + ac4 * 4) * 4u,
                       A + (size_t)(m0 + ar) * K + (size_t)t * BK + ac4 * 4);
            const int bk = f4 >> 5, bn4 = f4 & 31;
            cp_async16(boff + (uint32_t)(bk * BS_STRIDE + bn4 * 4) * 4u,
                       B + (size_t)((size_t)t * BK + bk) * N + n0 + bn4 * 4);
        }
    };

    #pragma unroll
    for (int t = 0; t < STAGES - 1; t++) {
        load_stage(t, t);
        cp_commit();
    }

    for (int t = 0; t < NT; t++) {
        asm volatile("cp.async.wait_group %0;" :: "n"(STAGES - 2) : "memory");
        __syncthreads();

        const int pf = t + STAGES - 1;
        if (pf < NT) load_stage(pf % STAGES, pf);
        cp_commit();

        const int st = t % STAGES;
        const float* sA = smf + st * STAGE_FLOATS + (wm * 64) * AS_STRIDE;
        const float* sB = smf + st * STAGE_FLOATS + A_ST_FLOATS + wn * 32;

        #pragma unroll
        for (int k0 = 0; k0 < BK; k0 += 8) {
            uint32_t afr[4][4], bfr[4][2];
            #pragma unroll
            for (int mt = 0; mt < 4; mt++) {
                const uint32_t* p = (const uint32_t*)(sA + (mt * 16 + g) * AS_STRIDE + k0 + tig);
                afr[mt][0] = p[0];
                afr[mt][1] = p[8 * AS_STRIDE];
                afr[mt][2] = p[4];
                afr[mt][3] = p[8 * AS_STRIDE + 4];
            }
            #pragma unroll
            for (int nt = 0; nt < 4; nt++) {
                const uint32_t* p = (const uint32_t*)(sB + (k0 + tig) * BS_STRIDE + nt * 8 + g);
                bfr[nt][0] = p[0];
                bfr[nt][1] = p[4 * BS_STRIDE];
            }
            #pragma unroll
            for (int mt = 0; mt < 4; mt++)
                #pragma unroll
                for (int nt = 0; nt < 4; nt++)
                    mma_tf32_16x8x8(acc[mt][nt], afr[mt], bfr[nt]);
        }
    }

    // ---- epilogue ----
    #pragma unroll
    for (int mt = 0; mt < 4; mt++) {
        const int r0 = m0 + wm * 64 + mt * 16 + g;
        float* c0 = C + (size_t)r0 * N;
        float* c1 = C + (size_t)(r0 + 8) * N;
        const float* rr0 = (EPI == 1) ? (res + (size_t)r0 * DM) : nullptr;
        const float* rr1 = (EPI == 1) ? (res + (size_t)(r0 + 8) * DM) : nullptr;
        #pragma unroll
        for (int nt = 0; nt < 4; nt++) {
            const int col = n0 + wn * 32 + nt * 8 + 2 * tig;
            const float bx = bias[col], by = bias[col + 1];
            float v0 = acc[mt][nt][0] + bx, v1 = acc[mt][nt][1] + by;
            float v2 = acc[mt][nt][2] + bx, v3 = acc[mt][nt][3] + by;
            if (EPI == 2) {
                v0 = to_tf32(gelu_exact(v0)); v1 = to_tf32(gelu_exact(v1));
                v2 = to_tf32(gelu_exact(v2)); v3 = to_tf32(gelu_exact(v3));
            }
            if (EPI == 1) {
                v0 += rr0[col]; v1 += rr0[col + 1];
                v2 += rr1[col]; v3 += rr1[col + 1];
            }
            if (ROUND) {
                v0 = to_tf32(v0); v1 = to_tf32(v1);
                v2 = to_tf32(v2); v3 = to_tf32(v3);
            }
            *(float2*)(c0 + col) = make_float2(v0, v1);
            *(float2*)(c1 + col) = make_float2(v2, v3);
        }
    }
}

// ---------------- tensor-core flash attention ----------------
// q/v live inside packed qkv (row stride QLD); kT is [(h*DK+dk)][BATCH*SEQ].
#define KT_STRIDE 136
#define VS_STRIDE 72
#define PS_STRIDE 132
#define KT_FLOATS (64 * KT_STRIDE)
#define VS_FLOATS (128 * VS_STRIDE)
#define PS_FLOATS (128 * PS_STRIDE)
#define ATTN_TC_FLOATS (2 * KT_FLOATS + 2 * VS_FLOATS + PS_FLOATS)
#define ATTN_TC_SMEM (ATTN_TC_FLOATS * 4)

__global__ void __launch_bounds__(256) attn_tc_kernel(const float* __restrict__ q,
                                                      const float* __restrict__ kT,
                                                      const float* __restrict__ v,
                                                      float* __restrict__ out)
{
    extern __shared__ float smf[];
    float* KTs = smf;
    float* VSs = KTs + 2 * KT_FLOATS;
    float* PSs = VSs + 2 * VS_FLOATS;
    const uint32_t sbase = smem_u32(smf);

    const int tid = threadIdx.x;
    const int w = tid >> 5;
    const int lane = tid & 31;
    const int g = lane >> 2;
    const int tig = lane & 3;

    const int qt = blockIdx.x, h = blockIdx.y, b = blockIdx.z;

    uint32_t qa[8][4];
    {
        const float* qb = q + ((size_t)(b * SEQ + qt * 128 + w * 16)) * QLD + h * DK;
        #pragma unroll
        for (int kt = 0; kt < 8; kt++) {
            const int c = kt * 8 + tig;
            qa[kt][0] = __float_as_uint(0.125f * qb[(size_t)g * QLD + c]);
            qa[kt][1] = __float_as_uint(0.125f * qb[(size_t)(g + 8) * QLD + c]);
            qa[kt][2] = __float_as_uint(0.125f * qb[(size_t)g * QLD + c + 4]);
            qa[kt][3] = __float_as_uint(0.125f * qb[(size_t)(g + 8) * QLD + c + 4]);
        }
    }

    float o[8][4];
    #pragma unroll
    for (int nt = 0; nt < 8; nt++)
        #pragma unroll
        for (int e = 0; e < 4; e++) o[nt][e] = 0.f;
    float m0 = -1e30f, m1 = -1e30f, l0 = 0.f, l1 = 0.f;

    auto load_kv = [&](int t, int buf) {
        const uint32_t kdst = sbase + (uint32_t)(buf * KT_FLOATS) * 4u;
        const uint32_t vdst = sbase + (uint32_t)(2 * KT_FLOATS + buf * VS_FLOATS) * 4u;
        const float* ksrc = kT + (size_t)(h * DK) * (BATCH * SEQ) + (size_t)b * SEQ + (size_t)t * 128;
        const float* vsrc = v + ((size_t)(b * SEQ + t * 128)) * QLD + h * DK;
        #pragma unroll
        for (int i = 0; i < 8; i++) {
            const int c = i * 256 + tid;
            const int kr = c >> 5, kc = c & 31;
            cp_async16(kdst + (uint32_t)(kr * KT_STRIDE + kc * 4) * 4u,
                       ksrc + (size_t)kr * (BATCH * SEQ) + kc * 4);
            const int vr = c >> 4, vc = c & 15;
            cp_async16(vdst + (uint32_t)(vr * VS_STRIDE + vc * 4) * 4u,
                       vsrc + (size_t)vr * QLD + vc * 4);
        }
    };

    load_kv(0, 0);
    cp_commit();

    const int NKV = SEQ / 128;
    for (int t = 0; t < NKV; t++) {
        asm volatile("cp.async.wait_group 0;" ::: "memory");
        __syncthreads();
        if (t + 1 < NKV) { load_kv(t + 1, (t + 1) & 1); cp_commit(); }

        float s[16][4];
        #pragma unroll
        for (int nt = 0; nt < 16; nt++)
            #pragma unroll
            for (int e = 0; e < 4; e++) s[nt][e] = 0.f;

        {
            const uint32_t* kp = (const uint32_t*)(KTs + (t & 1) * KT_FLOATS);
            #pragma unroll
            for (int k8 = 0; k8 < 8; k8++) {
                #pragma unroll
                for (int nt = 0; nt < 16; nt++) {
                    uint32_t bfr[2];
                    bfr[0] = kp[(k8 * 8 + tig) * KT_STRIDE + nt * 8 + g];
                    bfr[1] = kp[(k8 * 8 + tig + 4) * KT_STRIDE + nt * 8 + g];
                    mma_tf32_16x8x8(s[nt], qa[k8], bfr);
                }
            }
        }

        float rmax0 = -1e30f, rmax1 = -1e30f;
        #pragma unroll
        for (int nt = 0; nt < 16; nt++) {
            rmax0 = fmaxf(rmax0, fmaxf(s[nt][0], s[nt][1]));
            rmax1 = fmaxf(rmax1, fmaxf(s[nt][2], s[nt][3]));
        }
        rmax0 = fmaxf(rmax0, __shfl_xor_sync(0xffffffffu, rmax0, 1));
        rmax0 = fmaxf(rmax0, __shfl_xor_sync(0xffffffffu, rmax0, 2));
        rmax1 = fmaxf(rmax1, __shfl_xor_sync(0xffffffffu, rmax1, 1));
        rmax1 = fmaxf(rmax1, __shfl_xor_sync(0xffffffffu, rmax1, 2));

        const float mn0 = fmaxf(m0, rmax0);
        const float mn1 = fmaxf(m1, rmax1);
        const float al0 = __expf(m0 - mn0);
        const float al1 = __expf(m1 - mn1);
        m0 = mn0; m1 = mn1;

        float rs0 = 0.f, rs1 = 0.f;
        {
            float* ps0 = PSs + (size_t)(w * 16 + g) * PS_STRIDE + 2 * tig;
            float* ps1 = ps0 + 8 * PS_STRIDE;
            #pragma unroll
            for (int nt = 0; nt < 16; nt++) {
                const float p0 = to_tf32(__expf(s[nt][0] - mn0));
                const float p1 = to_tf32(__expf(s[nt][1] - mn0));
                const float p2 = to_tf32(__expf(s[nt][2] - mn1));
                const float p3 = to_tf32(__expf(s[nt][3] - mn1));
                rs0 += p0 + p1; rs1 += p2 + p3;
                *(float2*)(ps0 + nt * 8) = make_float2(p0, p1);
                *(float2*)(ps1 + nt * 8) = make_float2(p2, p3);
            }
        }
        rs0 += __shfl_xor_sync(0xffffffffu, rs0, 1);
        rs0 += __shfl_xor_sync(0xffffffffu, rs0, 2);
        rs1 += __shfl_xor_sync(0xffffffffu, rs1, 1);
        rs1 += __shfl_xor_sync(0xffffffffu, rs1, 2);
        l0 = l0 * al0 + rs0;
        l1 = l1 * al1 + rs1;

        #pragma unroll
        for (int nt = 0; nt < 8; nt++) {
            o[nt][0] *= al0; o[nt][1] *= al0;
            o[nt][2] *= al1; o[nt][3] *= al1;
        }
        __syncwarp();

        {
            const uint32_t* pp = (const uint32_t*)PSs;
            const uint32_t* vp = (const uint32_t*)(VSs + (t & 1) * VS_FLOATS);
            #pragma unroll
            for (int k16 = 0; k16 < 16; k16++) {
                uint32_t a[4];
                a[0] = pp[(w * 16 + g) * PS_STRIDE + k16 * 8 + tig];
                a[1] = pp[(w * 16 + g + 8) * PS_STRIDE + k16 * 8 + tig];
                a[2] = pp[(w * 16 + g) * PS_STRIDE + k16 * 8 + tig + 4];
                a[3] = pp[(w * 16 + g + 8) * PS_STRIDE + k16 * 8 + tig + 4];
                #pragma unroll
                for (int nt = 0; nt < 8; nt++) {
                    uint32_t bfr[2];
                    bfr[0] = vp[(k16 * 8 + tig) * VS_STRIDE + nt * 8 + g];
                    bfr[1] = vp[(k16 * 8 + tig + 4) * VS_STRIDE + nt * 8 + g];
                    mma_tf32_16x8x8(o[nt], a, bfr);
                }
            }
        }
        __syncwarp();
    }

    {
        const float i0 = 1.0f / l0, i1 = 1.0f / l1;
        const int r0 = qt * 128 + w * 16 + g;
        float* ob0 = out + ((size_t)(b * SEQ + r0)) * DM + h * DK + 2 * tig;
        float* ob1 = ob0 + 8 * DM;
        #pragma unroll
        for (int nt = 0; nt < 8; nt++) {
            *(float2*)(ob0 + nt * 8) = make_float2(to_tf32(o[nt][0] * i0), to_tf32(o[nt][1] * i0));
            *(float2*)(ob1 + nt * 8) = make_float2(to_tf32(o[nt][2] * i1), to_tf32(o[nt][3] * i1));
        }
    }
}

// ---------------- host launcher ----------------
extern "C" void kernel_launch(void* const* d_in, const int* in_sizes, int n_in,
                              void* d_out, int out_size)
{
    (void)in_sizes; (void)n_in; (void)out_size;
    const float* x     = (const float*)d_in[0];
    const float* Wq    = (const float*)d_in[1];
    const float* bq    = (const float*)d_in[2];
    const float* Wk    = (const float*)d_in[3];
    const float* bk    = (const float*)d_in[4];
    const float* Wv    = (const float*)d_in[5];
    const float* bv    = (const float*)d_in[6];
    const float* Wo    = (const float*)d_in[7];
    const float* bo    = (const float*)d_in[8];
    const float* ln1_g = (const float*)d_in[9];
    const float* ln1_b = (const float*)d_in[10];
    const float* W1    = (const float*)d_in[11];
    const float* b1    = (const float*)d_in[12];
    const float* W2    = (const float*)d_in[13];
    const float* b2    = (const float*)d_in[14];
    const float* ln2_g = (const float*)d_in[15];
    const float* ln2_b = (const float*)d_in[16];
    float* out = (float*)d_out;

    float *h, *qkv, *kt, *ctx, *x1, *h2, *ff;
    float *wqkv, *bqkv, *wo, *w1, *w2;
    cudaGetSymbolAddress((void**)&h,    g_h);
    cudaGetSymbolAddress((void**)&qkv,  g_qkv);
    cudaGetSymbolAddress((void**)&kt,   g_kt);
    cudaGetSymbolAddress((void**)&ctx,  g_ctx);
    cudaGetSymbolAddress((void**)&x1,   g_x1);
    cudaGetSymbolAddress((void**)&h2,   g_h2);
    cudaGetSymbolAddress((void**)&ff,   g_ff);
    cudaGetSymbolAddress((void**)&wqkv, g_wqkv);
    cudaGetSymbolAddress((void**)&bqkv, g_bqkv);
    cudaGetSymbolAddress((void**)&wo,   g_wo);
    cudaGetSymbolAddress((void**)&w1,   g_w1);
    cudaGetSymbolAddress((void**)&w2,   g_w2);

    cudaFuncSetAttribute(attn_tc_kernel, cudaFuncAttributeMaxDynamicSharedMemorySize, ATTN_TC_SMEM);
    cudaFuncSetAttribute(gemm_tc<0,1>, cudaFuncAttributeMaxDynamicSharedMemorySize, GEMM_SMEM_BYTES);
    cudaFuncSetAttribute(gemm_tc<1,0>, cudaFuncAttributeMaxDynamicSharedMemorySize, GEMM_SMEM_BYTES);
    cudaFuncSetAttribute(gemm_tc<2,0>, cudaFuncAttributeMaxDynamicSharedMemorySize, GEMM_SMEM_BYTES);

    // 0) pre-round weights; pack QKV weights/biases
    round_pack_kernel<<<DM * DM / 4 / 256, 256>>>(Wq, wqkv, 0);
    round_pack_kernel<<<DM * DM / 4 / 256, 256>>>(Wk, wqkv, DM);
    round_pack_kernel<<<DM * DM / 4 / 256, 256>>>(Wv, wqkv, 2 * DM);
    pack_bias3_kernel<<<3, 256>>>(bq, bk, bv, bqkv);
    round_tf32_kernel<<<DM * DM / 4 / 256, 256>>>(Wo, wo, DM * DM / 4);
    round_tf32_kernel<<<DM * DFF / 4 / 256, 256>>>(W1, w1, DM * DFF / 4);
    round_tf32_kernel<<<DFF * DM / 4 / 256, 256>>>(W2, w2, DFF * DM / 4);

    const dim3 gQKV(QLD / BN, TOK / BM);    // (24, 64)
    const dim3 gProj(DM / BN, TOK / BM);    // (8, 64)
    const dim3 gFF1(DFF / BN, TOK / BM);    // (32, 64)

    // 1) h = LN1(x)   (rounded to tf32)
    ln_kernel<1><<<TOK, 256>>>(x, ln1_g, ln1_b, h);
    // 2) fused qkv projection (outputs rounded to tf32)
    gemm_tc<0,1><<<gQKV, 256, GEMM_SMEM_BYTES>>>(h, wqkv, bqkv, nullptr, qkv, TOK, QLD, DM);
    // 3) transpose K
    transpose_k_kernel<<<dim3(SEQ / 32, DK / 32, NH * BATCH), dim3(32, 8)>>>(qkv, kt);
    // 4) tensor-core flash attention
    attn_tc_kernel<<<dim3(SEQ / 128, NH, BATCH), 256, ATTN_TC_SMEM>>>(qkv, kt, qkv + 2 * DM, ctx);
    // 5) x1 = x + ctx @ Wo + bo
    gemm_tc<1,0><<<gProj, 256, GEMM_SMEM_BYTES>>>(ctx, wo, bo, x, x1, TOK, DM, DM);
    // 6) h2 = LN2(x1)  (rounded)
    ln_kernel<1><<<TOK, 256>>>(x1, ln2_g, ln2_b, h2);
    // 7) ff = gelu(h2 @ W1 + b1)  (rounded in epilogue)
    gemm_tc<2,0><<<gFF1, 256, GEMM_SMEM_BYTES>>>(h2, w1, b1, nullptr, ff, TOK, DFF, DM);
    // 8) out = x1 + ff @ W2 + b2
    gemm_tc<1,0><<<gProj, 256, GEMM_SMEM_BYTES>>>(ff, w2, b2, x1, out, TOK, DM, DFF);
}

// round 6
// speedup vs baseline: 3.5523x; 1.0041x over previous
#include <cuda_runtime.h>
#include <math.h>
#include <stdint.h>

#define TOK   8192      // 4 * 2048 tokens
#define DM    1024
#define DFF   4096
#define NH    16
#define DK    64
#define SEQ   2048
#define BATCH 4
#define QLD   (3 * DM)  // packed qkv row stride

// ---------------- scratch (static device globals; no allocation) ----------------
__device__ float g_h   [TOK * DM];
__device__ float g_qkv [TOK * QLD];
__device__ float g_kt  [TOK * DM];     // K transposed: [(h*DK+dk)][BATCH*SEQ]
__device__ float g_ctx [TOK * DM];
__device__ float g_x1  [TOK * DM];
__device__ float g_h2  [TOK * DM];
__device__ float g_ff  [TOK * DFF];
// tf32-rounded weights
__device__ float g_wqkv[DM * QLD];
__device__ float g_bqkv[QLD];
__device__ float g_wo  [DM * DM];
__device__ float g_w1  [DM * DFF];
__device__ float g_w2  [DFF * DM];

// ---------------- helpers ----------------
__device__ __forceinline__ float to_tf32(float x) {
    uint32_t r;
    asm("cvt.rna.tf32.f32 %0, %1;" : "=r"(r) : "f"(x));
    return __uint_as_float(r);
}
__device__ __forceinline__ uint32_t smem_u32(const void* p) {
    uint32_t a;
    asm("{ .reg .u64 t; cvta.to.shared.u64 t, %1; cvt.u32.u64 %0, t; }" : "=r"(a) : "l"(p));
    return a;
}
__device__ __forceinline__ void cp_async16(uint32_t dst, const void* src) {
    asm volatile("cp.async.cg.shared.global [%0], [%1], 16;" :: "r"(dst), "l"(src));
}
__device__ __forceinline__ void cp_commit() {
    asm volatile("cp.async.commit_group;" ::: "memory");
}
__device__ __forceinline__ void mma_tf32_16x8x8(float* d, const uint32_t* a, const uint32_t* b) {
    asm volatile(
        "mma.sync.aligned.m16n8k8.row.col.f32.tf32.tf32.f32 "
        "{%0,%1,%2,%3}, {%4,%5,%6,%7}, {%8,%9}, {%0,%1,%2,%3};"
        : "+f"(d[0]), "+f"(d[1]), "+f"(d[2]), "+f"(d[3])
        : "r"(a[0]), "r"(a[1]), "r"(a[2]), "r"(a[3]), "r"(b[0]), "r"(b[1]));
}
__device__ __forceinline__ float4 round4(float4 v) {
    v.x = to_tf32(v.x); v.y = to_tf32(v.y);
    v.z = to_tf32(v.z); v.w = to_tf32(v.w);
    return v;
}

// ---------------- fused weight prep: one launch for all rounding/packing ----------------
// Work items (float4 granularity):
//   [0, 3*W4)           : Wq/Wk/Wv -> rounded + packed into wqkv [DM][QLD]
//   [3*W4, 4*W4)        : Wo -> wo
//   [4*W4, 4*W4+F4)     : W1 -> w1
//   [4*W4+F4, 4*W4+2F4) : W2 -> w2
//   last 768            : bq/bk/bv -> bqkv (copy, no rounding)
#define W4 (DM * DM / 4)
#define F4 (DM * DFF / 4)
#define PREP_TOTAL (4 * W4 + 2 * F4 + 3 * (DM / 4))

__global__ void __launch_bounds__(256) prep_weights_kernel(
    const float* __restrict__ Wq, const float* __restrict__ Wk, const float* __restrict__ Wv,
    const float* __restrict__ bq, const float* __restrict__ bk, const float* __restrict__ bv,
    const float* __restrict__ Wo, const float* __restrict__ W1, const float* __restrict__ W2,
    float* __restrict__ wqkv, float* __restrict__ bqkv,
    float* __restrict__ wo, float* __restrict__ w1, float* __restrict__ w2)
{
    const int i = blockIdx.x * blockDim.x + threadIdx.x;
    if (i < 3 * W4) {
        const int which = i / W4, j = i - which * W4;
        const int k = j / (DM / 4), c4 = j % (DM / 4);
        const float* src = which == 0 ? Wq : (which == 1 ? Wk : Wv);
        const float4 v = round4(((const float4*)src)[j]);
        *(float4*)(wqkv + (size_t)k * QLD + which * DM + c4 * 4) = v;
    } else if (i < 4 * W4) {
        const int j = i - 3 * W4;
        ((float4*)wo)[j] = round4(((const float4*)Wo)[j]);
    } else if (i < 4 * W4 + F4) {
        const int j = i - 4 * W4;
        ((float4*)w1)[j] = round4(((const float4*)W1)[j]);
    } else if (i < 4 * W4 + 2 * F4) {
        const int j = i - (4 * W4 + F4);
        ((float4*)w2)[j] = round4(((const float4*)W2)[j]);
    } else if (i < PREP_TOTAL) {
        const int j = i - (4 * W4 + 2 * F4);
        const int which = j / (DM / 4), c4 = j % (DM / 4);
        const float* src = which == 0 ? bq : (which == 1 ? bk : bv);
        ((float4*)bqkv)[which * (DM / 4) + c4] = ((const float4*)src)[c4];
    }
}

// ---------------- LayerNorm (ROUND=1: round output to tf32) ----------------
template <int ROUND>
__global__ void __launch_bounds__(256) ln_kernel(const float* __restrict__ x,
                                                 const float* __restrict__ g,
                                                 const float* __restrict__ b,
                                                 float* __restrict__ out)
{
    const int row = blockIdx.x;
    const int tid = threadIdx.x;
    const float4 v = ((const float4*)(x + (size_t)row * DM))[tid];

    float s  = v.x + v.y + v.z + v.w;
    float ss = v.x * v.x + v.y * v.y + v.z * v.z + v.w * v.w;
    #pragma unroll
    for (int o = 16; o; o >>= 1) {
        s  += __shfl_xor_sync(0xffffffffu, s,  o);
        ss += __shfl_xor_sync(0xffffffffu, ss, o);
    }
    __shared__ float sb[8], sb2[8];
    if ((tid & 31) == 0) { sb[tid >> 5] = s; sb2[tid >> 5] = ss; }
    __syncthreads();
    float ts = 0.f, ts2 = 0.f;
    #pragma unroll
    for (int i = 0; i < 8; i++) { ts += sb[i]; ts2 += sb2[i]; }

    const float mu  = ts * (1.0f / DM);
    const float var = ts2 * (1.0f / DM) - mu * mu;
    const float inv = rsqrtf(var + 1e-5f);

    const float4 gg = ((const float4*)g)[tid];
    const float4 bb = ((const float4*)b)[tid];
    float4 o;
    o.x = (v.x - mu) * inv * gg.x + bb.x;
    o.y = (v.y - mu) * inv * gg.y + bb.y;
    o.z = (v.z - mu) * inv * gg.z + bb.z;
    o.w = (v.w - mu) * inv * gg.w + bb.w;
    if (ROUND) o = round4(o);
    ((float4*)(out + (size_t)row * DM))[tid] = o;
}

// ---------------- K transpose: qkv[b*SEQ+s][DM + h*DK+dk] -> kt[(h*DK+dk)][b*SEQ+s] ----------------
__global__ void __launch_bounds__(256) transpose_k_kernel(const float* __restrict__ in,
                                                          float* __restrict__ out)
{
    __shared__ float tile[32][33];
    const int s0 = blockIdx.x * 32;
    const int d0 = blockIdx.y * 32;
    const int h  = blockIdx.z & (NH - 1);
    const int b  = blockIdx.z >> 4;
    const int txx = threadIdx.x, tyy = threadIdx.y;

    const float* ip = in + ((size_t)(b * SEQ + s0)) * QLD + DM + h * DK + d0;
    #pragma unroll
    for (int i = tyy; i < 32; i += 8)
        tile[i][txx] = ip[(size_t)i * QLD + txx];
    __syncthreads();
    float* op = out + ((size_t)(h * DK + d0)) * (BATCH * SEQ) + (size_t)b * SEQ + s0;
    #pragma unroll
    for (int i = tyy; i < 32; i += 8)
        op[(size_t)i * (BATCH * SEQ) + txx] = tile[txx][i];
}

// ---------------- tf32 mma.sync GEMM: 128x128 tile, BK=32, 3-stage, 2 CTAs/SM ----------------
__device__ __forceinline__ float gelu_exact(float v) {
    return 0.5f * v * (1.0f + erff(v * 0.70710678118654752440f));
}

#define BM 128
#define BN 128
#define BK 32
#define STAGES 3
#define AS_STRIDE 36
#define BS_STRIDE 136
#define A_ST_FLOATS (BM * AS_STRIDE)        // 4608
#define B_ST_FLOATS (BK * BS_STRIDE)        // 4352
#define STAGE_FLOATS (A_ST_FLOATS + B_ST_FLOATS)
#define GEMM_SMEM_BYTES (STAGES * STAGE_FLOATS * 4)   // 107520

template <int EPI, int ROUND>
__global__ void __launch_bounds__(256, 2) gemm_tc(
    const float* __restrict__ A, const float* __restrict__ B,
    const float* __restrict__ bias, const float* __restrict__ res,
    float* __restrict__ C, int M, int N, int K)
{
    extern __shared__ float smf[];
    const uint32_t sbase = smem_u32(smf);

    const int tid = threadIdx.x;
    const int wid = tid >> 5;
    const int lane = tid & 31;
    const int g = lane >> 2;        // 0..7
    const int tig = lane & 3;       // 0..3
    const int wm = wid & 1;         // 0..1
    const int wn = wid >> 1;        // 0..3

    const int n0 = blockIdx.x * BN;
    const int m0 = blockIdx.y * BM;
    const int NT = K / BK;

    float acc[4][4][4];
    #pragma unroll
    for (int mt = 0; mt < 4; mt++)
        #pragma unroll
        for (int nt = 0; nt < 4; nt++)
            #pragma unroll
            for (int e = 0; e < 4; e++) acc[mt][nt][e] = 0.f;

    auto load_stage = [&](int st, int t) {
        const uint32_t aoff = sbase + (uint32_t)(st * STAGE_FLOATS) * 4u;
        const uint32_t boff = aoff + A_ST_FLOATS * 4u;
        #pragma unroll
        for (int i = 0; i < 4; i++) {
            const int f4 = i * 256 + tid;
            const int ar = f4 >> 3, ac4 = f4 & 7;
            cp_async16(aoff + (uint32_t)(ar * AS_STRIDE + ac4 * 4) * 4u,
                       A + (size_t)(m0 + ar) * K + (size_t)t * BK + ac4 * 4);
            const int bk = f4 >> 5, bn4 = f4 & 31;
            cp_async16(boff + (uint32_t)(bk * BS_STRIDE + bn4 * 4) * 4u,
                       B + (size_t)((size_t)t * BK + bk) * N + n0 + bn4 * 4);
        }
    };

    #pragma unroll
    for (int t = 0; t < STAGES - 1; t++) {
        load_stage(t, t);
        cp_commit();
    }

    for (int t = 0; t < NT; t++) {
        asm volatile("cp.async.wait_group %0;" :: "n"(STAGES - 2) : "memory");
        __syncthreads();

        const int pf = t + STAGES - 1;
        if (pf < NT) load_stage(pf % STAGES, pf);
        cp_commit();

        const int st = t % STAGES;
        const float* sA = smf + st * STAGE_FLOATS + (wm * 64) * AS_STRIDE;
        const float* sB = smf + st * STAGE_FLOATS + A_ST_FLOATS + wn * 32;

        #pragma unroll
        for (int k0 = 0; k0 < BK; k0 += 8) {
            uint32_t afr[4][4], bfr[4][2];
            #pragma unroll
            for (int mt = 0; mt < 4; mt++) {
                const uint32_t* p = (const uint32_t*)(sA + (mt * 16 + g) * AS_STRIDE + k0 + tig);
                afr[mt][0] = p[0];
                afr[mt][1] = p[8 * AS_STRIDE];
                afr[mt][2] = p[4];
                afr[mt][3] = p[8 * AS_STRIDE + 4];
            }
            #pragma unroll
            for (int nt = 0; nt < 4; nt++) {
                const uint32_t* p = (const uint32_t*)(sB + (k0 + tig) * BS_STRIDE + nt * 8 + g);
                bfr[nt][0] = p[0];
                bfr[nt][1] = p[4 * BS_STRIDE];
            }
            #pragma unroll
            for (int mt = 0; mt < 4; mt++)
                #pragma unroll
                for (int nt = 0; nt < 4; nt++)
                    mma_tf32_16x8x8(acc[mt][nt], afr[mt], bfr[nt]);
        }
    }

    // ---- epilogue ----
    #pragma unroll
    for (int mt = 0; mt < 4; mt++) {
        const int r0 = m0 + wm * 64 + mt * 16 + g;
        float* c0 = C + (size_t)r0 * N;
        float* c1 = C + (size_t)(r0 + 8) * N;
        const float* rr0 = (EPI == 1) ? (res + (size_t)r0 * DM) : nullptr;
        const float* rr1 = (EPI == 1) ? (res + (size_t)(r0 + 8) * DM) : nullptr;
        #pragma unroll
        for (int nt = 0; nt < 4; nt++) {
            const int col = n0 + wn * 32 + nt * 8 + 2 * tig;
            const float bx = bias[col], by = bias[col + 1];
            float v0 = acc[mt][nt][0] + bx, v1 = acc[mt][nt][1] + by;
            float v2 = acc[mt][nt][2] + bx, v3 = acc[mt][nt][3] + by;
            if (EPI == 2) {
                v0 = to_tf32(gelu_exact(v0)); v1 = to_tf32(gelu_exact(v1));
                v2 = to_tf32(gelu_exact(v2)); v3 = to_tf32(gelu_exact(v3));
            }
            if (EPI == 1) {
                v0 += rr0[col]; v1 += rr0[col + 1];
                v2 += rr1[col]; v3 += rr1[col + 1];
            }
            if (ROUND) {
                v0 = to_tf32(v0); v1 = to_tf32(v1);
                v2 = to_tf32(v2); v3 = to_tf32(v3);
            }
            *(float2*)(c0 + col) = make_float2(v0, v1);
            *(float2*)(c1 + col) = make_float2(v2, v3);
        }
    }
}

// ---------------- tensor-core flash attention ----------------
#define KT_STRIDE 136
#define VS_STRIDE 72
#define PS_STRIDE 132
#define KT_FLOATS (64 * KT_STRIDE)
#define VS_FLOATS (128 * VS_STRIDE)
#define PS_FLOATS (128 * PS_STRIDE)
#define ATTN_TC_FLOATS (2 * KT_FLOATS + 2 * VS_FLOATS + PS_FLOATS)
#define ATTN_TC_SMEM (ATTN_TC_FLOATS * 4)

__global__ void __launch_bounds__(256) attn_tc_kernel(const float* __restrict__ q,
                                                      const float* __restrict__ kT,
                                                      const float* __restrict__ v,
                                                      float* __restrict__ out)
{
    extern __shared__ float smf[];
    float* KTs = smf;
    float* VSs = KTs + 2 * KT_FLOATS;
    float* PSs = VSs + 2 * VS_FLOATS;
    const uint32_t sbase = smem_u32(smf);

    const int tid = threadIdx.x;
    const int w = tid >> 5;
    const int lane = tid & 31;
    const int g = lane >> 2;
    const int tig = lane & 3;

    const int qt = blockIdx.x, h = blockIdx.y, b = blockIdx.z;

    uint32_t qa[8][4];
    {
        const float* qb = q + ((size_t)(b * SEQ + qt * 128 + w * 16)) * QLD + h * DK;
        #pragma unroll
        for (int kt = 0; kt < 8; kt++) {
            const int c = kt * 8 + tig;
            qa[kt][0] = __float_as_uint(0.125f * qb[(size_t)g * QLD + c]);
            qa[kt][1] = __float_as_uint(0.125f * qb[(size_t)(g + 8) * QLD + c]);
            qa[kt][2] = __float_as_uint(0.125f * qb[(size_t)g * QLD + c + 4]);
            qa[kt][3] = __float_as_uint(0.125f * qb[(size_t)(g + 8) * QLD + c + 4]);
        }
    }

    float o[8][4];
    #pragma unroll
    for (int nt = 0; nt < 8; nt++)
        #pragma unroll
        for (int e = 0; e < 4; e++) o[nt][e] = 0.f;
    float m0 = -1e30f, m1 = -1e30f, l0 = 0.f, l1 = 0.f;

    auto load_kv = [&](int t, int buf) {
        const uint32_t kdst = sbase + (uint32_t)(buf * KT_FLOATS) * 4u;
        const uint32_t vdst = sbase + (uint32_t)(2 * KT_FLOATS + buf * VS_FLOATS) * 4u;
        const float* ksrc = kT + (size_t)(h * DK) * (BATCH * SEQ) + (size_t)b * SEQ + (size_t)t * 128;
        const float* vsrc = v + ((size_t)(b * SEQ + t * 128)) * QLD + h * DK;
        #pragma unroll
        for (int i = 0; i < 8; i++) {
            const int c = i * 256 + tid;
            const int kr = c >> 5, kc = c & 31;
            cp_async16(kdst + (uint32_t)(kr * KT_STRIDE + kc * 4) * 4u,
                       ksrc + (size_t)kr * (BATCH * SEQ) + kc * 4);
            const int vr = c >> 4, vc = c & 15;
            cp_async16(vdst + (uint32_t)(vr * VS_STRIDE + vc * 4) * 4u,
                       vsrc + (size_t)vr * QLD + vc * 4);
        }
    };

    load_kv(0, 0);
    cp_commit();

    const int NKV = SEQ / 128;
    for (int t = 0; t < NKV; t++) {
        asm volatile("cp.async.wait_group 0;" ::: "memory");
        __syncthreads();
        if (t + 1 < NKV) { load_kv(t + 1, (t + 1) & 1); cp_commit(); }

        float s[16][4];
        #pragma unroll
        for (int nt = 0; nt < 16; nt++)
            #pragma unroll
            for (int e = 0; e < 4; e++) s[nt][e] = 0.f;

        {
            const uint32_t* kp = (const uint32_t*)(KTs + (t & 1) * KT_FLOATS);
            #pragma unroll
            for (int k8 = 0; k8 < 8; k8++) {
                #pragma unroll
                for (int nt = 0; nt < 16; nt++) {
                    uint32_t bfr[2];
                    bfr[0] = kp[(k8 * 8 + tig) * KT_STRIDE + nt * 8 + g];
                    bfr[1] = kp[(k8 * 8 + tig + 4) * KT_STRIDE + nt * 8 + g];
                    mma_tf32_16x8x8(s[nt], qa[k8], bfr);
                }
            }
        }

        float rmax0 = -1e30f, rmax1 = -1e30f;
        #pragma unroll
        for (int nt = 0; nt < 16; nt++) {
            rmax0 = fmaxf(rmax0, fmaxf(s[nt][0], s[nt][1]));
            rmax1 = fmaxf(rmax1, fmaxf(s[nt][2], s[nt][3]));
        }
        rmax0 = fmaxf(rmax0, __shfl_xor_sync(0xffffffffu, rmax0, 1));
        rmax0 = fmaxf(rmax0, __shfl_xor_sync(0xffffffffu, rmax0, 2));
        rmax1 = fmaxf(rmax1, __shfl_xor_sync(0xffffffffu, rmax1, 1));
        rmax1 = fmaxf(rmax1, __shfl_xor_sync(0xffffffffu, rmax1, 2));

        const float mn0 = fmaxf(m0, rmax0);
        const float mn1 = fmaxf(m1, rmax1);
        const float al0 = __expf(m0 - mn0);
        const float al1 = __expf(m1 - mn1);
        m0 = mn0; m1 = mn1;

        float rs0 = 0.f, rs1 = 0.f;
        {
            float* ps0 = PSs + (size_t)(w * 16 + g) * PS_STRIDE + 2 * tig;
            float* ps1 = ps0 + 8 * PS_STRIDE;
            #pragma unroll
            for (int nt = 0; nt < 16; nt++) {
                const float p0 = to_tf32(__expf(s[nt][0] - mn0));
                const float p1 = to_tf32(__expf(s[nt][1] - mn0));
                const float p2 = to_tf32(__expf(s[nt][2] - mn1));
                const float p3 = to_tf32(__expf(s[nt][3] - mn1));
                rs0 += p0 + p1; rs1 += p2 + p3;
                *(float2*)(ps0 + nt * 8) = make_float2(p0, p1);
                *(float2*)(ps1 + nt * 8) = make_float2(p2, p3);
            }
        }
        rs0 += __shfl_xor_sync(0xffffffffu, rs0, 1);
        rs0 += __shfl_xor_sync(0xffffffffu, rs0, 2);
        rs1 += __shfl_xor_sync(0xffffffffu, rs1, 1);
        rs1 += __shfl_xor_sync(0xffffffffu, rs1, 2);
        l0 = l0 * al0 + rs0;
        l1 = l1 * al1 + rs1;

        #pragma unroll
        for (int nt = 0; nt < 8; nt++) {
            o[nt][0] *= al0; o[nt][1] *= al0;
            o[nt][2] *= al1; o[nt][3] *= al1;
        }
        __syncwarp();

        {
            const uint32_t* pp = (const uint32_t*)PSs;
            const uint32_t* vp = (const uint32_t*)(VSs + (t & 1) * VS_FLOATS);
            #pragma unroll
            for (int k16 = 0; k16 < 16; k16++) {
                uint32_t a[4];
                a[0] = pp[(w * 16 + g) * PS_STRIDE + k16 * 8 + tig];
                a[1] = pp[(w * 16 + g + 8) * PS_STRIDE + k16 * 8 + tig];
                a[2] = pp[(w * 16 + g) * PS_STRIDE + k16 * 8 + tig + 4];
                a[3] = pp[(w * 16 + g + 8) * PS_STRIDE + k16 * 8 + tig + 4];
                #pragma unroll
                for (int nt = 0; nt < 8; nt++) {
                    uint32_t bfr[2];
                    bfr[0] = vp[(k16 * 8 + tig) * VS_STRIDE + nt * 8 + g];
                    bfr[1] = vp[(k16 * 8 + tig + 4) * VS_STRIDE + nt * 8 + g];
                    mma_tf32_16x8x8(o[nt], a, bfr);
                }
            }
        }
        __syncwarp();
    }

    {
        const float i0 = 1.0f / l0, i1 = 1.0f / l1;
        const int r0 = qt * 128 + w * 16 + g;
        float* ob0 = out + ((size_t)(b * SEQ + r0)) * DM + h * DK + 2 * tig;
        float* ob1 = ob0 + 8 * DM;
        #pragma unroll
        for (int nt = 0; nt < 8; nt++) {
            *(float2*)(ob0 + nt * 8) = make_float2(to_tf32(o[nt][0] * i0), to_tf32(o[nt][1] * i0));
            *(float2*)(ob1 + nt * 8) = make_float2(to_tf32(o[nt][2] * i1), to_tf32(o[nt][3] * i1));
        }
    }
}

// ---------------- host launcher ----------------
extern "C" void kernel_launch(void* const* d_in, const int* in_sizes, int n_in,
                              void* d_out, int out_size)
{
    (void)in_sizes; (void)n_in; (void)out_size;
    const float* x     = (const float*)d_in[0];
    const float* Wq    = (const float*)d_in[1];
    const float* bq    = (const float*)d_in[2];
    const float* Wk    = (const float*)d_in[3];
    const float* bk    = (const float*)d_in[4];
    const float* Wv    = (const float*)d_in[5];
    const float* bv    = (const float*)d_in[6];
    const float* Wo    = (const float*)d_in[7];
    const float* bo    = (const float*)d_in[8];
    const float* ln1_g = (const float*)d_in[9];
    const float* ln1_b = (const float*)d_in[10];
    const float* W1    = (const float*)d_in[11];
    const float* b1    = (const float*)d_in[12];
    const float* W2    = (const float*)d_in[13];
    const float* b2    = (const float*)d_in[14];
    const float* ln2_g = (const float*)d_in[15];
    const float* ln2_b = (const float*)d_in[16];
    float* out = (float*)d_out;

    float *h, *qkv, *kt, *ctx, *x1, *h2, *ff;
    float *wqkv, *bqkv, *wo, *w1, *w2;
    cudaGetSymbolAddress((void**)&h,    g_h);
    cudaGetSymbolAddress((void**)&qkv,  g_qkv);
    cudaGetSymbolAddress((void**)&kt,   g_kt);
    cudaGetSymbolAddress((void**)&ctx,  g_ctx);
    cudaGetSymbolAddress((void**)&x1,   g_x1);
    cudaGetSymbolAddress((void**)&h2,   g_h2);
    cudaGetSymbolAddress((void**)&ff,   g_ff);
    cudaGetSymbolAddress((void**)&wqkv, g_wqkv);
    cudaGetSymbolAddress((void**)&bqkv, g_bqkv);
    cudaGetSymbolAddress((void**)&wo,   g_wo);
    cudaGetSymbolAddress((void**)&w1,   g_w1);
    cudaGetSymbolAddress((void**)&w2,   g_w2);

    cudaFuncSetAttribute(attn_tc_kernel, cudaFuncAttributeMaxDynamicSharedMemorySize, ATTN_TC_SMEM);
    cudaFuncSetAttribute(gemm_tc<0,1>, cudaFuncAttributeMaxDynamicSharedMemorySize, GEMM_SMEM_BYTES);
    cudaFuncSetAttribute(gemm_tc<1,0>, cudaFuncAttributeMaxDynamicSharedMemorySize, GEMM_SMEM_BYTES);
    cudaFuncSetAttribute(gemm_tc<2,0>, cudaFuncAttributeMaxDynamicSharedMemorySize, GEMM_SMEM_BYTES);

    const dim3 gQKV(QLD / BN, TOK / BM);    // (24, 64)
    const dim3 gProj(DM / BN, TOK / BM);    // (8, 64)
    const dim3 gFF1(DFF / BN, TOK / BM);    // (32, 64)

    // launch 0: fused weight prep (round + pack, single launch)
    prep_weights_kernel<<<(PREP_TOTAL + 255) / 256, 256>>>(
        Wq, Wk, Wv, bq, bk, bv, Wo, W1, W2, wqkv, bqkv, wo, w1, w2);
    // launch 1: h = LN1(x) (rounded to tf32)
    ln_kernel<1><<<TOK, 256>>>(x, ln1_g, ln1_b, h);
    // launch 2: fused qkv projection (outputs rounded)
    gemm_tc<0,1><<<gQKV, 256, GEMM_SMEM_BYTES>>>(h, wqkv, bqkv, nullptr, qkv, TOK, QLD, DM);
    // launch 3: transpose K
    transpose_k_kernel<<<dim3(SEQ / 32, DK / 32, NH * BATCH), dim3(32, 8)>>>(qkv, kt);
    // launch 4: tensor-core flash attention
    attn_tc_kernel<<<dim3(SEQ / 128, NH, BATCH), 256, ATTN_TC_SMEM>>>(qkv, kt, qkv + 2 * DM, ctx);
    // launch 5 (ncu capture target): x1 = x + ctx @ Wo + bo
    gemm_tc<1,0><<<gProj, 256, GEMM_SMEM_BYTES>>>(ctx, wo, bo, x, x1, TOK, DM, DM);
    // launch 6: h2 = LN2(x1) (rounded)
    ln_kernel<1><<<TOK, 256>>>(x1, ln2_g, ln2_b, h2);
    // launch 7: ff = gelu(h2 @ W1 + b1)
    gemm_tc<2,0><<<gFF1, 256, GEMM_SMEM_BYTES>>>(h2, w1, b1, nullptr, ff, TOK, DFF, DM);
    // launch 8: out = x1 + ff @ W2 + b2
    gemm_tc<1,0><<<gProj, 256, GEMM_SMEM_BYTES>>>(ff, w2, b2, x1, out, TOK, DM, DFF);
}

// round 7
// speedup vs baseline: 6.6102x; 1.8608x over previous
#include <cuda_runtime.h>
#include <cuda_fp16.h>
#include <math.h>
#include <stdint.h>

#define TOK   8192
#define DM    1024
#define DFF   4096
#define NH    16
#define DK    64
#define SEQ   2048
#define BATCH 4
#define QLD   (3 * DM)

// ---------------- scratch ----------------
__device__ __half g_h   [TOK * DM];
__device__ __half g_qkv [TOK * QLD];
__device__ __half g_vt  [DM * TOK];            // [(h*DK+dk)][b*SEQ+s]
__device__ __half g_ctx [TOK * DM];
__device__ float  g_x1  [TOK * DM];
__device__ __half g_h2  [TOK * DM];
__device__ __half g_ff  [TOK * DFF];
// fp16 weights, transposed to [N][K]
__device__ __half g_wqkvT[QLD * DM];
__device__ float  g_bqkv [QLD];
__device__ __half g_woT  [DM * DM];
__device__ __half g_w1T  [DFF * DM];
__device__ __half g_w2T  [DM * DFF];

// ---------------- helpers ----------------
__device__ __forceinline__ uint32_t smem_u32(const void* p) {
    uint32_t a;
    asm("{ .reg .u64 t; cvta.to.shared.u64 t, %1; cvt.u32.u64 %0, t; }" : "=r"(a) : "l"(p));
    return a;
}
__device__ __forceinline__ void cp_async16(uint32_t dst, const void* src) {
    asm volatile("cp.async.cg.shared.global [%0], [%1], 16;" :: "r"(dst), "l"(src));
}
__device__ __forceinline__ void cp_commit() {
    asm volatile("cp.async.commit_group;" ::: "memory");
}
__device__ __forceinline__ void mma_f16_16x8x16(float* d, const uint32_t* a, const uint32_t* b) {
    asm volatile(
        "mma.sync.aligned.m16n8k16.row.col.f32.f16.f16.f32 "
        "{%0,%1,%2,%3}, {%4,%5,%6,%7}, {%8,%9}, {%0,%1,%2,%3};"
        : "+f"(d[0]), "+f"(d[1]), "+f"(d[2]), "+f"(d[3])
        : "r"(a[0]), "r"(a[1]), "r"(a[2]), "r"(a[3]), "r"(b[0]), "r"(b[1]));
}
__device__ __forceinline__ uint32_t pack_h2(float x, float y) {
    __half2 h = __floats2half2_rn(x, y);
    return *(uint32_t*)&h;
}

// ---------------- transpose + fp32->fp16 convert: in [R][C] -> out [C][R] ----------------
__global__ void __launch_bounds__(256) tcvt_kernel(const float* __restrict__ in,
                                                   __half* __restrict__ out, int R, int C)
{
    __shared__ float tile[32][33];
    const int c0 = blockIdx.x * 32, r0 = blockIdx.y * 32;
    const int tx = threadIdx.x, ty = threadIdx.y;
    #pragma unroll
    for (int i = ty; i < 32; i += 8)
        tile[i][tx] = in[(size_t)(r0 + i) * C + c0 + tx];
    __syncthreads();
    #pragma unroll
    for (int i = ty; i < 32; i += 8)
        out[(size_t)(c0 + i) * R + r0 + tx] = __float2half_rn(tile[tx][i]);
}

// ---------------- V transpose (fp16): qkv v-block [s][dk] -> vt [dk][s] ----------------
__global__ void __launch_bounds__(256) vtrans_kernel(const __half* __restrict__ in,
                                                     __half* __restrict__ out)
{
    __shared__ __half tile[32][33];
    const int s0 = blockIdx.x * 32;
    const int d0 = blockIdx.y * 32;
    const int h  = blockIdx.z & (NH - 1);
    const int b  = blockIdx.z >> 4;
    const int tx = threadIdx.x, ty = threadIdx.y;

    const __half* ip = in + ((size_t)(b * SEQ + s0)) * QLD + 2 * DM + h * DK + d0;
    #pragma unroll
    for (int i = ty; i < 32; i += 8)
        tile[i][tx] = ip[(size_t)i * QLD + tx];
    __syncthreads();
    __half* op = out + ((size_t)(h * DK + d0)) * (BATCH * SEQ) + (size_t)b * SEQ + s0;
    #pragma unroll
    for (int i = ty; i < 32; i += 8)
        op[(size_t)i * (BATCH * SEQ) + tx] = tile[tx][i];
}

// ---------------- bias pack (fp32 copy) ----------------
__global__ void __launch_bounds__(256) pack_bias3_kernel(const float* __restrict__ b0,
                                                         const float* __restrict__ b1,
                                                         const float* __restrict__ b2,
                                                         float* __restrict__ out)
{
    const int i = blockIdx.x * blockDim.x + threadIdx.x;
    const int which = i >> 8, c4 = i & 255;
    const float* src = which == 0 ? b0 : (which == 1 ? b1 : b2);
    ((float4*)out)[which * 256 + c4] = ((const float4*)src)[c4];
}

// ---------------- LayerNorm: fp32 in, fp16 out ----------------
__global__ void __launch_bounds__(256) ln_kernel(const float* __restrict__ x,
                                                 const float* __restrict__ g,
                                                 const float* __restrict__ b,
                                                 __half* __restrict__ out)
{
    const int row = blockIdx.x;
    const int tid = threadIdx.x;
    const float4 v = ((const float4*)(x + (size_t)row * DM))[tid];

    float s  = v.x + v.y + v.z + v.w;
    float ss = v.x * v.x + v.y * v.y + v.z * v.z + v.w * v.w;
    #pragma unroll
    for (int o = 16; o; o >>= 1) {
        s  += __shfl_xor_sync(0xffffffffu, s,  o);
        ss += __shfl_xor_sync(0xffffffffu, ss, o);
    }
    __shared__ float sb[8], sb2[8];
    if ((tid & 31) == 0) { sb[tid >> 5] = s; sb2[tid >> 5] = ss; }
    __syncthreads();
    float ts = 0.f, ts2 = 0.f;
    #pragma unroll
    for (int i = 0; i < 8; i++) { ts += sb[i]; ts2 += sb2[i]; }

    const float mu  = ts * (1.0f / DM);
    const float var = ts2 * (1.0f / DM) - mu * mu;
    const float inv = rsqrtf(var + 1e-5f);

    const float4 gg = ((const float4*)g)[tid];
    const float4 bb = ((const float4*)b)[tid];
    uint32_t p0 = pack_h2((v.x - mu) * inv * gg.x + bb.x, (v.y - mu) * inv * gg.y + bb.y);
    uint32_t p1 = pack_h2((v.z - mu) * inv * gg.z + bb.z, (v.w - mu) * inv * gg.w + bb.w);
    uint2 o; o.x = p0; o.y = p1;
    ((uint2*)(out + (size_t)row * DM))[tid] = o;
}

// ---------------- fp16 mma.sync GEMM: 128x128 tile, BK=64 halves, 3-stage, 2 CTAs/SM ----------------
// A: fp16 [M][K] row-major.  BT: fp16 [N][K] (k-contiguous = B col-major).
// EPI: 0 = bias; 1 = bias + residual(fp32); 2 = gelu(bias)
// OUTH: 1 -> fp16 out, 0 -> fp32 out
__device__ __forceinline__ float gelu_exact(float v) {
    return 0.5f * v * (1.0f + erff(v * 0.70710678118654752440f));
}

#define BM 128
#define BN 128
#define BKH 64                         // halves per k-tile
#define STAGES 3
#define TSH 72                         // halves per smem row (36 words; 36 mod 32 = 4 -> conflict-free)
#define TILE_HALVES (128 * TSH)        // 9216 halves = 18432 B per operand tile
#define STAGE_BYTES (2 * TILE_HALVES * 2)            // 36864
#define GEMM_SMEM_BYTES (STAGES * STAGE_BYTES)       // 110592; x2 CTA = 221184 <= 227KB

template <int EPI, int OUTH>
__global__ void __launch_bounds__(256, 2) gemm_f16(
    const __half* __restrict__ A, const __half* __restrict__ BT,
    const float* __restrict__ bias, const float* __restrict__ res,
    void* __restrict__ Cv, int M, int N, int K)
{
    extern __shared__ __half smh[];
    const uint32_t sbase = smem_u32(smh);

    const int tid = threadIdx.x;
    const int wid = tid >> 5;
    const int lane = tid & 31;
    const int g = lane >> 2;        // 0..7
    const int tig = lane & 3;       // 0..3
    const int wm = wid & 1;
    const int wn = wid >> 1;

    const int n0 = blockIdx.x * BN;
    const int m0 = blockIdx.y * BM;
    const int NT = K / BKH;

    float acc[4][4][4];
    #pragma unroll
    for (int mt = 0; mt < 4; mt++)
        #pragma unroll
        for (int nt = 0; nt < 4; nt++)
            #pragma unroll
            for (int e = 0; e < 4; e++) acc[mt][nt][e] = 0.f;

    auto load_stage = [&](int st, int t) {
        const uint32_t aoff = sbase + (uint32_t)st * STAGE_BYTES;
        const uint32_t boff = aoff + TILE_HALVES * 2;
        #pragma unroll
        for (int i = 0; i < 4; i++) {
            const int idx = i * 256 + tid;          // 0..1023
            const int row = idx >> 3, ch = idx & 7; // 128 rows x 8 chunks(16B)
            cp_async16(aoff + (uint32_t)(row * TSH + ch * 8) * 2u,
                       A + (size_t)(m0 + row) * K + (size_t)t * BKH + ch * 8);
            cp_async16(boff + (uint32_t)(row * TSH + ch * 8) * 2u,
                       BT + (size_t)(n0 + row) * K + (size_t)t * BKH + ch * 8);
        }
    };

    #pragma unroll
    for (int t = 0; t < STAGES - 1; t++) {
        load_stage(t, t);
        cp_commit();
    }

    for (int t = 0; t < NT; t++) {
        asm volatile("cp.async.wait_group %0;" :: "n"(STAGES - 2) : "memory");
        __syncthreads();

        const int pf = t + STAGES - 1;
        if (pf < NT) load_stage(pf % STAGES, pf);
        cp_commit();

        const int st = t % STAGES;
        const uint32_t* pA = (const uint32_t*)(smh + (size_t)st * STAGE_BYTES / 2) + (wm * 64) * 36;
        const uint32_t* pB = (const uint32_t*)(smh + (size_t)st * STAGE_BYTES / 2 + TILE_HALVES) + (wn * 32) * 36;

        #pragma unroll
        for (int ks = 0; ks < 4; ks++) {          // 4 x k16
            const int k8 = ks * 8;                // word offset
            uint32_t afr[4][4], bfr[4][2];
            #pragma unroll
            for (int mt = 0; mt < 4; mt++) {
                const uint32_t* p = pA + (mt * 16 + g) * 36 + k8 + tig;
                afr[mt][0] = p[0];
                afr[mt][1] = p[8 * 36];
                afr[mt][2] = p[4];
                afr[mt][3] = p[8 * 36 + 4];
            }
            #pragma unroll
            for (int nt = 0; nt < 4; nt++) {
                const uint32_t* p = pB + (nt * 8 + g) * 36 + k8 + tig;
                bfr[nt][0] = p[0];
                bfr[nt][1] = p[4];
            }
            #pragma unroll
            for (int mt = 0; mt < 4; mt++)
                #pragma unroll
                for (int nt = 0; nt < 4; nt++)
                    mma_f16_16x8x16(acc[mt][nt], afr[mt], bfr[nt]);
        }
    }

    // ---- epilogue ----
    #pragma unroll
    for (int mt = 0; mt < 4; mt++) {
        const int r0 = m0 + wm * 64 + mt * 16 + g;
        const float* rr0 = (EPI == 1) ? (res + (size_t)r0 * N) : nullptr;
        const float* rr1 = (EPI == 1) ? (res + (size_t)(r0 + 8) * N) : nullptr;
        #pragma unroll
        for (int nt = 0; nt < 4; nt++) {
            const int col = n0 + wn * 32 + nt * 8 + 2 * tig;
            const float bx = bias[col], by = bias[col + 1];
            float v0 = acc[mt][nt][0] + bx, v1 = acc[mt][nt][1] + by;
            float v2 = acc[mt][nt][2] + bx, v3 = acc[mt][nt][3] + by;
            if (EPI == 2) {
                v0 = gelu_exact(v0); v1 = gelu_exact(v1);
                v2 = gelu_exact(v2); v3 = gelu_exact(v3);
            }
            if (EPI == 1) {
                v0 += rr0[col]; v1 += rr0[col + 1];
                v2 += rr1[col]; v3 += rr1[col + 1];
            }
            if (OUTH) {
                __half* C = (__half*)Cv;
                *(uint32_t*)(C + (size_t)r0 * N + col)       = pack_h2(v0, v1);
                *(uint32_t*)(C + (size_t)(r0 + 8) * N + col) = pack_h2(v2, v3);
            } else {
                float* C = (float*)Cv;
                *(float2*)(C + (size_t)r0 * N + col)       = make_float2(v0, v1);
                *(float2*)(C + (size_t)(r0 + 8) * N + col) = make_float2(v2, v3);
            }
        }
    }
}

// ---------------- fp16 tensor-core flash attention ----------------
// CTA: (qt, h, b); 128 Q rows, 8 warps x 16 rows; KV tiles of 128, double-buffered.
// K consumed in natural [s][dk] layout (B col-major, k=dk contiguous). V via vt [dk][s].
#define KSH 72                                   // halves per K smem row (s-major), 36 words
#define VSH 136                                  // halves per VT smem row (dk-major), 68 words
#define PSH 136                                  // halves per P smem row, 68 words
#define K_TILE_HALVES (128 * KSH)                // 9216
#define V_TILE_HALVES (64 * VSH)                 // 8704
#define P_HALVES (128 * PSH)                     // 17408
#define ATTN_SMEM ((2 * K_TILE_HALVES + 2 * V_TILE_HALVES + P_HALVES) * 2)   // 106496 B

__global__ void __launch_bounds__(256) attn_f16_kernel(const __half* __restrict__ qkv,
                                                       const __half* __restrict__ vt,
                                                       __half* __restrict__ out)
{
    extern __shared__ __half smh[];
    __half* Ks  = smh;                                  // 2 x [128][72]
    __half* Vts = Ks + 2 * K_TILE_HALVES;               // 2 x [64][136]
    __half* Ps  = Vts + 2 * V_TILE_HALVES;              // [128][136]
    const uint32_t sbase = smem_u32(smh);

    const int tid = threadIdx.x;
    const int w = tid >> 5;
    const int lane = tid & 31;
    const int g = lane >> 2;
    const int tig = lane & 3;

    const int qt = blockIdx.x, h = blockIdx.y, b = blockIdx.z;

    // ---- Q fragments (scaled by 1/8, exact in fp16) ----
    uint32_t qa[4][4];
    {
        const __half* qb = qkv + ((size_t)(b * SEQ + qt * 128 + w * 16)) * QLD + h * DK;
        const __half2 sc = __floats2half2_rn(0.125f, 0.125f);
        #pragma unroll
        for (int ks = 0; ks < 4; ks++) {
            const int c = ks * 16 + 2 * tig;
            __half2 a0 = __hmul2(*(const __half2*)(qb + (size_t)g * QLD + c), sc);
            __half2 a1 = __hmul2(*(const __half2*)(qb + (size_t)(g + 8) * QLD + c), sc);
            __half2 a2 = __hmul2(*(const __half2*)(qb + (size_t)g * QLD + c + 8), sc);
            __half2 a3 = __hmul2(*(const __half2*)(qb + (size_t)(g + 8) * QLD + c + 8), sc);
            qa[ks][0] = *(uint32_t*)&a0; qa[ks][1] = *(uint32_t*)&a1;
            qa[ks][2] = *(uint32_t*)&a2; qa[ks][3] = *(uint32_t*)&a3;
        }
    }

    float o[8][4];
    #pragma unroll
    for (int nt = 0; nt < 8; nt++)
        #pragma unroll
        for (int e = 0; e < 4; e++) o[nt][e] = 0.f;
    float m0 = -1e30f, m1 = -1e30f, l0 = 0.f, l1 = 0.f;

    auto load_kv = [&](int t, int buf) {
        const uint32_t kdst = sbase + (uint32_t)(buf * K_TILE_HALVES) * 2u;
        const uint32_t vdst = sbase + (uint32_t)(2 * K_TILE_HALVES + buf * V_TILE_HALVES) * 2u;
        const __half* ksrc = qkv + ((size_t)(b * SEQ + t * 128)) * QLD + DM + h * DK;
        const __half* vsrc = vt + (size_t)(h * DK) * (BATCH * SEQ) + (size_t)b * SEQ + (size_t)t * 128;
        #pragma unroll
        for (int i = 0; i < 4; i++) {
            const int idx = i * 256 + tid;
            const int kr = idx >> 3, kc = idx & 7;      // K: 128 rows x 8 chunks
            cp_async16(kdst + (uint32_t)(kr * KSH + kc * 8) * 2u,
                       ksrc + (size_t)kr * QLD + kc * 8);
            const int vr = idx >> 4, vc = idx & 15;     // VT: 64 rows x 16 chunks
            cp_async16(vdst + (uint32_t)(vr * VSH + vc * 8) * 2u,
                       vsrc + (size_t)vr * (BATCH * SEQ) + vc * 8);
        }
    };

    load_kv(0, 0);
    cp_commit();

    const int NKV = SEQ / 128;
    for (int t = 0; t < NKV; t++) {
        asm volatile("cp.async.wait_group 0;" ::: "memory");
        __syncthreads();
        if (t + 1 < NKV) { load_kv(t + 1, (t + 1) & 1); cp_commit(); }

        // ---- S = Q @ K^T ----
        float s[16][4];
        #pragma unroll
        for (int nt = 0; nt < 16; nt++)
            #pragma unroll
            for (int e = 0; e < 4; e++) s[nt][e] = 0.f;
        {
            const uint32_t* kp = (const uint32_t*)(Ks + (t & 1) * K_TILE_HALVES);
            #pragma unroll
            for (int ks = 0; ks < 4; ks++) {
                const int k8 = ks * 8;
                #pragma unroll
                for (int nt = 0; nt < 16; nt++) {
                    uint32_t bfr[2];
                    const uint32_t* p = kp + (nt * 8 + g) * 36 + k8 + tig;
                    bfr[0] = p[0];
                    bfr[1] = p[4];
                    mma_f16_16x8x16(s[nt], qa[ks], bfr);
                }
            }
        }

        // ---- online softmax ----
        float rmax0 = -1e30f, rmax1 = -1e30f;
        #pragma unroll
        for (int nt = 0; nt < 16; nt++) {
            rmax0 = fmaxf(rmax0, fmaxf(s[nt][0], s[nt][1]));
            rmax1 = fmaxf(rmax1, fmaxf(s[nt][2], s[nt][3]));
        }
        rmax0 = fmaxf(rmax0, __shfl_xor_sync(0xffffffffu, rmax0, 1));
        rmax0 = fmaxf(rmax0, __shfl_xor_sync(0xffffffffu, rmax0, 2));
        rmax1 = fmaxf(rmax1, __shfl_xor_sync(0xffffffffu, rmax1, 1));
        rmax1 = fmaxf(rmax1, __shfl_xor_sync(0xffffffffu, rmax1, 2));

        const float mn0 = fmaxf(m0, rmax0);
        const float mn1 = fmaxf(m1, rmax1);
        const float al0 = __expf(m0 - mn0);
        const float al1 = __expf(m1 - mn1);
        m0 = mn0; m1 = mn1;

        float rs0 = 0.f, rs1 = 0.f;
        {
            uint32_t* ps0 = (uint32_t*)Ps + (size_t)(w * 16 + g) * 68 + tig;
            uint32_t* ps1 = ps0 + 8 * 68;
            #pragma unroll
            for (int nt = 0; nt < 16; nt++) {
                const __half2 h0 = __floats2half2_rn(__expf(s[nt][0] - mn0), __expf(s[nt][1] - mn0));
                const __half2 h1 = __floats2half2_rn(__expf(s[nt][2] - mn1), __expf(s[nt][3] - mn1));
                const float2 f0 = __half22float2(h0);
                const float2 f1 = __half22float2(h1);
                rs0 += f0.x + f0.y; rs1 += f1.x + f1.y;
                ps0[nt * 4] = *(const uint32_t*)&h0;
                ps1[nt * 4] = *(const uint32_t*)&h1;
            }
        }
        rs0 += __shfl_xor_sync(0xffffffffu, rs0, 1);
        rs0 += __shfl_xor_sync(0xffffffffu, rs0, 2);
        rs1 += __shfl_xor_sync(0xffffffffu, rs1, 1);
        rs1 += __shfl_xor_sync(0xffffffffu, rs1, 2);
        l0 = l0 * al0 + rs0;
        l1 = l1 * al1 + rs1;

        #pragma unroll
        for (int nt = 0; nt < 8; nt++) {
            o[nt][0] *= al0; o[nt][1] *= al0;
            o[nt][2] *= al1; o[nt][3] *= al1;
        }
        __syncwarp();

        // ---- O += P @ V ----
        {
            const uint32_t* pp = (const uint32_t*)Ps + (size_t)(w * 16) * 68;
            const uint32_t* vp = (const uint32_t*)(Vts + (t & 1) * V_TILE_HALVES);
            #pragma unroll
            for (int ks = 0; ks < 8; ks++) {          // 8 x k16 over 128 s
                const int k8 = ks * 8;
                uint32_t a[4];
                a[0] = pp[(g) * 68 + k8 + tig];
                a[1] = pp[(g + 8) * 68 + k8 + tig];
                a[2] = pp[(g) * 68 + k8 + tig + 4];
                a[3] = pp[(g + 8) * 68 + k8 + tig + 4];
                #pragma unroll
                for (int nt = 0; nt < 8; nt++) {
                    uint32_t bfr[2];
                    const uint32_t* p = vp + (nt * 8 + g) * 68 + k8 + tig;
                    bfr[0] = p[0];
                    bfr[1] = p[4];
                    mma_f16_16x8x16(o[nt], a, bfr);
                }
            }
        }
        __syncwarp();
    }

    // ---- epilogue: normalize, fp16 out ----
    {
        const float i0 = 1.0f / l0, i1 = 1.0f / l1;
        const int r0 = qt * 128 + w * 16 + g;
        __half* ob0 = out + ((size_t)(b * SEQ + r0)) * DM + h * DK + 2 * tig;
        __half* ob1 = ob0 + 8 * DM;
        #pragma unroll
        for (int nt = 0; nt < 8; nt++) {
            *(uint32_t*)(ob0 + nt * 8) = pack_h2(o[nt][0] * i0, o[nt][1] * i0);
            *(uint32_t*)(ob1 + nt * 8) = pack_h2(o[nt][2] * i1, o[nt][3] * i1);
        }
    }
}

// ---------------- host launcher ----------------
extern "C" void kernel_launch(void* const* d_in, const int* in_sizes, int n_in,
                              void* d_out, int out_size)
{
    (void)in_sizes; (void)n_in; (void)out_size;
    const float* x     = (const float*)d_in[0];
    const float* Wq    = (const float*)d_in[1];
    const float* bq    = (const float*)d_in[2];
    const float* Wk    = (const float*)d_in[3];
    const float* bk    = (const float*)d_in[4];
    const float* Wv    = (const float*)d_in[5];
    const float* bv    = (const float*)d_in[6];
    const float* Wo    = (const float*)d_in[7];
    const float* bo    = (const float*)d_in[8];
    const float* ln1_g = (const float*)d_in[9];
    const float* ln1_b = (const float*)d_in[10];
    const float* W1    = (const float*)d_in[11];
    const float* b1    = (const float*)d_in[12];
    const float* W2    = (const float*)d_in[13];
    const float* b2    = (const float*)d_in[14];
    const float* ln2_g = (const float*)d_in[15];
    const float* ln2_b = (const float*)d_in[16];
    float* out = (float*)d_out;

    __half *h, *qkv, *vt, *ctx, *h2, *ff, *wqkvT, *woT, *w1T, *w2T;
    float *x1, *bqkv;
    cudaGetSymbolAddress((void**)&h,     g_h);
    cudaGetSymbolAddress((void**)&qkv,   g_qkv);
    cudaGetSymbolAddress((void**)&vt,    g_vt);
    cudaGetSymbolAddress((void**)&ctx,   g_ctx);
    cudaGetSymbolAddress((void**)&x1,    g_x1);
    cudaGetSymbolAddress((void**)&h2,    g_h2);
    cudaGetSymbolAddress((void**)&ff,    g_ff);
    cudaGetSymbolAddress((void**)&wqkvT, g_wqkvT);
    cudaGetSymbolAddress((void**)&bqkv,  g_bqkv);
    cudaGetSymbolAddress((void**)&woT,   g_woT);
    cudaGetSymbolAddress((void**)&w1T,   g_w1T);
    cudaGetSymbolAddress((void**)&w2T,   g_w2T);

    cudaFuncSetAttribute(attn_f16_kernel, cudaFuncAttributeMaxDynamicSharedMemorySize, ATTN_SMEM);
    cudaFuncSetAttribute(gemm_f16<0,1>, cudaFuncAttributeMaxDynamicSharedMemorySize, GEMM_SMEM_BYTES);
    cudaFuncSetAttribute(gemm_f16<1,0>, cudaFuncAttributeMaxDynamicSharedMemorySize, GEMM_SMEM_BYTES);
    cudaFuncSetAttribute(gemm_f16<2,1>, cudaFuncAttributeMaxDynamicSharedMemorySize, GEMM_SMEM_BYTES);

    const dim3 tB(32, 8);
    // weight transpose + fp16 convert
    tcvt_kernel<<<dim3(DM / 32, DM / 32), tB>>>(Wq, wqkvT, DM, DM);
    tcvt_kernel<<<dim3(DM / 32, DM / 32), tB>>>(Wk, wqkvT + (size_t)DM * DM, DM, DM);
    tcvt_kernel<<<dim3(DM / 32, DM / 32), tB>>>(Wv, wqkvT + (size_t)2 * DM * DM, DM, DM);
    tcvt_kernel<<<dim3(DM / 32, DM / 32), tB>>>(Wo, woT, DM, DM);
    tcvt_kernel<<<dim3(DFF / 32, DM / 32), tB>>>(W1, w1T, DM, DFF);
    tcvt_kernel<<<dim3(DM / 32, DFF / 32), tB>>>(W2, w2T, DFF, DM);
    pack_bias3_kernel<<<3, 256>>>(bq, bk, bv, bqkv);

    const dim3 gQKV(QLD / BN, TOK / BM);    // (24, 64)
    const dim3 gProj(DM / BN, TOK / BM);    // (8, 64)
    const dim3 gFF1(DFF / BN, TOK / BM);    // (32, 64)

    // LN1 -> fp16
    ln_kernel<<<TOK, 256>>>(x, ln1_g, ln1_b, h);
    // fused qkv projection (fp16 out)
    gemm_f16<0,1><<<gQKV, 256, GEMM_SMEM_BYTES>>>(h, wqkvT, bqkv, nullptr, qkv, TOK, QLD, DM);
    // V transpose (fp16)
    vtrans_kernel<<<dim3(SEQ / 32, DK / 32, NH * BATCH), tB>>>(qkv, vt);
    // fp16 flash attention (fp16 ctx out)
    attn_f16_kernel<<<dim3(SEQ / 128, NH, BATCH), 256, ATTN_SMEM>>>(qkv, vt, ctx);
    // x1 = x + ctx @ Wo + bo  (fp32 out)
    gemm_f16<1,0><<<gProj, 256, GEMM_SMEM_BYTES>>>(ctx, woT, bo, x, x1, TOK, DM, DM);
    // LN2 -> fp16
    ln_kernel<<<TOK, 256>>>(x1, ln2_g, ln2_b, h2);
    // ff = gelu(h2 @ W1 + b1)  (fp16 out)
    gemm_f16<2,1><<<gFF1, 256, GEMM_SMEM_BYTES>>>(h2, w1T, b1, nullptr, ff, TOK, DFF, DM);
    // out = x1 + ff @ W2 + b2  (fp32 out)
    gemm_f16<1,0><<<gProj, 256, GEMM_SMEM_BYTES>>>(ff, w2T, b2, x1, out, TOK, DM, DFF);
}

// round 8
// speedup vs baseline: 6.9013x; 1.0440x over previous
#include <cuda_runtime.h>
#include <cuda_fp16.h>
#include <math.h>
#include <stdint.h>

#define TOK   8192
#define DM    1024
#define DFF   4096
#define NH    16
#define DK    64
#define SEQ   2048
#define BATCH 4
#define QLD   (3 * DM)

// ---------------- scratch ----------------
__device__ __half g_h   [TOK * DM];
__device__ __half g_qkv [TOK * QLD];
__device__ __half g_vt  [DM * TOK];            // [(h*DK+dk)][b*SEQ+s]
__device__ __half g_ctx [TOK * DM];
__device__ float  g_x1  [TOK * DM];
__device__ __half g_h2  [TOK * DM];
__device__ __half g_ff  [TOK * DFF];
// fp16 weights, transposed to [N][K]
__device__ __half g_wqkvT[QLD * DM];
__device__ float  g_bqkv [QLD];
__device__ __half g_woT  [DM * DM];
__device__ __half g_w1T  [DFF * DM];
__device__ __half g_w2T  [DM * DFF];

// ---------------- helpers ----------------
__device__ __forceinline__ uint32_t smem_u32(const void* p) {
    uint32_t a;
    asm("{ .reg .u64 t; cvta.to.shared.u64 t, %1; cvt.u32.u64 %0, t; }" : "=r"(a) : "l"(p));
    return a;
}
__device__ __forceinline__ void cp_async16(uint32_t dst, const void* src) {
    asm volatile("cp.async.cg.shared.global [%0], [%1], 16;" :: "r"(dst), "l"(src));
}
__device__ __forceinline__ void cp_commit() {
    asm volatile("cp.async.commit_group;" ::: "memory");
}
__device__ __forceinline__ void mma_f16_16x8x16(float* d, const uint32_t* a, const uint32_t* b) {
    asm volatile(
        "mma.sync.aligned.m16n8k16.row.col.f32.f16.f16.f32 "
        "{%0,%1,%2,%3}, {%4,%5,%6,%7}, {%8,%9}, {%0,%1,%2,%3};"
        : "+f"(d[0]), "+f"(d[1]), "+f"(d[2]), "+f"(d[3])
        : "r"(a[0]), "r"(a[1]), "r"(a[2]), "r"(a[3]), "r"(b[0]), "r"(b[1]));
}
__device__ __forceinline__ uint32_t pack_h2(float x, float y) {
    __half2 h = __floats2half2_rn(x, y);
    return *(uint32_t*)&h;
}

// ---------------- fused prep: all weight transposes+convert + bias pack, ONE launch ----------------
// blocks [0,4096): Wq/Wk/Wv/Wo (1024 tiles each); [4096,8192): W1; [8192,12288): W2; [12288,12291): bias
__global__ void __launch_bounds__(256) prep_kernel(
    const float* __restrict__ Wq, const float* __restrict__ Wk, const float* __restrict__ Wv,
    const float* __restrict__ bq, const float* __restrict__ bk, const float* __restrict__ bv,
    const float* __restrict__ Wo, const float* __restrict__ W1, const float* __restrict__ W2,
    __half* __restrict__ wqkvT, float* __restrict__ bqkv,
    __half* __restrict__ woT, __half* __restrict__ w1T, __half* __restrict__ w2T)
{
    const int id = blockIdx.x;
    const int tx = threadIdx.x, ty = threadIdx.y;
    if (id >= 12288) {
        const int which = id - 12288;
        const float* src = which == 0 ? bq : (which == 1 ? bk : bv);
        const int t = ty * 32 + tx;
        ((float4*)bqkv)[which * 256 + t] = ((const float4*)src)[t];
        return;
    }
    const float* in; __half* out; int R, C, lid;
    if (id < 4096) {
        const int m = id >> 10; lid = id & 1023;
        in = m == 0 ? Wq : (m == 1 ? Wk : (m == 2 ? Wv : Wo));
        out = (m == 3) ? woT : (wqkvT + (size_t)m * DM * DM);
        R = DM; C = DM;
    } else if (id < 8192) {
        lid = id - 4096; in = W1; out = w1T; R = DM; C = DFF;
    } else {
        lid = id - 8192; in = W2; out = w2T; R = DFF; C = DM;
    }
    const int tilesx = C / 32;
    const int c0 = (lid % tilesx) * 32, r0 = (lid / tilesx) * 32;
    __shared__ float tile[32][33];
    #pragma unroll
    for (int i = ty; i < 32; i += 8)
        tile[i][tx] = in[(size_t)(r0 + i) * C + c0 + tx];
    __syncthreads();
    #pragma unroll
    for (int i = ty; i < 32; i += 8)
        out[(size_t)(c0 + i) * R + r0 + tx] = __float2half_rn(tile[tx][i]);
}

// ---------------- V transpose (fp16): qkv v-block [s][dk] -> vt [dk][s] ----------------
__global__ void __launch_bounds__(256) vtrans_kernel(const __half* __restrict__ in,
                                                     __half* __restrict__ out)
{
    __shared__ __half tile[32][33];
    const int s0 = blockIdx.x * 32;
    const int d0 = blockIdx.y * 32;
    const int h  = blockIdx.z & (NH - 1);
    const int b  = blockIdx.z >> 4;
    const int tx = threadIdx.x, ty = threadIdx.y;

    const __half* ip = in + ((size_t)(b * SEQ + s0)) * QLD + 2 * DM + h * DK + d0;
    #pragma unroll
    for (int i = ty; i < 32; i += 8)
        tile[i][tx] = ip[(size_t)i * QLD + tx];
    __syncthreads();
    __half* op = out + ((size_t)(h * DK + d0)) * (BATCH * SEQ) + (size_t)b * SEQ + s0;
    #pragma unroll
    for (int i = ty; i < 32; i += 8)
        op[(size_t)i * (BATCH * SEQ) + tx] = tile[tx][i];
}

// ---------------- LayerNorm: fp32 in, fp16 out ----------------
__global__ void __launch_bounds__(256) ln_kernel(const float* __restrict__ x,
                                                 const float* __restrict__ g,
                                                 const float* __restrict__ b,
                                                 __half* __restrict__ out)
{
    const int row = blockIdx.x;
    const int tid = threadIdx.x;
    const float4 v = ((const float4*)(x + (size_t)row * DM))[tid];

    float s  = v.x + v.y + v.z + v.w;
    float ss = v.x * v.x + v.y * v.y + v.z * v.z + v.w * v.w;
    #pragma unroll
    for (int o = 16; o; o >>= 1) {
        s  += __shfl_xor_sync(0xffffffffu, s,  o);
        ss += __shfl_xor_sync(0xffffffffu, ss, o);
    }
    __shared__ float sb[8], sb2[8];
    if ((tid & 31) == 0) { sb[tid >> 5] = s; sb2[tid >> 5] = ss; }
    __syncthreads();
    float ts = 0.f, ts2 = 0.f;
    #pragma unroll
    for (int i = 0; i < 8; i++) { ts += sb[i]; ts2 += sb2[i]; }

    const float mu  = ts * (1.0f / DM);
    const float var = ts2 * (1.0f / DM) - mu * mu;
    const float inv = rsqrtf(var + 1e-5f);

    const float4 gg = ((const float4*)g)[tid];
    const float4 bb = ((const float4*)b)[tid];
    uint32_t p0 = pack_h2((v.x - mu) * inv * gg.x + bb.x, (v.y - mu) * inv * gg.y + bb.y);
    uint32_t p1 = pack_h2((v.z - mu) * inv * gg.z + bb.z, (v.w - mu) * inv * gg.w + bb.w);
    uint2 o; o.x = p0; o.y = p1;
    ((uint2*)(out + (size_t)row * DM))[tid] = o;
}

// ---------------- fp16 mma.sync GEMM: 128x128 tile, BK=64 halves, 3-stage, 2 CTAs/SM ----------------
__device__ __forceinline__ float gelu_exact(float v) {
    return 0.5f * v * (1.0f + erff(v * 0.70710678118654752440f));
}

#define BM 128
#define BN 128
#define BKH 64
#define STAGES 3
#define TSH 72
#define TILE_HALVES (128 * TSH)
#define STAGE_BYTES (2 * TILE_HALVES * 2)
#define GEMM_SMEM_BYTES (STAGES * STAGE_BYTES)

template <int EPI, int OUTH>
__global__ void __launch_bounds__(256, 2) gemm_f16(
    const __half* __restrict__ A, const __half* __restrict__ BT,
    const float* __restrict__ bias, const float* __restrict__ res,
    void* __restrict__ Cv, int M, int N, int K)
{
    extern __shared__ __half smh[];
    const uint32_t sbase = smem_u32(smh);

    const int tid = threadIdx.x;
    const int wid = tid >> 5;
    const int lane = tid & 31;
    const int g = lane >> 2;
    const int tig = lane & 3;
    const int wm = wid & 1;
    const int wn = wid >> 1;

    const int n0 = blockIdx.x * BN;
    const int m0 = blockIdx.y * BM;
    const int NT = K / BKH;

    float acc[4][4][4];
    #pragma unroll
    for (int mt = 0; mt < 4; mt++)
        #pragma unroll
        for (int nt = 0; nt < 4; nt++)
            #pragma unroll
            for (int e = 0; e < 4; e++) acc[mt][nt][e] = 0.f;

    auto load_stage = [&](int st, int t) {
        const uint32_t aoff = sbase + (uint32_t)st * STAGE_BYTES;
        const uint32_t boff = aoff + TILE_HALVES * 2;
        #pragma unroll
        for (int i = 0; i < 4; i++) {
            const int idx = i * 256 + tid;
            const int row = idx >> 3, ch = idx & 7;
            cp_async16(aoff + (uint32_t)(row * TSH + ch * 8) * 2u,
                       A + (size_t)(m0 + row) * K + (size_t)t * BKH + ch * 8);
            cp_async16(boff + (uint32_t)(row * TSH + ch * 8) * 2u,
                       BT + (size_t)(n0 + row) * K + (size_t)t * BKH + ch * 8);
        }
    };

    #pragma unroll
    for (int t = 0; t < STAGES - 1; t++) {
        load_stage(t, t);
        cp_commit();
    }

    for (int t = 0; t < NT; t++) {
        asm volatile("cp.async.wait_group %0;" :: "n"(STAGES - 2) : "memory");
        __syncthreads();

        const int pf = t + STAGES - 1;
        if (pf < NT) load_stage(pf % STAGES, pf);
        cp_commit();

        const int st = t % STAGES;
        const uint32_t* pA = (const uint32_t*)(smh + (size_t)st * STAGE_BYTES / 2) + (wm * 64) * 36;
        const uint32_t* pB = (const uint32_t*)(smh + (size_t)st * STAGE_BYTES / 2 + TILE_HALVES) + (wn * 32) * 36;

        #pragma unroll
        for (int ks = 0; ks < 4; ks++) {
            const int k8 = ks * 8;
            uint32_t afr[4][4], bfr[4][2];
            #pragma unroll
            for (int mt = 0; mt < 4; mt++) {
                const uint32_t* p = pA + (mt * 16 + g) * 36 + k8 + tig;
                afr[mt][0] = p[0];
                afr[mt][1] = p[8 * 36];
                afr[mt][2] = p[4];
                afr[mt][3] = p[8 * 36 + 4];
            }
            #pragma unroll
            for (int nt = 0; nt < 4; nt++) {
                const uint32_t* p = pB + (nt * 8 + g) * 36 + k8 + tig;
                bfr[nt][0] = p[0];
                bfr[nt][1] = p[4];
            }
            #pragma unroll
            for (int mt = 0; mt < 4; mt++)
                #pragma unroll
                for (int nt = 0; nt < 4; nt++)
                    mma_f16_16x8x16(acc[mt][nt], afr[mt], bfr[nt]);
        }
    }

    #pragma unroll
    for (int mt = 0; mt < 4; mt++) {
        const int r0 = m0 + wm * 64 + mt * 16 + g;
        const float* rr0 = (EPI == 1) ? (res + (size_t)r0 * N) : nullptr;
        const float* rr1 = (EPI == 1) ? (res + (size_t)(r0 + 8) * N) : nullptr;
        #pragma unroll
        for (int nt = 0; nt < 4; nt++) {
            const int col = n0 + wn * 32 + nt * 8 + 2 * tig;
            const float bx = bias[col], by = bias[col + 1];
            float v0 = acc[mt][nt][0] + bx, v1 = acc[mt][nt][1] + by;
            float v2 = acc[mt][nt][2] + bx, v3 = acc[mt][nt][3] + by;
            if (EPI == 2) {
                v0 = gelu_exact(v0); v1 = gelu_exact(v1);
                v2 = gelu_exact(v2); v3 = gelu_exact(v3);
            }
            if (EPI == 1) {
                v0 += rr0[col]; v1 += rr0[col + 1];
                v2 += rr1[col]; v3 += rr1[col + 1];
            }
            if (OUTH) {
                __half* C = (__half*)Cv;
                *(uint32_t*)(C + (size_t)r0 * N + col)       = pack_h2(v0, v1);
                *(uint32_t*)(C + (size_t)(r0 + 8) * N + col) = pack_h2(v2, v3);
            } else {
                float* C = (float*)Cv;
                *(float2*)(C + (size_t)r0 * N + col)       = make_float2(v0, v1);
                *(float2*)(C + (size_t)(r0 + 8) * N + col) = make_float2(v2, v3);
            }
        }
    }
}

// ---------------- fp16 flash attention: KV tile 64, 2 CTAs/SM ----------------
// Q tile 128 (8 warps x 16 rows); K natural [s][dk]; V via vt [dk][s].
#define KV 64
#define KSH 72                                   // halves per K smem row, 36 words
#define VSH 72                                   // halves per VT smem row (s-cols of this tile), 36 words
#define PSH 72                                   // halves per P smem row, 36 words
#define K_TILE_HALVES (KV * KSH)                 // 4608
#define V_TILE_HALVES (DK * VSH)                 // 4608
#define P_HALVES (128 * PSH)                     // 9216
#define ATTN_SMEM ((2 * K_TILE_HALVES + 2 * V_TILE_HALVES + P_HALVES) * 2)   // 55296 B

__global__ void __launch_bounds__(256, 2) attn_f16_kernel(const __half* __restrict__ qkv,
                                                          const __half* __restrict__ vt,
                                                          __half* __restrict__ out)
{
    extern __shared__ __half smh[];
    __half* Ks  = smh;                                  // 2 x [64][72]
    __half* Vts = Ks + 2 * K_TILE_HALVES;               // 2 x [64][72]
    __half* Ps  = Vts + 2 * V_TILE_HALVES;              // [128][72]
    const uint32_t sbase = smem_u32(smh);

    const int tid = threadIdx.x;
    const int w = tid >> 5;
    const int lane = tid & 31;
    const int g = lane >> 2;
    const int tig = lane & 3;

    const int qt = blockIdx.x, h = blockIdx.y, b = blockIdx.z;

    // ---- Q fragments (scaled by 1/8, exact in fp16) ----
    uint32_t qa[4][4];
    {
        const __half* qb = qkv + ((size_t)(b * SEQ + qt * 128 + w * 16)) * QLD + h * DK;
        const __half2 sc = __floats2half2_rn(0.125f, 0.125f);
        #pragma unroll
        for (int ks = 0; ks < 4; ks++) {
            const int c = ks * 16 + 2 * tig;
            __half2 a0 = __hmul2(*(const __half2*)(qb + (size_t)g * QLD + c), sc);
            __half2 a1 = __hmul2(*(const __half2*)(qb + (size_t)(g + 8) * QLD + c), sc);
            __half2 a2 = __hmul2(*(const __half2*)(qb + (size_t)g * QLD + c + 8), sc);
            __half2 a3 = __hmul2(*(const __half2*)(qb + (size_t)(g + 8) * QLD + c + 8), sc);
            qa[ks][0] = *(uint32_t*)&a0; qa[ks][1] = *(uint32_t*)&a1;
            qa[ks][2] = *(uint32_t*)&a2; qa[ks][3] = *(uint32_t*)&a3;
        }
    }

    float o[8][4];
    #pragma unroll
    for (int nt = 0; nt < 8; nt++)
        #pragma unroll
        for (int e = 0; e < 4; e++) o[nt][e] = 0.f;
    float m0 = -1e30f, m1 = -1e30f, l0 = 0.f, l1 = 0.f;

    auto load_kv = [&](int t, int buf) {
        const uint32_t kdst = sbase + (uint32_t)(buf * K_TILE_HALVES) * 2u;
        const uint32_t vdst = sbase + (uint32_t)(2 * K_TILE_HALVES + buf * V_TILE_HALVES) * 2u;
        const __half* ksrc = qkv + ((size_t)(b * SEQ + t * KV)) * QLD + DM + h * DK;
        const __half* vsrc = vt + (size_t)(h * DK) * (BATCH * SEQ) + (size_t)b * SEQ + (size_t)t * KV;
        // K: 64 rows x 8 chunks = 512; V: 64 rows x 8 chunks = 512
        {
            const int idx = tid;                      // 0..255 -> rows 0..31
            const int kr0 = idx >> 3, kc = idx & 7;
            cp_async16(kdst + (uint32_t)(kr0 * KSH + kc * 8) * 2u,
                       ksrc + (size_t)kr0 * QLD + kc * 8);
            cp_async16(kdst + (uint32_t)((kr0 + 32) * KSH + kc * 8) * 2u,
                       ksrc + (size_t)(kr0 + 32) * QLD + kc * 8);
            cp_async16(vdst + (uint32_t)(kr0 * VSH + kc * 8) * 2u,
                       vsrc + (size_t)kr0 * (BATCH * SEQ) + kc * 8);
            cp_async16(vdst + (uint32_t)((kr0 + 32) * VSH + kc * 8) * 2u,
                       vsrc + (size_t)(kr0 + 32) * (BATCH * SEQ) + kc * 8);
        }
    };

    load_kv(0, 0);
    cp_commit();

    const int NKV = SEQ / KV;
    for (int t = 0; t < NKV; t++) {
        asm volatile("cp.async.wait_group 0;" ::: "memory");
        __syncthreads();
        if (t + 1 < NKV) { load_kv(t + 1, (t + 1) & 1); cp_commit(); }

        // ---- S = Q @ K^T : per warp 16 x 64 ----
        float s[8][4];
        #pragma unroll
        for (int nt = 0; nt < 8; nt++)
            #pragma unroll
            for (int e = 0; e < 4; e++) s[nt][e] = 0.f;
        {
            const uint32_t* kp = (const uint32_t*)(Ks + (t & 1) * K_TILE_HALVES);
            #pragma unroll
            for (int ks = 0; ks < 4; ks++) {
                const int k8 = ks * 8;
                #pragma unroll
                for (int nt = 0; nt < 8; nt++) {
                    uint32_t bfr[2];
                    const uint32_t* p = kp + (nt * 8 + g) * 36 + k8 + tig;
                    bfr[0] = p[0];
                    bfr[1] = p[4];
                    mma_f16_16x8x16(s[nt], qa[ks], bfr);
                }
            }
        }

        // ---- online softmax ----
        float rmax0 = -1e30f, rmax1 = -1e30f;
        #pragma unroll
        for (int nt = 0; nt < 8; nt++) {
            rmax0 = fmaxf(rmax0, fmaxf(s[nt][0], s[nt][1]));
            rmax1 = fmaxf(rmax1, fmaxf(s[nt][2], s[nt][3]));
        }
        rmax0 = fmaxf(rmax0, __shfl_xor_sync(0xffffffffu, rmax0, 1));
        rmax0 = fmaxf(rmax0, __shfl_xor_sync(0xffffffffu, rmax0, 2));
        rmax1 = fmaxf(rmax1, __shfl_xor_sync(0xffffffffu, rmax1, 1));
        rmax1 = fmaxf(rmax1, __shfl_xor_sync(0xffffffffu, rmax1, 2));

        const float mn0 = fmaxf(m0, rmax0);
        const float mn1 = fmaxf(m1, rmax1);
        const float al0 = __expf(m0 - mn0);
        const float al1 = __expf(m1 - mn1);
        m0 = mn0; m1 = mn1;

        float rs0 = 0.f, rs1 = 0.f;
        {
            uint32_t* ps0 = (uint32_t*)Ps + (size_t)(w * 16 + g) * 36 + tig;
            uint32_t* ps1 = ps0 + 8 * 36;
            #pragma unroll
            for (int nt = 0; nt < 8; nt++) {
                const __half2 h0 = __floats2half2_rn(__expf(s[nt][0] - mn0), __expf(s[nt][1] - mn0));
                const __half2 h1 = __floats2half2_rn(__expf(s[nt][2] - mn1), __expf(s[nt][3] - mn1));
                const float2 f0 = __half22float2(h0);
                const float2 f1 = __half22float2(h1);
                rs0 += f0.x + f0.y; rs1 += f1.x + f1.y;
                ps0[nt * 4] = *(const uint32_t*)&h0;
                ps1[nt * 4] = *(const uint32_t*)&h1;
            }
        }
        rs0 += __shfl_xor_sync(0xffffffffu, rs0, 1);
        rs0 += __shfl_xor_sync(0xffffffffu, rs0, 2);
        rs1 += __shfl_xor_sync(0xffffffffu, rs1, 1);
        rs1 += __shfl_xor_sync(0xffffffffu, rs1, 2);
        l0 = l0 * al0 + rs0;
        l1 = l1 * al1 + rs1;

        #pragma unroll
        for (int nt = 0; nt < 8; nt++) {
            o[nt][0] *= al0; o[nt][1] *= al0;
            o[nt][2] *= al1; o[nt][3] *= al1;
        }
        __syncwarp();

        // ---- O += P @ V : per warp 16 x 64, k = 64 ----
        {
            const uint32_t* pp = (const uint32_t*)Ps + (size_t)(w * 16) * 36;
            const uint32_t* vp = (const uint32_t*)(Vts + (t & 1) * V_TILE_HALVES);
            #pragma unroll
            for (int ks = 0; ks < 4; ks++) {
                const int k8 = ks * 8;
                uint32_t a[4];
                a[0] = pp[(g) * 36 + k8 + tig];
                a[1] = pp[(g + 8) * 36 + k8 + tig];
                a[2] = pp[(g) * 36 + k8 + tig + 4];
                a[3] = pp[(g + 8) * 36 + k8 + tig + 4];
                #pragma unroll
                for (int nt = 0; nt < 8; nt++) {
                    uint32_t bfr[2];
                    const uint32_t* p = vp + (nt * 8 + g) * 36 + k8 + tig;
                    bfr[0] = p[0];
                    bfr[1] = p[4];
                    mma_f16_16x8x16(o[nt], a, bfr);
                }
            }
        }
        __syncwarp();
    }

    // ---- epilogue: normalize, fp16 out ----
    {
        const float i0 = 1.0f / l0, i1 = 1.0f / l1;
        const int r0 = qt * 128 + w * 16 + g;
        __half* ob0 = out + ((size_t)(b * SEQ + r0)) * DM + h * DK + 2 * tig;
        __half* ob1 = ob0 + 8 * DM;
        #pragma unroll
        for (int nt = 0; nt < 8; nt++) {
            *(uint32_t*)(ob0 + nt * 8) = pack_h2(o[nt][0] * i0, o[nt][1] * i0);
            *(uint32_t*)(ob1 + nt * 8) = pack_h2(o[nt][2] * i1, o[nt][3] * i1);
        }
    }
}

// ---------------- host launcher ----------------
extern "C" void kernel_launch(void* const* d_in, const int* in_sizes, int n_in,
                              void* d_out, int out_size)
{
    (void)in_sizes; (void)n_in; (void)out_size;
    const float* x     = (const float*)d_in[0];
    const float* Wq    = (const float*)d_in[1];
    const float* bq    = (const float*)d_in[2];
    const float* Wk    = (const float*)d_in[3];
    const float* bk    = (const float*)d_in[4];
    const float* Wv    = (const float*)d_in[5];
    const float* bv    = (const float*)d_in[6];
    const float* Wo    = (const float*)d_in[7];
    const float* bo    = (const float*)d_in[8];
    const float* ln1_g = (const float*)d_in[9];
    const float* ln1_b = (const float*)d_in[10];
    const float* W1    = (const float*)d_in[11];
    const float* b1    = (const float*)d_in[12];
    const float* W2    = (const float*)d_in[13];
    const float* b2    = (const float*)d_in[14];
    const float* ln2_g = (const float*)d_in[15];
    const float* ln2_b = (const float*)d_in[16];
    float* out = (float*)d_out;

    __half *h, *qkv, *vt, *ctx, *h2, *ff, *wqkvT, *woT, *w1T, *w2T;
    float *x1, *bqkv;
    cudaGetSymbolAddress((void**)&h,     g_h);
    cudaGetSymbolAddress((void**)&qkv,   g_qkv);
    cudaGetSymbolAddress((void**)&vt,    g_vt);
    cudaGetSymbolAddress((void**)&ctx,   g_ctx);
    cudaGetSymbolAddress((void**)&x1,    g_x1);
    cudaGetSymbolAddress((void**)&h2,    g_h2);
    cudaGetSymbolAddress((void**)&ff,    g_ff);
    cudaGetSymbolAddress((void**)&wqkvT, g_wqkvT);
    cudaGetSymbolAddress((void**)&bqkv,  g_bqkv);
    cudaGetSymbolAddress((void**)&woT,   g_woT);
    cudaGetSymbolAddress((void**)&w1T,   g_w1T);
    cudaGetSymbolAddress((void**)&w2T,   g_w2T);

    cudaFuncSetAttribute(attn_f16_kernel, cudaFuncAttributeMaxDynamicSharedMemorySize, ATTN_SMEM);
    cudaFuncSetAttribute(gemm_f16<0,1>, cudaFuncAttributeMaxDynamicSharedMemorySize, GEMM_SMEM_BYTES);
    cudaFuncSetAttribute(gemm_f16<1,0>, cudaFuncAttributeMaxDynamicSharedMemorySize, GEMM_SMEM_BYTES);
    cudaFuncSetAttribute(gemm_f16<2,1>, cudaFuncAttributeMaxDynamicSharedMemorySize, GEMM_SMEM_BYTES);

    const dim3 tB(32, 8);
    const dim3 gQKV(QLD / BN, TOK / BM);    // (24, 64)
    const dim3 gProj(DM / BN, TOK / BM);    // (8, 64)
    const dim3 gFF1(DFF / BN, TOK / BM);    // (32, 64)

    // launch 0: fused weight prep
    prep_kernel<<<12291, tB>>>(Wq, Wk, Wv, bq, bk, bv, Wo, W1, W2,
                               wqkvT, bqkv, woT, w1T, w2T);
    // launch 1: LN1 -> fp16
    ln_kernel<<<TOK, 256>>>(x, ln1_g, ln1_b, h);
    // launch 2: fused qkv projection (fp16 out)
    gemm_f16<0,1><<<gQKV, 256, GEMM_SMEM_BYTES>>>(h, wqkvT, bqkv, nullptr, qkv, TOK, QLD, DM);
    // launch 3: V transpose
    vtrans_kernel<<<dim3(SEQ / 32, DK / 32, NH * BATCH), tB>>>(qkv, vt);
    // launch 4: flash attention
    attn_f16_kernel<<<dim3(SEQ / 128, NH, BATCH), 256, ATTN_SMEM>>>(qkv, vt, ctx);
    // launch 5 (ncu capture): x1 = x + ctx @ Wo + bo (fp32 out)
    gemm_f16<1,0><<<gProj, 256, GEMM_SMEM_BYTES>>>(ctx, woT, bo, x, x1, TOK, DM, DM);
    // launch 6: LN2 -> fp16
    ln_kernel<<<TOK, 256>>>(x1, ln2_g, ln2_b, h2);
    // launch 7: ff = gelu(h2 @ W1 + b1) (fp16 out)
    gemm_f16<2,1><<<gFF1, 256, GEMM_SMEM_BYTES>>>(h2, w1T, b1, nullptr, ff, TOK, DFF, DM);
    // launch 8: out = x1 + ff @ W2 + b2 (fp32 out)
    gemm_f16<1,0><<<gProj, 256, GEMM_SMEM_BYTES>>>(ff, w2T, b2, x1, out, TOK, DM, DFF);
}

// round 9
// speedup vs baseline: 7.2381x; 1.0488x over previous
#include <cuda_runtime.h>
#include <cuda_fp16.h>
#include <math.h>
#include <stdint.h>

#define TOK   8192
#define DM    1024
#define DFF   4096
#define NH    16
#define DK    64
#define SEQ   2048
#define BATCH 4
#define QLD   (3 * DM)

// ---------------- scratch ----------------
__device__ __half g_h   [TOK * DM];
__device__ __half g_qkv [TOK * QLD];
__device__ __half g_vt  [DM * TOK];            // [(h*DK+dk)][b*SEQ+s]
__device__ __half g_ctx [TOK * DM];
__device__ float  g_x1  [TOK * DM];
__device__ __half g_h2  [TOK * DM];
__device__ __half g_ff  [TOK * DFF];
// fp16 weights, transposed to [N][K]
__device__ __half g_wqkvT[QLD * DM];
__device__ float  g_bqkv [QLD];
__device__ __half g_woT  [DM * DM];
__device__ __half g_w1T  [DFF * DM];
__device__ __half g_w2T  [DM * DFF];

// ---------------- helpers ----------------
__device__ __forceinline__ uint32_t smem_u32(const void* p) {
    uint32_t a;
    asm("{ .reg .u64 t; cvta.to.shared.u64 t, %1; cvt.u32.u64 %0, t; }" : "=r"(a) : "l"(p));
    return a;
}
__device__ __forceinline__ void cp_async16(uint32_t dst, const void* src) {
    asm volatile("cp.async.cg.shared.global [%0], [%1], 16;" :: "r"(dst), "l"(src));
}
__device__ __forceinline__ void cp_commit() {
    asm volatile("cp.async.commit_group;" ::: "memory");
}
__device__ __forceinline__ void mma_f16_16x8x16(float* d, const uint32_t* a, const uint32_t* b) {
    asm volatile(
        "mma.sync.aligned.m16n8k16.row.col.f32.f16.f16.f32 "
        "{%0,%1,%2,%3}, {%4,%5,%6,%7}, {%8,%9}, {%0,%1,%2,%3};"
        : "+f"(d[0]), "+f"(d[1]), "+f"(d[2]), "+f"(d[3])
        : "r"(a[0]), "r"(a[1]), "r"(a[2]), "r"(a[3]), "r"(b[0]), "r"(b[1]));
}
__device__ __forceinline__ void ldmatrix_x4(uint32_t* r, uint32_t addr) {
    asm volatile("ldmatrix.sync.aligned.m8n8.x4.shared.b16 {%0,%1,%2,%3}, [%4];"
        : "=r"(r[0]), "=r"(r[1]), "=r"(r[2]), "=r"(r[3]) : "r"(addr));
}
__device__ __forceinline__ void ldmatrix_x2(uint32_t* r, uint32_t addr) {
    asm volatile("ldmatrix.sync.aligned.m8n8.x2.shared.b16 {%0,%1}, [%2];"
        : "=r"(r[0]), "=r"(r[1]) : "r"(addr));
}
__device__ __forceinline__ uint32_t pack_h2(float x, float y) {
    __half2 h = __floats2half2_rn(x, y);
    return *(uint32_t*)&h;
}

// ---------------- prep part 1: QKV weights + bias (needed before QKV GEMM) ----------------
// blocks [0,3072): Wq/Wk/Wv 32x32 tiles; [3072,3075): bias
__global__ void __launch_bounds__(256) prep1_kernel(
    const float* __restrict__ Wq, const float* __restrict__ Wk, const float* __restrict__ Wv,
    const float* __restrict__ bq, const float* __restrict__ bk, const float* __restrict__ bv,
    __half* __restrict__ wqkvT, float* __restrict__ bqkv)
{
    const int id = blockIdx.x;
    const int tx = threadIdx.x, ty = threadIdx.y;
    if (id >= 3072) {
        const int which = id - 3072;
        const float* src = which == 0 ? bq : (which == 1 ? bk : bv);
        const int t = ty * 32 + tx;
        ((float4*)bqkv)[which * 256 + t] = ((const float4*)src)[t];
        return;
    }
    const int m = id >> 10, lid = id & 1023;
    const float* in = m == 0 ? Wq : (m == 1 ? Wk : Wv);
    __half* out = wqkvT + (size_t)m * DM * DM;
    const int c0 = (lid & 31) * 32, r0 = (lid >> 5) * 32;
    __shared__ float tile[32][33];
    #pragma unroll
    for (int i = ty; i < 32; i += 8)
        tile[i][tx] = in[(size_t)(r0 + i) * DM + c0 + tx];
    __syncthreads();
    #pragma unroll
    for (int i = ty; i < 32; i += 8)
        out[(size_t)(c0 + i) * DM + r0 + tx] = __float2half_rn(tile[tx][i]);
}

// ---------------- prep part 2: Wo/W1/W2 ----------------
// blocks [0,1024): Wo; [1024,5120): W1; [5120,9216): W2
__global__ void __launch_bounds__(256) prep2_kernel(
    const float* __restrict__ Wo, const float* __restrict__ W1, const float* __restrict__ W2,
    __half* __restrict__ woT, __half* __restrict__ w1T, __half* __restrict__ w2T)
{
    const int id = blockIdx.x;
    const int tx = threadIdx.x, ty = threadIdx.y;
    const float* in; __half* out; int R, C, lid;
    if (id < 1024)      { lid = id;        in = Wo; out = woT; R = DM;  C = DM;  }
    else if (id < 5120) { lid = id - 1024; in = W1; out = w1T; R = DM;  C = DFF; }
    else                { lid = id - 5120; in = W2; out = w2T; R = DFF; C = DM;  }
    const int tilesx = C / 32;
    const int c0 = (lid % tilesx) * 32, r0 = (lid / tilesx) * 32;
    __shared__ float tile[32][33];
    #pragma unroll
    for (int i = ty; i < 32; i += 8)
        tile[i][tx] = in[(size_t)(r0 + i) * C + c0 + tx];
    __syncthreads();
    #pragma unroll
    for (int i = ty; i < 32; i += 8)
        out[(size_t)(c0 + i) * R + r0 + tx] = __float2half_rn(tile[tx][i]);
}

// ---------------- V transpose (fp16) ----------------
__global__ void __launch_bounds__(256) vtrans_kernel(const __half* __restrict__ in,
                                                     __half* __restrict__ out)
{
    __shared__ __half tile[32][33];
    const int s0 = blockIdx.x * 32;
    const int d0 = blockIdx.y * 32;
    const int h  = blockIdx.z & (NH - 1);
    const int b  = blockIdx.z >> 4;
    const int tx = threadIdx.x, ty = threadIdx.y;

    const __half* ip = in + ((size_t)(b * SEQ + s0)) * QLD + 2 * DM + h * DK + d0;
    #pragma unroll
    for (int i = ty; i < 32; i += 8)
        tile[i][tx] = ip[(size_t)i * QLD + tx];
    __syncthreads();
    __half* op = out + ((size_t)(h * DK + d0)) * (BATCH * SEQ) + (size_t)b * SEQ + s0;
    #pragma unroll
    for (int i = ty; i < 32; i += 8)
        op[(size_t)i * (BATCH * SEQ) + tx] = tile[tx][i];
}

// ---------------- LayerNorm: fp32 in, fp16 out ----------------
__global__ void __launch_bounds__(256) ln_kernel(const float* __restrict__ x,
                                                 const float* __restrict__ g,
                                                 const float* __restrict__ b,
                                                 __half* __restrict__ out)
{
    const int row = blockIdx.x;
    const int tid = threadIdx.x;
    const float4 v = ((const float4*)(x + (size_t)row * DM))[tid];

    float s  = v.x + v.y + v.z + v.w;
    float ss = v.x * v.x + v.y * v.y + v.z * v.z + v.w * v.w;
    #pragma unroll
    for (int o = 16; o; o >>= 1) {
        s  += __shfl_xor_sync(0xffffffffu, s,  o);
        ss += __shfl_xor_sync(0xffffffffu, ss, o);
    }
    __shared__ float sb[8], sb2[8];
    if ((tid & 31) == 0) { sb[tid >> 5] = s; sb2[tid >> 5] = ss; }
    __syncthreads();
    float ts = 0.f, ts2 = 0.f;
    #pragma unroll
    for (int i = 0; i < 8; i++) { ts += sb[i]; ts2 += sb2[i]; }

    const float mu  = ts * (1.0f / DM);
    const float var = ts2 * (1.0f / DM) - mu * mu;
    const float inv = rsqrtf(var + 1e-5f);

    const float4 gg = ((const float4*)g)[tid];
    const float4 bb = ((const float4*)b)[tid];
    uint32_t p0 = pack_h2((v.x - mu) * inv * gg.x + bb.x, (v.y - mu) * inv * gg.y + bb.y);
    uint32_t p1 = pack_h2((v.z - mu) * inv * gg.z + bb.z, (v.w - mu) * inv * gg.w + bb.w);
    uint2 o; o.x = p0; o.y = p1;
    ((uint2*)(out + (size_t)row * DM))[tid] = o;
}

// ---------------- fp16 mma.sync GEMM: 128x128 tile, BK=64 halves, 3-stage, 2 CTAs/SM ----------------
__device__ __forceinline__ float gelu_exact(float v) {
    return 0.5f * v * (1.0f + erff(v * 0.70710678118654752440f));
}

#define BM 128
#define BN 128
#define BKH 64
#define STAGES 3
#define TSH 72                          // halves per smem row = 144 bytes
#define TILE_HALVES (128 * TSH)
#define STAGE_BYTES (2 * TILE_HALVES * 2)
#define GEMM_SMEM_BYTES (STAGES * STAGE_BYTES)

template <int EPI, int OUTH>
__global__ void __launch_bounds__(256, 2) gemm_f16(
    const __half* __restrict__ A, const __half* __restrict__ BT,
    const float* __restrict__ bias, const float* __restrict__ res,
    void* __restrict__ Cv, int M, int N, int K)
{
    extern __shared__ __half smh[];
    const uint32_t sbase = smem_u32(smh);

    const int tid = threadIdx.x;
    const int wid = tid >> 5;
    const int lane = tid & 31;
    const int g = lane >> 2;
    const int tig = lane & 3;
    const int wm = wid & 1;
    const int wn = wid >> 1;

    // ldmatrix per-lane row offsets (bytes)
    const uint32_t aRow = (uint32_t)((lane & 15) * 144 + (lane >> 4) * 16);
    const uint32_t bRow = (uint32_t)((lane & 7) * 144 + ((lane >> 3) & 1) * 16);

    const int n0 = blockIdx.x * BN;
    const int m0 = blockIdx.y * BM;
    const int NT = K / BKH;

    float acc[4][4][4];
    #pragma unroll
    for (int mt = 0; mt < 4; mt++)
        #pragma unroll
        for (int nt = 0; nt < 4; nt++)
            #pragma unroll
            for (int e = 0; e < 4; e++) acc[mt][nt][e] = 0.f;

    auto load_stage = [&](int st, int t) {
        const uint32_t aoff = sbase + (uint32_t)st * STAGE_BYTES;
        const uint32_t boff = aoff + TILE_HALVES * 2;
        #pragma unroll
        for (int i = 0; i < 4; i++) {
            const int idx = i * 256 + tid;
            const int row = idx >> 3, ch = idx & 7;
            cp_async16(aoff + (uint32_t)(row * TSH + ch * 8) * 2u,
                       A + (size_t)(m0 + row) * K + (size_t)t * BKH + ch * 8);
            cp_async16(boff + (uint32_t)(row * TSH + ch * 8) * 2u,
                       BT + (size_t)(n0 + row) * K + (size_t)t * BKH + ch * 8);
        }
    };

    #pragma unroll
    for (int t = 0; t < STAGES - 1; t++) {
        load_stage(t, t);
        cp_commit();
    }

    for (int t = 0; t < NT; t++) {
        asm volatile("cp.async.wait_group %0;" :: "n"(STAGES - 2) : "memory");
        __syncthreads();

        const int pf = t + STAGES - 1;
        if (pf < NT) load_stage(pf % STAGES, pf);
        cp_commit();

        const int st = t % STAGES;
        const uint32_t aBase = sbase + (uint32_t)st * STAGE_BYTES + (uint32_t)(wm * 64) * 144 + aRow;
        const uint32_t bBase = sbase + (uint32_t)st * STAGE_BYTES + TILE_HALVES * 2 + (uint32_t)(wn * 32) * 144 + bRow;

        #pragma unroll
        for (int ks = 0; ks < 4; ks++) {
            const uint32_t kb = (uint32_t)(ks * 32);
            uint32_t afr[4][4], bfr[4][2];
            #pragma unroll
            for (int mt = 0; mt < 4; mt++)
                ldmatrix_x4(afr[mt], aBase + (uint32_t)(mt * 16) * 144 + kb);
            #pragma unroll
            for (int nt = 0; nt < 4; nt++)
                ldmatrix_x2(bfr[nt], bBase + (uint32_t)(nt * 8) * 144 + kb);
            #pragma unroll
            for (int mt = 0; mt < 4; mt++)
                #pragma unroll
                for (int nt = 0; nt < 4; nt++)
                    mma_f16_16x8x16(acc[mt][nt], afr[mt], bfr[nt]);
        }
    }

    #pragma unroll
    for (int mt = 0; mt < 4; mt++) {
        const int r0 = m0 + wm * 64 + mt * 16 + g;
        const float* rr0 = (EPI == 1) ? (res + (size_t)r0 * N) : nullptr;
        const float* rr1 = (EPI == 1) ? (res + (size_t)(r0 + 8) * N) : nullptr;
        #pragma unroll
        for (int nt = 0; nt < 4; nt++) {
            const int col = n0 + wn * 32 + nt * 8 + 2 * tig;
            const float bx = bias[col], by = bias[col + 1];
            float v0 = acc[mt][nt][0] + bx, v1 = acc[mt][nt][1] + by;
            float v2 = acc[mt][nt][2] + bx, v3 = acc[mt][nt][3] + by;
            if (EPI == 2) {
                v0 = gelu_exact(v0); v1 = gelu_exact(v1);
                v2 = gelu_exact(v2); v3 = gelu_exact(v3);
            }
            if (EPI == 1) {
                v0 += rr0[col]; v1 += rr0[col + 1];
                v2 += rr1[col]; v3 += rr1[col + 1];
            }
            if (OUTH) {
                __half* C = (__half*)Cv;
                *(uint32_t*)(C + (size_t)r0 * N + col)       = pack_h2(v0, v1);
                *(uint32_t*)(C + (size_t)(r0 + 8) * N + col) = pack_h2(v2, v3);
            } else {
                float* C = (float*)Cv;
                *(float2*)(C + (size_t)r0 * N + col)       = make_float2(v0, v1);
                *(float2*)(C + (size_t)(r0 + 8) * N + col) = make_float2(v2, v3);
            }
        }
    }
}

// ---------------- fp16 flash attention: KV tile 64, 2 CTAs/SM ----------------
#define KV 64
#define KSH 72
#define VSH 72
#define PSH 72
#define K_TILE_HALVES (KV * KSH)
#define V_TILE_HALVES (DK * VSH)
#define P_HALVES (128 * PSH)
#define ATTN_SMEM ((2 * K_TILE_HALVES + 2 * V_TILE_HALVES + P_HALVES) * 2)

__global__ void __launch_bounds__(256, 2) attn_f16_kernel(const __half* __restrict__ qkv,
                                                          const __half* __restrict__ vt,
                                                          __half* __restrict__ out)
{
    extern __shared__ __half smh[];
    __half* Ks  = smh;
    __half* Vts = Ks + 2 * K_TILE_HALVES;
    __half* Ps  = Vts + 2 * V_TILE_HALVES;
    const uint32_t sbase = smem_u32(smh);
    const uint32_t vtsBase = sbase + 2 * K_TILE_HALVES * 2;
    const uint32_t psBase  = vtsBase + 2 * V_TILE_HALVES * 2;

    const int tid = threadIdx.x;
    const int w = tid >> 5;
    const int lane = tid & 31;
    const int g = lane >> 2;
    const int tig = lane & 3;

    const uint32_t aRow = (uint32_t)((lane & 15) * 144 + (lane >> 4) * 16);
    const uint32_t bRow = (uint32_t)((lane & 7) * 144 + ((lane >> 3) & 1) * 16);

    const int qt = blockIdx.x, h = blockIdx.y, b = blockIdx.z;

    // ---- Q fragments (scaled by 1/8, exact) ----
    uint32_t qa[4][4];
    {
        const __half* qb = qkv + ((size_t)(b * SEQ + qt * 128 + w * 16)) * QLD + h * DK;
        const __half2 sc = __floats2half2_rn(0.125f, 0.125f);
        #pragma unroll
        for (int ks = 0; ks < 4; ks++) {
            const int c = ks * 16 + 2 * tig;
            __half2 a0 = __hmul2(*(const __half2*)(qb + (size_t)g * QLD + c), sc);
            __half2 a1 = __hmul2(*(const __half2*)(qb + (size_t)(g + 8) * QLD + c), sc);
            __half2 a2 = __hmul2(*(const __half2*)(qb + (size_t)g * QLD + c + 8), sc);
            __half2 a3 = __hmul2(*(const __half2*)(qb + (size_t)(g + 8) * QLD + c + 8), sc);
            qa[ks][0] = *(uint32_t*)&a0; qa[ks][1] = *(uint32_t*)&a1;
            qa[ks][2] = *(uint32_t*)&a2; qa[ks][3] = *(uint32_t*)&a3;
        }
    }

    float o[8][4];
    #pragma unroll
    for (int nt = 0; nt < 8; nt++)
        #pragma unroll
        for (int e = 0; e < 4; e++) o[nt][e] = 0.f;
    float m0 = -1e30f, m1 = -1e30f, l0 = 0.f, l1 = 0.f;

    auto load_kv = [&](int t, int buf) {
        const uint32_t kdst = sbase + (uint32_t)(buf * K_TILE_HALVES) * 2u;
        const uint32_t vdst = vtsBase + (uint32_t)(buf * V_TILE_HALVES) * 2u;
        const __half* ksrc = qkv + ((size_t)(b * SEQ + t * KV)) * QLD + DM + h * DK;
        const __half* vsrc = vt + (size_t)(h * DK) * (BATCH * SEQ) + (size_t)b * SEQ + (size_t)t * KV;
        const int kr0 = tid >> 3, kc = tid & 7;
        cp_async16(kdst + (uint32_t)(kr0 * KSH + kc * 8) * 2u,
                   ksrc + (size_t)kr0 * QLD + kc * 8);
        cp_async16(kdst + (uint32_t)((kr0 + 32) * KSH + kc * 8) * 2u,
                   ksrc + (size_t)(kr0 + 32) * QLD + kc * 8);
        cp_async16(vdst + (uint32_t)(kr0 * VSH + kc * 8) * 2u,
                   vsrc + (size_t)kr0 * (BATCH * SEQ) + kc * 8);
        cp_async16(vdst + (uint32_t)((kr0 + 32) * VSH + kc * 8) * 2u,
                   vsrc + (size_t)(kr0 + 32) * (BATCH * SEQ) + kc * 8);
    };

    load_kv(0, 0);
    cp_commit();

    const int NKV = SEQ / KV;
    for (int t = 0; t < NKV; t++) {
        asm volatile("cp.async.wait_group 0;" ::: "memory");
        __syncthreads();
        if (t + 1 < NKV) { load_kv(t + 1, (t + 1) & 1); cp_commit(); }

        // ---- S = Q @ K^T ----
        float s[8][4];
        #pragma unroll
        for (int nt = 0; nt < 8; nt++)
            #pragma unroll
            for (int e = 0; e < 4; e++) s[nt][e] = 0.f;
        {
            const uint32_t kTile = sbase + (uint32_t)((t & 1) * K_TILE_HALVES) * 2u + bRow;
            #pragma unroll
            for (int ks = 0; ks < 4; ks++) {
                const uint32_t kb = (uint32_t)(ks * 32);
                #pragma unroll
                for (int nt = 0; nt < 8; nt++) {
                    uint32_t bfr[2];
                    ldmatrix_x2(bfr, kTile + (uint32_t)(nt * 8) * 144 + kb);
                    mma_f16_16x8x16(s[nt], qa[ks], bfr);
                }
            }
        }

        // ---- online softmax ----
        float rmax0 = -1e30f, rmax1 = -1e30f;
        #pragma unroll
        for (int nt = 0; nt < 8; nt++) {
            rmax0 = fmaxf(rmax0, fmaxf(s[nt][0], s[nt][1]));
            rmax1 = fmaxf(rmax1, fmaxf(s[nt][2], s[nt][3]));
        }
        rmax0 = fmaxf(rmax0, __shfl_xor_sync(0xffffffffu, rmax0, 1));
        rmax0 = fmaxf(rmax0, __shfl_xor_sync(0xffffffffu, rmax0, 2));
        rmax1 = fmaxf(rmax1, __shfl_xor_sync(0xffffffffu, rmax1, 1));
        rmax1 = fmaxf(rmax1, __shfl_xor_sync(0xffffffffu, rmax1, 2));

        const float mn0 = fmaxf(m0, rmax0);
        const float mn1 = fmaxf(m1, rmax1);
        const float al0 = __expf(m0 - mn0);
        const float al1 = __expf(m1 - mn1);
        m0 = mn0; m1 = mn1;

        float rs0 = 0.f, rs1 = 0.f;
        {
            uint32_t* ps0 = (uint32_t*)Ps + (size_t)(w * 16 + g) * 36 + tig;
            uint32_t* ps1 = ps0 + 8 * 36;
            #pragma unroll
            for (int nt = 0; nt < 8; nt++) {
                const __half2 h0 = __floats2half2_rn(__expf(s[nt][0] - mn0), __expf(s[nt][1] - mn0));
                const __half2 h1 = __floats2half2_rn(__expf(s[nt][2] - mn1), __expf(s[nt][3] - mn1));
                const float2 f0 = __half22float2(h0);
                const float2 f1 = __half22float2(h1);
                rs0 += f0.x + f0.y; rs1 += f1.x + f1.y;
                ps0[nt * 4] = *(const uint32_t*)&h0;
                ps1[nt * 4] = *(const uint32_t*)&h1;
            }
        }
        rs0 += __shfl_xor_sync(0xffffffffu, rs0, 1);
        rs0 += __shfl_xor_sync(0xffffffffu, rs0, 2);
        rs1 += __shfl_xor_sync(0xffffffffu, rs1, 1);
        rs1 += __shfl_xor_sync(0xffffffffu, rs1, 2);
        l0 = l0 * al0 + rs0;
        l1 = l1 * al1 + rs1;

        #pragma unroll
        for (int nt = 0; nt < 8; nt++) {
            o[nt][0] *= al0; o[nt][1] *= al0;
            o[nt][2] *= al1; o[nt][3] *= al1;
        }
        __syncwarp();

        // ---- O += P @ V ----
        {
            const uint32_t pBase = psBase + (uint32_t)(w * 16) * 144 + aRow;
            const uint32_t vTile = vtsBase + (uint32_t)((t & 1) * V_TILE_HALVES) * 2u + bRow;
            #pragma unroll
            for (int ks = 0; ks < 4; ks++) {
                const uint32_t kb = (uint32_t)(ks * 32);
                uint32_t a[4];
                ldmatrix_x4(a, pBase + kb);
                #pragma unroll
                for (int nt = 0; nt < 8; nt++) {
                    uint32_t bfr[2];
                    ldmatrix_x2(bfr, vTile + (uint32_t)(nt * 8) * 144 + kb);
                    mma_f16_16x8x16(o[nt], a, bfr);
                }
            }
        }
        __syncwarp();
    }

    // ---- epilogue ----
    {
        const float i0 = 1.0f / l0, i1 = 1.0f / l1;
        const int r0 = qt * 128 + w * 16 + g;
        __half* ob0 = out + ((size_t)(b * SEQ + r0)) * DM + h * DK + 2 * tig;
        __half* ob1 = ob0 + 8 * DM;
        #pragma unroll
        for (int nt = 0; nt < 8; nt++) {
            *(uint32_t*)(ob0 + nt * 8) = pack_h2(o[nt][0] * i0, o[nt][1] * i0);
            *(uint32_t*)(ob1 + nt * 8) = pack_h2(o[nt][2] * i1, o[nt][3] * i1);
        }
    }
}

// ---------------- host launcher ----------------
extern "C" void kernel_launch(void* const* d_in, const int* in_sizes, int n_in,
                              void* d_out, int out_size)
{
    (void)in_sizes; (void)n_in; (void)out_size;
    const float* x     = (const float*)d_in[0];
    const float* Wq    = (const float*)d_in[1];
    const float* bq    = (const float*)d_in[2];
    const float* Wk    = (const float*)d_in[3];
    const float* bk    = (const float*)d_in[4];
    const float* Wv    = (const float*)d_in[5];
    const float* bv    = (const float*)d_in[6];
    const float* Wo    = (const float*)d_in[7];
    const float* bo    = (const float*)d_in[8];
    const float* ln1_g = (const float*)d_in[9];
    const float* ln1_b = (const float*)d_in[10];
    const float* W1    = (const float*)d_in[11];
    const float* b1    = (const float*)d_in[12];
    const float* W2    = (const float*)d_in[13];
    const float* b2    = (const float*)d_in[14];
    const float* ln2_g = (const float*)d_in[15];
    const float* ln2_b = (const float*)d_in[16];
    float* out = (float*)d_out;

    __half *h, *qkv, *vt, *ctx, *h2, *ff, *wqkvT, *woT, *w1T, *w2T;
    float *x1, *bqkv;
    cudaGetSymbolAddress((void**)&h,     g_h);
    cudaGetSymbolAddress((void**)&qkv,   g_qkv);
    cudaGetSymbolAddress((void**)&vt,    g_vt);
    cudaGetSymbolAddress((void**)&ctx,   g_ctx);
    cudaGetSymbolAddress((void**)&x1,    g_x1);
    cudaGetSymbolAddress((void**)&h2,    g_h2);
    cudaGetSymbolAddress((void**)&ff,    g_ff);
    cudaGetSymbolAddress((void**)&wqkvT, g_wqkvT);
    cudaGetSymbolAddress((void**)&bqkv,  g_bqkv);
    cudaGetSymbolAddress((void**)&woT,   g_woT);
    cudaGetSymbolAddress((void**)&w1T,   g_w1T);
    cudaGetSymbolAddress((void**)&w2T,   g_w2T);

    cudaFuncSetAttribute(attn_f16_kernel, cudaFuncAttributeMaxDynamicSharedMemorySize, ATTN_SMEM);
    cudaFuncSetAttribute(gemm_f16<0,1>, cudaFuncAttributeMaxDynamicSharedMemorySize, GEMM_SMEM_BYTES);
    cudaFuncSetAttribute(gemm_f16<1,0>, cudaFuncAttributeMaxDynamicSharedMemorySize, GEMM_SMEM_BYTES);
    cudaFuncSetAttribute(gemm_f16<2,1>, cudaFuncAttributeMaxDynamicSharedMemorySize, GEMM_SMEM_BYTES);

    const dim3 tB(32, 8);
    const dim3 gQKV(QLD / BN, TOK / BM);
    const dim3 gProj(DM / BN, TOK / BM);
    const dim3 gFF1(DFF / BN, TOK / BM);

    // launch 0: LN1 -> fp16 (depends only on x)
    ln_kernel<<<TOK, 256>>>(x, ln1_g, ln1_b, h);
    // launch 1: prep QKV weights + bias
    prep1_kernel<<<3075, tB>>>(Wq, Wk, Wv, bq, bk, bv, wqkvT, bqkv);
    // launch 2: prep Wo/W1/W2
    prep2_kernel<<<9216, tB>>>(Wo, W1, W2, woT, w1T, w2T);
    // launch 3 (ncu capture target): fused qkv projection (fp16 out)
    gemm_f16<0,1><<<gQKV, 256, GEMM_SMEM_BYTES>>>(h, wqkvT, bqkv, nullptr, qkv, TOK, QLD, DM);
    // launch 4: V transpose
    vtrans_kernel<<<dim3(SEQ / 32, DK / 32, NH * BATCH), tB>>>(qkv, vt);
    // launch 5: flash attention
    attn_f16_kernel<<<dim3(SEQ / 128, NH, BATCH), 256, ATTN_SMEM>>>(qkv, vt, ctx);
    // launch 6: x1 = x + ctx @ Wo + bo (fp32 out)
    gemm_f16<1,0><<<gProj, 256, GEMM_SMEM_BYTES>>>(ctx, woT, bo, x, x1, TOK, DM, DM);
    // launch 7: LN2 -> fp16
    ln_kernel<<<TOK, 256>>>(x1, ln2_g, ln2_b, h2);
    // launch 8: ff = gelu(h2 @ W1 + b1) (fp16 out)
    gemm_f16<2,1><<<gFF1, 256, GEMM_SMEM_BYTES>>>(h2, w1T, b1, nullptr, ff, TOK, DFF, DM);
    // launch 9: out = x1 + ff @ W2 + b2 (fp32 out)
    gemm_f16<1,0><<<gProj, 256, GEMM_SMEM_BYTES>>>(ff, w2T, b2, x1, out, TOK, DM, DFF);
}

// round 10
// speedup vs baseline: 7.3954x; 1.0217x over previous
#include <cuda_runtime.h>
#include <cuda_fp16.h>
#include <math.h>
#include <stdint.h>

#define TOK   8192
#define DM    1024
#define DFF   4096
#define NH    16
#define DK    64
#define SEQ   2048
#define BATCH 4
#define QLD   (3 * DM)

// ---------------- scratch ----------------
__device__ __half g_h   [TOK * DM];
__device__ __half g_qkv [TOK * QLD];
__device__ __half g_vt  [DM * TOK];            // [(h*DK+dk)][b*SEQ+s]
__device__ __half g_ctx [TOK * DM];
__device__ float  g_x1  [TOK * DM];
__device__ __half g_h2  [TOK * DM];
__device__ __half g_ff  [TOK * DFF];
// fp16 weights, transposed to [N][K]
__device__ __half g_wqkvT[QLD * DM];
__device__ float  g_bqkv [QLD];
__device__ __half g_woT  [DM * DM];
__device__ __half g_w1T  [DFF * DM];
__device__ __half g_w2T  [DM * DFF];

// ---------------- helpers ----------------
__device__ __forceinline__ uint32_t smem_u32(const void* p) {
    uint32_t a;
    asm("{ .reg .u64 t; cvta.to.shared.u64 t, %1; cvt.u32.u64 %0, t; }" : "=r"(a) : "l"(p));
    return a;
}
__device__ __forceinline__ void cp_async16(uint32_t dst, const void* src) {
    asm volatile("cp.async.cg.shared.global [%0], [%1], 16;" :: "r"(dst), "l"(src));
}
__device__ __forceinline__ void cp_commit() {
    asm volatile("cp.async.commit_group;" ::: "memory");
}
__device__ __forceinline__ void mma_f16_16x8x16(float* d, const uint32_t* a, const uint32_t* b) {
    asm volatile(
        "mma.sync.aligned.m16n8k16.row.col.f32.f16.f16.f32 "
        "{%0,%1,%2,%3}, {%4,%5,%6,%7}, {%8,%9}, {%0,%1,%2,%3};"
        : "+f"(d[0]), "+f"(d[1]), "+f"(d[2]), "+f"(d[3])
        : "r"(a[0]), "r"(a[1]), "r"(a[2]), "r"(a[3]), "r"(b[0]), "r"(b[1]));
}
__device__ __forceinline__ void ldmatrix_x4(uint32_t* r, uint32_t addr) {
    asm volatile("ldmatrix.sync.aligned.m8n8.x4.shared.b16 {%0,%1,%2,%3}, [%4];"
        : "=r"(r[0]), "=r"(r[1]), "=r"(r[2]), "=r"(r[3]) : "r"(addr));
}
__device__ __forceinline__ uint32_t pack_h2(float x, float y) {
    __half2 h = __floats2half2_rn(x, y);
    return *(uint32_t*)&h;
}

// ---------------- prep part 1: QKV weights + bias ----------------
__global__ void __launch_bounds__(256) prep1_kernel(
    const float* __restrict__ Wq, const float* __restrict__ Wk, const float* __restrict__ Wv,
    const float* __restrict__ bq, const float* __restrict__ bk, const float* __restrict__ bv,
    __half* __restrict__ wqkvT, float* __restrict__ bqkv)
{
    const int id = blockIdx.x;
    const int tx = threadIdx.x, ty = threadIdx.y;
    if (id >= 3072) {
        const int which = id - 3072;
        const float* src = which == 0 ? bq : (which == 1 ? bk : bv);
        const int t = ty * 32 + tx;
        ((float4*)bqkv)[which * 256 + t] = ((const float4*)src)[t];
        return;
    }
    const int m = id >> 10, lid = id & 1023;
    const float* in = m == 0 ? Wq : (m == 1 ? Wk : Wv);
    __half* out = wqkvT + (size_t)m * DM * DM;
    const int c0 = (lid & 31) * 32, r0 = (lid >> 5) * 32;
    __shared__ float tile[32][33];
    #pragma unroll
    for (int i = ty; i < 32; i += 8)
        tile[i][tx] = in[(size_t)(r0 + i) * DM + c0 + tx];
    __syncthreads();
    #pragma unroll
    for (int i = ty; i < 32; i += 8)
        out[(size_t)(c0 + i) * DM + r0 + tx] = __float2half_rn(tile[tx][i]);
}

// ---------------- prep part 2: Wo/W1/W2 ----------------
__global__ void __launch_bounds__(256) prep2_kernel(
    const float* __restrict__ Wo, const float* __restrict__ W1, const float* __restrict__ W2,
    __half* __restrict__ woT, __half* __restrict__ w1T, __half* __restrict__ w2T)
{
    const int id = blockIdx.x;
    const int tx = threadIdx.x, ty = threadIdx.y;
    const float* in; __half* out; int R, C, lid;
    if (id < 1024)      { lid = id;        in = Wo; out = woT; R = DM;  C = DM;  }
    else if (id < 5120) { lid = id - 1024; in = W1; out = w1T; R = DM;  C = DFF; }
    else                { lid = id - 5120; in = W2; out = w2T; R = DFF; C = DM;  }
    const int tilesx = C / 32;
    const int c0 = (lid % tilesx) * 32, r0 = (lid / tilesx) * 32;
    __shared__ float tile[32][33];
    #pragma unroll
    for (int i = ty; i < 32; i += 8)
        tile[i][tx] = in[(size_t)(r0 + i) * C + c0 + tx];
    __syncthreads();
    #pragma unroll
    for (int i = ty; i < 32; i += 8)
        out[(size_t)(c0 + i) * R + r0 + tx] = __float2half_rn(tile[tx][i]);
}

// ---------------- V transpose (fp16) ----------------
__global__ void __launch_bounds__(256) vtrans_kernel(const __half* __restrict__ in,
                                                     __half* __restrict__ out)
{
    __shared__ __half tile[32][33];
    const int s0 = blockIdx.x * 32;
    const int d0 = blockIdx.y * 32;
    const int h  = blockIdx.z & (NH - 1);
    const int b  = blockIdx.z >> 4;
    const int tx = threadIdx.x, ty = threadIdx.y;

    const __half* ip = in + ((size_t)(b * SEQ + s0)) * QLD + 2 * DM + h * DK + d0;
    #pragma unroll
    for (int i = ty; i < 32; i += 8)
        tile[i][tx] = ip[(size_t)i * QLD + tx];
    __syncthreads();
    __half* op = out + ((size_t)(h * DK + d0)) * (BATCH * SEQ) + (size_t)b * SEQ + s0;
    #pragma unroll
    for (int i = ty; i < 32; i += 8)
        op[(size_t)i * (BATCH * SEQ) + tx] = tile[tx][i];
}

// ---------------- LayerNorm: fp32 in, fp16 out ----------------
__global__ void __launch_bounds__(256) ln_kernel(const float* __restrict__ x,
                                                 const float* __restrict__ g,
                                                 const float* __restrict__ b,
                                                 __half* __restrict__ out)
{
    const int row = blockIdx.x;
    const int tid = threadIdx.x;
    const float4 v = ((const float4*)(x + (size_t)row * DM))[tid];

    float s  = v.x + v.y + v.z + v.w;
    float ss = v.x * v.x + v.y * v.y + v.z * v.z + v.w * v.w;
    #pragma unroll
    for (int o = 16; o; o >>= 1) {
        s  += __shfl_xor_sync(0xffffffffu, s,  o);
        ss += __shfl_xor_sync(0xffffffffu, ss, o);
    }
    __shared__ float sb[8], sb2[8];
    if ((tid & 31) == 0) { sb[tid >> 5] = s; sb2[tid >> 5] = ss; }
    __syncthreads();
    float ts = 0.f, ts2 = 0.f;
    #pragma unroll
    for (int i = 0; i < 8; i++) { ts += sb[i]; ts2 += sb2[i]; }

    const float mu  = ts * (1.0f / DM);
    const float var = ts2 * (1.0f / DM) - mu * mu;
    const float inv = rsqrtf(var + 1e-5f);

    const float4 gg = ((const float4*)g)[tid];
    const float4 bb = ((const float4*)b)[tid];
    uint32_t p0 = pack_h2((v.x - mu) * inv * gg.x + bb.x, (v.y - mu) * inv * gg.y + bb.y);
    uint32_t p1 = pack_h2((v.z - mu) * inv * gg.z + bb.z, (v.w - mu) * inv * gg.w + bb.w);
    uint2 o; o.x = p0; o.y = p1;
    ((uint2*)(out + (size_t)row * DM))[tid] = o;
}

// ---------------- fp16 GEMM: 128x64 tile, warp 32x32, 2-stage, 3 CTAs/SM ----------------
__device__ __forceinline__ float gelu_exact(float v) {
    return 0.5f * v * (1.0f + erff(v * 0.70710678118654752440f));
}

#define BM 128
#define BN 64
#define BKH 64
#define STAGES 2
#define TSH 72                          // halves per smem row = 144 bytes
#define A_TILE_HALVES (BM * TSH)        // 9216
#define B_TILE_HALVES (BN * TSH)        // 4608
#define STAGE_BYTES ((A_TILE_HALVES + B_TILE_HALVES) * 2)   // 27648
#define GEMM_SMEM_BYTES (STAGES * STAGE_BYTES)               // 55296; x3 CTA = 165888

template <int EPI, int OUTH>
__global__ void __launch_bounds__(256, 3) gemm_f16(
    const __half* __restrict__ A, const __half* __restrict__ BT,
    const float* __restrict__ bias, const float* __restrict__ res,
    void* __restrict__ Cv, int M, int N, int K)
{
    extern __shared__ __half smh[];
    const uint32_t sbase = smem_u32(smh);

    const int tid = threadIdx.x;
    const int wid = tid >> 5;
    const int lane = tid & 31;
    const int g = lane >> 2;
    const int tig = lane & 3;
    const int wm = wid & 3;          // 0..3 (32-row quarters)
    const int wn = wid >> 2;         // 0..1 (32-col halves)

    // ldmatrix lane-address offsets (bytes)
    const uint32_t aRow  = (uint32_t)((lane & 15) * 144 + (lane >> 4) * 16);
    const uint32_t bRow2 = (uint32_t)((lane & 7) * 144 + ((lane >> 3) & 1) * 16 + (lane >> 4) * (8 * 144));

    const int n0 = blockIdx.x * BN;
    const int m0 = blockIdx.y * BM;
    const int NT = K / BKH;

    float acc[2][4][4];
    #pragma unroll
    for (int mt = 0; mt < 2; mt++)
        #pragma unroll
        for (int nt = 0; nt < 4; nt++)
            #pragma unroll
            for (int e = 0; e < 4; e++) acc[mt][nt][e] = 0.f;

    auto load_stage = [&](int st, int t) {
        const uint32_t aoff = sbase + (uint32_t)st * STAGE_BYTES;
        const uint32_t boff = aoff + A_TILE_HALVES * 2;
        #pragma unroll
        for (int i = 0; i < 6; i++) {
            const int idx = i * 256 + tid;          // 0..1535
            if (idx < 1024) {
                const int row = idx >> 3, ch = idx & 7;
                cp_async16(aoff + (uint32_t)(row * TSH + ch * 8) * 2u,
                           A + (size_t)(m0 + row) * K + (size_t)t * BKH + ch * 8);
            } else {
                const int j = idx - 1024;
                const int row = j >> 3, ch = j & 7;
                cp_async16(boff + (uint32_t)(row * TSH + ch * 8) * 2u,
                           BT + (size_t)(n0 + row) * K + (size_t)t * BKH + ch * 8);
            }
        }
    };

    load_stage(0, 0);
    cp_commit();

    for (int t = 0; t < NT; t++) {
        asm volatile("cp.async.wait_group 0;" ::: "memory");
        __syncthreads();

        if (t + 1 < NT) { load_stage((t + 1) & 1, t + 1); cp_commit(); }

        const int st = t & 1;
        const uint32_t aBase = sbase + (uint32_t)st * STAGE_BYTES + (uint32_t)(wm * 32) * 144 + aRow;
        const uint32_t bBase = sbase + (uint32_t)st * STAGE_BYTES + A_TILE_HALVES * 2
                             + (uint32_t)(wn * 32) * 144 + bRow2;

        #pragma unroll
        for (int ks = 0; ks < 4; ks++) {
            const uint32_t kb = (uint32_t)(ks * 32);
            uint32_t afr[2][4], bfr[2][4];
            #pragma unroll
            for (int mt = 0; mt < 2; mt++)
                ldmatrix_x4(afr[mt], aBase + (uint32_t)(mt * 16) * 144 + kb);
            #pragma unroll
            for (int p = 0; p < 2; p++)
                ldmatrix_x4(bfr[p], bBase + (uint32_t)(p * 16) * 144 + kb);
            #pragma unroll
            for (int mt = 0; mt < 2; mt++)
                #pragma unroll
                for (int nt = 0; nt < 4; nt++)
                    mma_f16_16x8x16(acc[mt][nt], afr[mt], &bfr[nt >> 1][(nt & 1) * 2]);
        }
    }

    #pragma unroll
    for (int mt = 0; mt < 2; mt++) {
        const int r0 = m0 + wm * 32 + mt * 16 + g;
        const float* rr0 = (EPI == 1) ? (res + (size_t)r0 * N) : nullptr;
        const float* rr1 = (EPI == 1) ? (res + (size_t)(r0 + 8) * N) : nullptr;
        #pragma unroll
        for (int nt = 0; nt < 4; nt++) {
            const int col = n0 + wn * 32 + nt * 8 + 2 * tig;
            const float bx = bias[col], by = bias[col + 1];
            float v0 = acc[mt][nt][0] + bx, v1 = acc[mt][nt][1] + by;
            float v2 = acc[mt][nt][2] + bx, v3 = acc[mt][nt][3] + by;
            if (EPI == 2) {
                v0 = gelu_exact(v0); v1 = gelu_exact(v1);
                v2 = gelu_exact(v2); v3 = gelu_exact(v3);
            }
            if (EPI == 1) {
                v0 += rr0[col]; v1 += rr0[col + 1];
                v2 += rr1[col]; v3 += rr1[col + 1];
            }
            if (OUTH) {
                __half* C = (__half*)Cv;
                *(uint32_t*)(C + (size_t)r0 * N + col)       = pack_h2(v0, v1);
                *(uint32_t*)(C + (size_t)(r0 + 8) * N + col) = pack_h2(v2, v3);
            } else {
                float* C = (float*)Cv;
                *(float2*)(C + (size_t)r0 * N + col)       = make_float2(v0, v1);
                *(float2*)(C + (size_t)(r0 + 8) * N + col) = make_float2(v2, v3);
            }
        }
    }
}

// ---------------- fp16 flash attention: KV tile 64, 2 CTAs/SM, paired-x4 B loads ----------------
#define KV 64
#define KSH 72
#define VSH 72
#define PSH 72
#define K_TILE_HALVES (KV * KSH)
#define V_TILE_HALVES (DK * VSH)
#define P_HALVES (128 * PSH)
#define ATTN_SMEM ((2 * K_TILE_HALVES + 2 * V_TILE_HALVES + P_HALVES) * 2)

__global__ void __launch_bounds__(256, 2) attn_f16_kernel(const __half* __restrict__ qkv,
                                                          const __half* __restrict__ vt,
                                                          __half* __restrict__ out)
{
    extern __shared__ __half smh[];
    __half* Ps = smh + 2 * K_TILE_HALVES + 2 * V_TILE_HALVES;
    const uint32_t sbase = smem_u32(smh);
    const uint32_t vtsBase = sbase + 2 * K_TILE_HALVES * 2;
    const uint32_t psBase  = vtsBase + 2 * V_TILE_HALVES * 2;

    const int tid = threadIdx.x;
    const int w = tid >> 5;
    const int lane = tid & 31;
    const int g = lane >> 2;
    const int tig = lane & 3;

    const uint32_t aRow  = (uint32_t)((lane & 15) * 144 + (lane >> 4) * 16);
    const uint32_t bRow2 = (uint32_t)((lane & 7) * 144 + ((lane >> 3) & 1) * 16 + (lane >> 4) * (8 * 144));

    const int qt = blockIdx.x, h = blockIdx.y, b = blockIdx.z;

    // ---- Q fragments (scaled by 1/8, exact) ----
    uint32_t qa[4][4];
    {
        const __half* qb = qkv + ((size_t)(b * SEQ + qt * 128 + w * 16)) * QLD + h * DK;
        const __half2 sc = __floats2half2_rn(0.125f, 0.125f);
        #pragma unroll
        for (int ks = 0; ks < 4; ks++) {
            const int c = ks * 16 + 2 * tig;
            __half2 a0 = __hmul2(*(const __half2*)(qb + (size_t)g * QLD + c), sc);
            __half2 a1 = __hmul2(*(const __half2*)(qb + (size_t)(g + 8) * QLD + c), sc);
            __half2 a2 = __hmul2(*(const __half2*)(qb + (size_t)g * QLD + c + 8), sc);
            __half2 a3 = __hmul2(*(const __half2*)(qb + (size_t)(g + 8) * QLD + c + 8), sc);
            qa[ks][0] = *(uint32_t*)&a0; qa[ks][1] = *(uint32_t*)&a1;
            qa[ks][2] = *(uint32_t*)&a2; qa[ks][3] = *(uint32_t*)&a3;
        }
    }

    float o[8][4];
    #pragma unroll
    for (int nt = 0; nt < 8; nt++)
        #pragma unroll
        for (int e = 0; e < 4; e++) o[nt][e] = 0.f;
    float m0 = -1e30f, m1 = -1e30f, l0 = 0.f, l1 = 0.f;

    auto load_kv = [&](int t, int buf) {
        const uint32_t kdst = sbase + (uint32_t)(buf * K_TILE_HALVES) * 2u;
        const uint32_t vdst = vtsBase + (uint32_t)(buf * V_TILE_HALVES) * 2u;
        const __half* ksrc = qkv + ((size_t)(b * SEQ + t * KV)) * QLD + DM + h * DK;
        const __half* vsrc = vt + (size_t)(h * DK) * (BATCH * SEQ) + (size_t)b * SEQ + (size_t)t * KV;
        const int kr0 = tid >> 3, kc = tid & 7;
        cp_async16(kdst + (uint32_t)(kr0 * KSH + kc * 8) * 2u,
                   ksrc + (size_t)kr0 * QLD + kc * 8);
        cp_async16(kdst + (uint32_t)((kr0 + 32) * KSH + kc * 8) * 2u,
                   ksrc + (size_t)(kr0 + 32) * QLD + kc * 8);
        cp_async16(vdst + (uint32_t)(kr0 * VSH + kc * 8) * 2u,
                   vsrc + (size_t)kr0 * (BATCH * SEQ) + kc * 8);
        cp_async16(vdst + (uint32_t)((kr0 + 32) * VSH + kc * 8) * 2u,
                   vsrc + (size_t)(kr0 + 32) * (BATCH * SEQ) + kc * 8);
    };

    load_kv(0, 0);
    cp_commit();

    const int NKV = SEQ / KV;
    for (int t = 0; t < NKV; t++) {
        asm volatile("cp.async.wait_group 0;" ::: "memory");
        __syncthreads();
        if (t + 1 < NKV) { load_kv(t + 1, (t + 1) & 1); cp_commit(); }

        // ---- S = Q @ K^T (paired x4 K loads) ----
        float s[8][4];
        #pragma unroll
        for (int nt = 0; nt < 8; nt++)
            #pragma unroll
            for (int e = 0; e < 4; e++) s[nt][e] = 0.f;
        {
            const uint32_t kTile = sbase + (uint32_t)((t & 1) * K_TILE_HALVES) * 2u + bRow2;
            #pragma unroll
            for (int ks = 0; ks < 4; ks++) {
                const uint32_t kb = (uint32_t)(ks * 32);
                #pragma unroll
                for (int p = 0; p < 4; p++) {
                    uint32_t bp[4];
                    ldmatrix_x4(bp, kTile + (uint32_t)(p * 16) * 144 + kb);
                    mma_f16_16x8x16(s[2 * p],     qa[ks], bp);
                    mma_f16_16x8x16(s[2 * p + 1], qa[ks], bp + 2);
                }
            }
        }

        // ---- online softmax ----
        float rmax0 = -1e30f, rmax1 = -1e30f;
        #pragma unroll
        for (int nt = 0; nt < 8; nt++) {
            rmax0 = fmaxf(rmax0, fmaxf(s[nt][0], s[nt][1]));
            rmax1 = fmaxf(rmax1, fmaxf(s[nt][2], s[nt][3]));
        }
        rmax0 = fmaxf(rmax0, __shfl_xor_sync(0xffffffffu, rmax0, 1));
        rmax0 = fmaxf(rmax0, __shfl_xor_sync(0xffffffffu, rmax0, 2));
        rmax1 = fmaxf(rmax1, __shfl_xor_sync(0xffffffffu, rmax1, 1));
        rmax1 = fmaxf(rmax1, __shfl_xor_sync(0xffffffffu, rmax1, 2));

        const float mn0 = fmaxf(m0, rmax0);
        const float mn1 = fmaxf(m1, rmax1);
        const float al0 = __expf(m0 - mn0);
        const float al1 = __expf(m1 - mn1);
        m0 = mn0; m1 = mn1;

        float rs0 = 0.f, rs1 = 0.f;
        {
            uint32_t* ps0 = (uint32_t*)Ps + (size_t)(w * 16 + g) * 36 + tig;
            uint32_t* ps1 = ps0 + 8 * 36;
            #pragma unroll
            for (int nt = 0; nt < 8; nt++) {
                const __half2 h0 = __floats2half2_rn(__expf(s[nt][0] - mn0), __expf(s[nt][1] - mn0));
                const __half2 h1 = __floats2half2_rn(__expf(s[nt][2] - mn1), __expf(s[nt][3] - mn1));
                const float2 f0 = __half22float2(h0);
                const float2 f1 = __half22float2(h1);
                rs0 += f0.x + f0.y; rs1 += f1.x + f1.y;
                ps0[nt * 4] = *(const uint32_t*)&h0;
                ps1[nt * 4] = *(const uint32_t*)&h1;
            }
        }
        rs0 += __shfl_xor_sync(0xffffffffu, rs0, 1);
        rs0 += __shfl_xor_sync(0xffffffffu, rs0, 2);
        rs1 += __shfl_xor_sync(0xffffffffu, rs1, 1);
        rs1 += __shfl_xor_sync(0xffffffffu, rs1, 2);
        l0 = l0 * al0 + rs0;
        l1 = l1 * al1 + rs1;

        #pragma unroll
        for (int nt = 0; nt < 8; nt++) {
            o[nt][0] *= al0; o[nt][1] *= al0;
            o[nt][2] *= al1; o[nt][3] *= al1;
        }
        __syncwarp();

        // ---- O += P @ V (paired x4 V loads) ----
        {
            const uint32_t pBase = psBase + (uint32_t)(w * 16) * 144 + aRow;
            const uint32_t vTile = vtsBase + (uint32_t)((t & 1) * V_TILE_HALVES) * 2u + bRow2;
            #pragma unroll
            for (int ks = 0; ks < 4; ks++) {
                const uint32_t kb = (uint32_t)(ks * 32);
                uint32_t a[4];
                ldmatrix_x4(a, pBase + kb);
                #pragma unroll
                for (int p = 0; p < 4; p++) {
                    uint32_t bp[4];
                    ldmatrix_x4(bp, vTile + (uint32_t)(p * 16) * 144 + kb);
                    mma_f16_16x8x16(o[2 * p],     a, bp);
                    mma_f16_16x8x16(o[2 * p + 1], a, bp + 2);
                }
            }
        }
        __syncwarp();
    }

    // ---- epilogue ----
    {
        const float i0 = 1.0f / l0, i1 = 1.0f / l1;
        const int r0 = qt * 128 + w * 16 + g;
        __half* ob0 = out + ((size_t)(b * SEQ + r0)) * DM + h * DK + 2 * tig;
        __half* ob1 = ob0 + 8 * DM;
        #pragma unroll
        for (int nt = 0; nt < 8; nt++) {
            *(uint32_t*)(ob0 + nt * 8) = pack_h2(o[nt][0] * i0, o[nt][1] * i0);
            *(uint32_t*)(ob1 + nt * 8) = pack_h2(o[nt][2] * i1, o[nt][3] * i1);
        }
    }
}

// ---------------- host launcher ----------------
extern "C" void kernel_launch(void* const* d_in, const int* in_sizes, int n_in,
                              void* d_out, int out_size)
{
    (void)in_sizes; (void)n_in; (void)out_size;
    const float* x     = (const float*)d_in[0];
    const float* Wq    = (const float*)d_in[1];
    const float* bq    = (const float*)d_in[2];
    const float* Wk    = (const float*)d_in[3];
    const float* bk    = (const float*)d_in[4];
    const float* Wv    = (const float*)d_in[5];
    const float* bv    = (const float*)d_in[6];
    const float* Wo    = (const float*)d_in[7];
    const float* bo    = (const float*)d_in[8];
    const float* ln1_g = (const float*)d_in[9];
    const float* ln1_b = (const float*)d_in[10];
    const float* W1    = (const float*)d_in[11];
    const float* b1    = (const float*)d_in[12];
    const float* W2    = (const float*)d_in[13];
    const float* b2    = (const float*)d_in[14];
    const float* ln2_g = (const float*)d_in[15];
    const float* ln2_b = (const float*)d_in[16];
    float* out = (float*)d_out;

    __half *h, *qkv, *vt, *ctx, *h2, *ff, *wqkvT, *woT, *w1T, *w2T;
    float *x1, *bqkv;
    cudaGetSymbolAddress((void**)&h,     g_h);
    cudaGetSymbolAddress((void**)&qkv,   g_qkv);
    cudaGetSymbolAddress((void**)&vt,    g_vt);
    cudaGetSymbolAddress((void**)&ctx,   g_ctx);
    cudaGetSymbolAddress((void**)&x1,    g_x1);
    cudaGetSymbolAddress((void**)&h2,    g_h2);
    cudaGetSymbolAddress((void**)&ff,    g_ff);
    cudaGetSymbolAddress((void**)&wqkvT, g_wqkvT);
    cudaGetSymbolAddress((void**)&bqkv,  g_bqkv);
    cudaGetSymbolAddress((void**)&woT,   g_woT);
    cudaGetSymbolAddress((void**)&w1T,   g_w1T);
    cudaGetSymbolAddress((void**)&w2T,   g_w2T);

    cudaFuncSetAttribute(attn_f16_kernel, cudaFuncAttributeMaxDynamicSharedMemorySize, ATTN_SMEM);
    cudaFuncSetAttribute(gemm_f16<0,1>, cudaFuncAttributeMaxDynamicSharedMemorySize, GEMM_SMEM_BYTES);
    cudaFuncSetAttribute(gemm_f16<1,0>, cudaFuncAttributeMaxDynamicSharedMemorySize, GEMM_SMEM_BYTES);
    cudaFuncSetAttribute(gemm_f16<2,1>, cudaFuncAttributeMaxDynamicSharedMemorySize, GEMM_SMEM_BYTES);

    const dim3 tB(32, 8);
    const dim3 gQKV(QLD / BN, TOK / BM);    // (48, 64)
    const dim3 gProj(DM / BN, TOK / BM);    // (16, 64)
    const dim3 gFF1(DFF / BN, TOK / BM);    // (64, 64)

    // launch 0: LN1 -> fp16
    ln_kernel<<<TOK, 256>>>(x, ln1_g, ln1_b, h);
    // launch 1: prep QKV weights + bias
    prep1_kernel<<<3075, tB>>>(Wq, Wk, Wv, bq, bk, bv, wqkvT, bqkv);
    // launch 2: prep Wo/W1/W2
    prep2_kernel<<<9216, tB>>>(Wo, W1, W2, woT, w1T, w2T);
    // launch 3 (ncu capture): fused qkv projection (fp16 out)
    gemm_f16<0,1><<<gQKV, 256, GEMM_SMEM_BYTES>>>(h, wqkvT, bqkv, nullptr, qkv, TOK, QLD, DM);
    // launch 4: V transpose
    vtrans_kernel<<<dim3(SEQ / 32, DK / 32, NH * BATCH), tB>>>(qkv, vt);
    // launch 5: flash attention
    attn_f16_kernel<<<dim3(SEQ / 128, NH, BATCH), 256, ATTN_SMEM>>>(qkv, vt, ctx);
    // launch 6: x1 = x + ctx @ Wo + bo (fp32 out)
    gemm_f16<1,0><<<gProj, 256, GEMM_SMEM_BYTES>>>(ctx, woT, bo, x, x1, TOK, DM, DM);
    // launch 7: LN2 -> fp16
    ln_kernel<<<TOK, 256>>>(x1, ln2_g, ln2_b, h2);
    // launch 8: ff = gelu(h2 @ W1 + b1) (fp16 out)
    gemm_f16<2,1><<<gFF1, 256, GEMM_SMEM_BYTES>>>(h2, w1T, b1, nullptr, ff, TOK, DFF, DM);
    // launch 9: out = x1 + ff @ W2 + b2 (fp32 out)
    gemm_f16<1,0><<<gProj, 256, GEMM_SMEM_BYTES>>>(ff, w2T, b2, x1, out, TOK, DM, DFF);
}

// round 11
// speedup vs baseline: 7.4112x; 1.0021x over previous
#include <cuda_runtime.h>
#include <cuda_fp16.h>
#include <math.h>
#include <stdint.h>

#define TOK   8192
#define DM    1024
#define DFF   4096
#define NH    16
#define DK    64
#define SEQ   2048
#define BATCH 4
#define QLD   (3 * DM)

// ---------------- scratch ----------------
__device__ __half g_h   [TOK * DM];
__device__ __half g_qkv [TOK * QLD];
__device__ __half g_ctx [TOK * DM];
__device__ float  g_x1  [TOK * DM];
__device__ __half g_h2  [TOK * DM];
__device__ __half g_ff  [TOK * DFF];
// fp16 weights, transposed to [N][K]
__device__ __half g_wqkvT[QLD * DM];
__device__ float  g_bqkv [QLD];
__device__ __half g_woT  [DM * DM];
__device__ __half g_w1T  [DFF * DM];
__device__ __half g_w2T  [DM * DFF];

// ---------------- helpers ----------------
__device__ __forceinline__ uint32_t smem_u32(const void* p) {
    uint32_t a;
    asm("{ .reg .u64 t; cvta.to.shared.u64 t, %1; cvt.u32.u64 %0, t; }" : "=r"(a) : "l"(p));
    return a;
}
__device__ __forceinline__ void cp_async16(uint32_t dst, const void* src) {
    asm volatile("cp.async.cg.shared.global [%0], [%1], 16;" :: "r"(dst), "l"(src));
}
__device__ __forceinline__ void cp_commit() {
    asm volatile("cp.async.commit_group;" ::: "memory");
}
__device__ __forceinline__ void mma_f16_16x8x16(float* d, const uint32_t* a, const uint32_t* b) {
    asm volatile(
        "mma.sync.aligned.m16n8k16.row.col.f32.f16.f16.f32 "
        "{%0,%1,%2,%3}, {%4,%5,%6,%7}, {%8,%9}, {%0,%1,%2,%3};"
        : "+f"(d[0]), "+f"(d[1]), "+f"(d[2]), "+f"(d[3])
        : "r"(a[0]), "r"(a[1]), "r"(a[2]), "r"(a[3]), "r"(b[0]), "r"(b[1]));
}
__device__ __forceinline__ void ldmatrix_x4(uint32_t* r, uint32_t addr) {
    asm volatile("ldmatrix.sync.aligned.m8n8.x4.shared.b16 {%0,%1,%2,%3}, [%4];"
        : "=r"(r[0]), "=r"(r[1]), "=r"(r[2]), "=r"(r[3]) : "r"(addr));
}
__device__ __forceinline__ void ldmatrix_x4_trans(uint32_t* r, uint32_t addr) {
    asm volatile("ldmatrix.sync.aligned.m8n8.x4.trans.shared.b16 {%0,%1,%2,%3}, [%4];"
        : "=r"(r[0]), "=r"(r[1]), "=r"(r[2]), "=r"(r[3]) : "r"(addr));
}
__device__ __forceinline__ uint32_t pack_h2(float x, float y) {
    __half2 h = __floats2half2_rn(x, y);
    return *(uint32_t*)&h;
}

// ---------------- prep part 1: QKV weights + bias ----------------
__global__ void __launch_bounds__(256) prep1_kernel(
    const float* __restrict__ Wq, const float* __restrict__ Wk, const float* __restrict__ Wv,
    const float* __restrict__ bq, const float* __restrict__ bk, const float* __restrict__ bv,
    __half* __restrict__ wqkvT, float* __restrict__ bqkv)
{
    const int id = blockIdx.x;
    const int tx = threadIdx.x, ty = threadIdx.y;
    if (id >= 3072) {
        const int which = id - 3072;
        const float* src = which == 0 ? bq : (which == 1 ? bk : bv);
        const int t = ty * 32 + tx;
        ((float4*)bqkv)[which * 256 + t] = ((const float4*)src)[t];
        return;
    }
    const int m = id >> 10, lid = id & 1023;
    const float* in = m == 0 ? Wq : (m == 1 ? Wk : Wv);
    __half* out = wqkvT + (size_t)m * DM * DM;
    const int c0 = (lid & 31) * 32, r0 = (lid >> 5) * 32;
    __shared__ float tile[32][33];
    #pragma unroll
    for (int i = ty; i < 32; i += 8)
        tile[i][tx] = in[(size_t)(r0 + i) * DM + c0 + tx];
    __syncthreads();
    #pragma unroll
    for (int i = ty; i < 32; i += 8)
        out[(size_t)(c0 + i) * DM + r0 + tx] = __float2half_rn(tile[tx][i]);
}

// ---------------- prep part 2: Wo/W1/W2 ----------------
__global__ void __launch_bounds__(256) prep2_kernel(
    const float* __restrict__ Wo, const float* __restrict__ W1, const float* __restrict__ W2,
    __half* __restrict__ woT, __half* __restrict__ w1T, __half* __restrict__ w2T)
{
    const int id = blockIdx.x;
    const int tx = threadIdx.x, ty = threadIdx.y;
    const float* in; __half* out; int R, C, lid;
    if (id < 1024)      { lid = id;        in = Wo; out = woT; R = DM;  C = DM;  }
    else if (id < 5120) { lid = id - 1024; in = W1; out = w1T; R = DM;  C = DFF; }
    else                { lid = id - 5120; in = W2; out = w2T; R = DFF; C = DM;  }
    const int tilesx = C / 32;
    const int c0 = (lid % tilesx) * 32, r0 = (lid / tilesx) * 32;
    __shared__ float tile[32][33];
    #pragma unroll
    for (int i = ty; i < 32; i += 8)
        tile[i][tx] = in[(size_t)(r0 + i) * C + c0 + tx];
    __syncthreads();
    #pragma unroll
    for (int i = ty; i < 32; i += 8)
        out[(size_t)(c0 + i) * R + r0 + tx] = __float2half_rn(tile[tx][i]);
}

// ---------------- LayerNorm: fp32 in, fp16 out ----------------
__global__ void __launch_bounds__(256) ln_kernel(const float* __restrict__ x,
                                                 const float* __restrict__ g,
                                                 const float* __restrict__ b,
                                                 __half* __restrict__ out)
{
    const int row = blockIdx.x;
    const int tid = threadIdx.x;
    const float4 v = ((const float4*)(x + (size_t)row * DM))[tid];

    float s  = v.x + v.y + v.z + v.w;
    float ss = v.x * v.x + v.y * v.y + v.z * v.z + v.w * v.w;
    #pragma unroll
    for (int o = 16; o; o >>= 1) {
        s  += __shfl_xor_sync(0xffffffffu, s,  o);
        ss += __shfl_xor_sync(0xffffffffu, ss, o);
    }
    __shared__ float sb[8], sb2[8];
    if ((tid & 31) == 0) { sb[tid >> 5] = s; sb2[tid >> 5] = ss; }
    __syncthreads();
    float ts = 0.f, ts2 = 0.f;
    #pragma unroll
    for (int i = 0; i < 8; i++) { ts += sb[i]; ts2 += sb2[i]; }

    const float mu  = ts * (1.0f / DM);
    const float var = ts2 * (1.0f / DM) - mu * mu;
    const float inv = rsqrtf(var + 1e-5f);

    const float4 gg = ((const float4*)g)[tid];
    const float4 bb = ((const float4*)b)[tid];
    uint32_t p0 = pack_h2((v.x - mu) * inv * gg.x + bb.x, (v.y - mu) * inv * gg.y + bb.y);
    uint32_t p1 = pack_h2((v.z - mu) * inv * gg.z + bb.z, (v.w - mu) * inv * gg.w + bb.w);
    uint2 o; o.x = p0; o.y = p1;
    ((uint2*)(out + (size_t)row * DM))[tid] = o;
}

// ---------------- fp16 GEMM: 128x64 tile, warp 32x32, 2-stage, 3 CTAs/SM ----------------
__device__ __forceinline__ float gelu_exact(float v) {
    return 0.5f * v * (1.0f + erff(v * 0.70710678118654752440f));
}

#define BM 128
#define BN 64
#define BKH 64
#define STAGES 2
#define TSH 72                          // halves per smem row = 144 bytes
#define A_TILE_HALVES (BM * TSH)
#define B_TILE_HALVES (BN * TSH)
#define STAGE_BYTES ((A_TILE_HALVES + B_TILE_HALVES) * 2)
#define GEMM_SMEM_BYTES (STAGES * STAGE_BYTES)

template <int EPI, int OUTH>
__global__ void __launch_bounds__(256, 3) gemm_f16(
    const __half* __restrict__ A, const __half* __restrict__ BT,
    const float* __restrict__ bias, const float* __restrict__ res,
    void* __restrict__ Cv, int M, int N, int K)
{
    extern __shared__ __half smh[];
    const uint32_t sbase = smem_u32(smh);

    const int tid = threadIdx.x;
    const int wid = tid >> 5;
    const int lane = tid & 31;
    const int g = lane >> 2;
    const int tig = lane & 3;
    const int wm = wid & 3;
    const int wn = wid >> 2;

    const uint32_t aRow  = (uint32_t)((lane & 15) * 144 + (lane >> 4) * 16);
    const uint32_t bRow2 = (uint32_t)((lane & 7) * 144 + ((lane >> 3) & 1) * 16 + (lane >> 4) * (8 * 144));

    const int n0 = blockIdx.x * BN;
    const int m0 = blockIdx.y * BM;
    const int NT = K / BKH;

    float acc[2][4][4];
    #pragma unroll
    for (int mt = 0; mt < 2; mt++)
        #pragma unroll
        for (int nt = 0; nt < 4; nt++)
            #pragma unroll
            for (int e = 0; e < 4; e++) acc[mt][nt][e] = 0.f;

    auto load_stage = [&](int st, int t) {
        const uint32_t aoff = sbase + (uint32_t)st * STAGE_BYTES;
        const uint32_t boff = aoff + A_TILE_HALVES * 2;
        #pragma unroll
        for (int i = 0; i < 6; i++) {
            const int idx = i * 256 + tid;
            if (idx < 1024) {
                const int row = idx >> 3, ch = idx & 7;
                cp_async16(aoff + (uint32_t)(row * TSH + ch * 8) * 2u,
                           A + (size_t)(m0 + row) * K + (size_t)t * BKH + ch * 8);
            } else {
                const int j = idx - 1024;
                const int row = j >> 3, ch = j & 7;
                cp_async16(boff + (uint32_t)(row * TSH + ch * 8) * 2u,
                           BT + (size_t)(n0 + row) * K + (size_t)t * BKH + ch * 8);
            }
        }
    };

    load_stage(0, 0);
    cp_commit();

    for (int t = 0; t < NT; t++) {
        asm volatile("cp.async.wait_group 0;" ::: "memory");
        __syncthreads();

        if (t + 1 < NT) { load_stage((t + 1) & 1, t + 1); cp_commit(); }

        const int st = t & 1;
        const uint32_t aBase = sbase + (uint32_t)st * STAGE_BYTES + (uint32_t)(wm * 32) * 144 + aRow;
        const uint32_t bBase = sbase + (uint32_t)st * STAGE_BYTES + A_TILE_HALVES * 2
                             + (uint32_t)(wn * 32) * 144 + bRow2;

        #pragma unroll
        for (int ks = 0; ks < 4; ks++) {
            const uint32_t kb = (uint32_t)(ks * 32);
            uint32_t afr[2][4], bfr[2][4];
            #pragma unroll
            for (int mt = 0; mt < 2; mt++)
                ldmatrix_x4(afr[mt], aBase + (uint32_t)(mt * 16) * 144 + kb);
            #pragma unroll
            for (int p = 0; p < 2; p++)
                ldmatrix_x4(bfr[p], bBase + (uint32_t)(p * 16) * 144 + kb);
            #pragma unroll
            for (int mt = 0; mt < 2; mt++)
                #pragma unroll
                for (int nt = 0; nt < 4; nt++)
                    mma_f16_16x8x16(acc[mt][nt], afr[mt], &bfr[nt >> 1][(nt & 1) * 2]);
        }
    }

    #pragma unroll
    for (int mt = 0; mt < 2; mt++) {
        const int r0 = m0 + wm * 32 + mt * 16 + g;
        const float* rr0 = (EPI == 1) ? (res + (size_t)r0 * N) : nullptr;
        const float* rr1 = (EPI == 1) ? (res + (size_t)(r0 + 8) * N) : nullptr;
        #pragma unroll
        for (int nt = 0; nt < 4; nt++) {
            const int col = n0 + wn * 32 + nt * 8 + 2 * tig;
            const float bx = bias[col], by = bias[col + 1];
            float v0 = acc[mt][nt][0] + bx, v1 = acc[mt][nt][1] + by;
            float v2 = acc[mt][nt][2] + bx, v3 = acc[mt][nt][3] + by;
            if (EPI == 2) {
                v0 = gelu_exact(v0); v1 = gelu_exact(v1);
                v2 = gelu_exact(v2); v3 = gelu_exact(v3);
            }
            if (EPI == 1) {
                v0 += rr0[col]; v1 += rr0[col + 1];
                v2 += rr1[col]; v3 += rr1[col + 1];
            }
            if (OUTH) {
                __half* C = (__half*)Cv;
                *(uint32_t*)(C + (size_t)r0 * N + col)       = pack_h2(v0, v1);
                *(uint32_t*)(C + (size_t)(r0 + 8) * N + col) = pack_h2(v2, v3);
            } else {
                float* C = (float*)Cv;
                *(float2*)(C + (size_t)r0 * N + col)       = make_float2(v0, v1);
                *(float2*)(C + (size_t)(r0 + 8) * N + col) = make_float2(v2, v3);
            }
        }
    }
}

// ---------------- fp16 flash attention: KV tile 64, 2 CTAs/SM, V via ldmatrix.trans ----------------
#define KV 64
#define KSH 72
#define VSH 72
#define PSH 72
#define K_TILE_HALVES (KV * KSH)
#define V_TILE_HALVES (KV * VSH)
#define P_HALVES (128 * PSH)
#define ATTN_SMEM ((2 * K_TILE_HALVES + 2 * V_TILE_HALVES + P_HALVES) * 2)

__global__ void __launch_bounds__(256, 2) attn_f16_kernel(const __half* __restrict__ qkv,
                                                          __half* __restrict__ out)
{
    extern __shared__ __half smh[];
    __half* Ps = smh + 2 * K_TILE_HALVES + 2 * V_TILE_HALVES;
    const uint32_t sbase = smem_u32(smh);
    const uint32_t vtsBase = sbase + 2 * K_TILE_HALVES * 2;
    const uint32_t psBase  = vtsBase + 2 * V_TILE_HALVES * 2;

    const int tid = threadIdx.x;
    const int w = tid >> 5;
    const int lane = tid & 31;
    const int g = lane >> 2;
    const int tig = lane & 3;

    const uint32_t aRow  = (uint32_t)((lane & 15) * 144 + (lane >> 4) * 16);
    const uint32_t bRow2 = (uint32_t)((lane & 7) * 144 + ((lane >> 3) & 1) * 16 + (lane >> 4) * (8 * 144));
    // trans-ldmatrix lane address: rows = k (s-dim), col pair select via lane>>4
    const uint32_t vRowT = (uint32_t)(((lane & 7) + ((lane >> 3) & 1) * 8) * 144 + (lane >> 4) * 16);

    const int qt = blockIdx.x, h = blockIdx.y, b = blockIdx.z;

    // ---- Q fragments (scaled by 1/8, exact) ----
    uint32_t qa[4][4];
    {
        const __half* qb = qkv + ((size_t)(b * SEQ + qt * 128 + w * 16)) * QLD + h * DK;
        const __half2 sc = __floats2half2_rn(0.125f, 0.125f);
        #pragma unroll
        for (int ks = 0; ks < 4; ks++) {
            const int c = ks * 16 + 2 * tig;
            __half2 a0 = __hmul2(*(const __half2*)(qb + (size_t)g * QLD + c), sc);
            __half2 a1 = __hmul2(*(const __half2*)(qb + (size_t)(g + 8) * QLD + c), sc);
            __half2 a2 = __hmul2(*(const __half2*)(qb + (size_t)g * QLD + c + 8), sc);
            __half2 a3 = __hmul2(*(const __half2*)(qb + (size_t)(g + 8) * QLD + c + 8), sc);
            qa[ks][0] = *(uint32_t*)&a0; qa[ks][1] = *(uint32_t*)&a1;
            qa[ks][2] = *(uint32_t*)&a2; qa[ks][3] = *(uint32_t*)&a3;
        }
    }

    float o[8][4];
    #pragma unroll
    for (int nt = 0; nt < 8; nt++)
        #pragma unroll
        for (int e = 0; e < 4; e++) o[nt][e] = 0.f;
    float m0 = -1e30f, m1 = -1e30f, l0 = 0.f, l1 = 0.f;

    // K tile: [s][dk] rows; V tile: [s][dk] rows (same layout, consumed via trans)
    auto load_kv = [&](int t, int buf) {
        const uint32_t kdst = sbase + (uint32_t)(buf * K_TILE_HALVES) * 2u;
        const uint32_t vdst = vtsBase + (uint32_t)(buf * V_TILE_HALVES) * 2u;
        const __half* ksrc = qkv + ((size_t)(b * SEQ + t * KV)) * QLD + DM + h * DK;
        const __half* vsrc = qkv + ((size_t)(b * SEQ + t * KV)) * QLD + 2 * DM + h * DK;
        const int kr0 = tid >> 3, kc = tid & 7;
        cp_async16(kdst + (uint32_t)(kr0 * KSH + kc * 8) * 2u,
                   ksrc + (size_t)kr0 * QLD + kc * 8);
        cp_async16(kdst + (uint32_t)((kr0 + 32) * KSH + kc * 8) * 2u,
                   ksrc + (size_t)(kr0 + 32) * QLD + kc * 8);
        cp_async16(vdst + (uint32_t)(kr0 * VSH + kc * 8) * 2u,
                   vsrc + (size_t)kr0 * QLD + kc * 8);
        cp_async16(vdst + (uint32_t)((kr0 + 32) * VSH + kc * 8) * 2u,
                   vsrc + (size_t)(kr0 + 32) * QLD + kc * 8);
    };

    load_kv(0, 0);
    cp_commit();

    const int NKV = SEQ / KV;
    for (int t = 0; t < NKV; t++) {
        asm volatile("cp.async.wait_group 0;" ::: "memory");
        __syncthreads();
        if (t + 1 < NKV) { load_kv(t + 1, (t + 1) & 1); cp_commit(); }

        // ---- S = Q @ K^T (paired x4 K loads) ----
        float s[8][4];
        #pragma unroll
        for (int nt = 0; nt < 8; nt++)
            #pragma unroll
            for (int e = 0; e < 4; e++) s[nt][e] = 0.f;
        {
            const uint32_t kTile = sbase + (uint32_t)((t & 1) * K_TILE_HALVES) * 2u + bRow2;
            #pragma unroll
            for (int ks = 0; ks < 4; ks++) {
                const uint32_t kb = (uint32_t)(ks * 32);
                #pragma unroll
                for (int p = 0; p < 4; p++) {
                    uint32_t bp[4];
                    ldmatrix_x4(bp, kTile + (uint32_t)(p * 16) * 144 + kb);
                    mma_f16_16x8x16(s[2 * p],     qa[ks], bp);
                    mma_f16_16x8x16(s[2 * p + 1], qa[ks], bp + 2);
                }
            }
        }

        // ---- online softmax ----
        float rmax0 = -1e30f, rmax1 = -1e30f;
        #pragma unroll
        for (int nt = 0; nt < 8; nt++) {
            rmax0 = fmaxf(rmax0, fmaxf(s[nt][0], s[nt][1]));
            rmax1 = fmaxf(rmax1, fmaxf(s[nt][2], s[nt][3]));
        }
        rmax0 = fmaxf(rmax0, __shfl_xor_sync(0xffffffffu, rmax0, 1));
        rmax0 = fmaxf(rmax0, __shfl_xor_sync(0xffffffffu, rmax0, 2));
        rmax1 = fmaxf(rmax1, __shfl_xor_sync(0xffffffffu, rmax1, 1));
        rmax1 = fmaxf(rmax1, __shfl_xor_sync(0xffffffffu, rmax1, 2));

        const float mn0 = fmaxf(m0, rmax0);
        const float mn1 = fmaxf(m1, rmax1);
        const float al0 = __expf(m0 - mn0);
        const float al1 = __expf(m1 - mn1);
        m0 = mn0; m1 = mn1;

        float rs0 = 0.f, rs1 = 0.f;
        {
            uint32_t* ps0 = (uint32_t*)Ps + (size_t)(w * 16 + g) * 36 + tig;
            uint32_t* ps1 = ps0 + 8 * 36;
            #pragma unroll
            for (int nt = 0; nt < 8; nt++) {
                const __half2 h0 = __floats2half2_rn(__expf(s[nt][0] - mn0), __expf(s[nt][1] - mn0));
                const __half2 h1 = __floats2half2_rn(__expf(s[nt][2] - mn1), __expf(s[nt][3] - mn1));
                const float2 f0 = __half22float2(h0);
                const float2 f1 = __half22float2(h1);
                rs0 += f0.x + f0.y; rs1 += f1.x + f1.y;
                ps0[nt * 4] = *(const uint32_t*)&h0;
                ps1[nt * 4] = *(const uint32_t*)&h1;
            }
        }
        rs0 += __shfl_xor_sync(0xffffffffu, rs0, 1);
        rs0 += __shfl_xor_sync(0xffffffffu, rs0, 2);
        rs1 += __shfl_xor_sync(0xffffffffu, rs1, 1);
        rs1 += __shfl_xor_sync(0xffffffffu, rs1, 2);
        l0 = l0 * al0 + rs0;
        l1 = l1 * al1 + rs1;

        #pragma unroll
        for (int nt = 0; nt < 8; nt++) {
            o[nt][0] *= al0; o[nt][1] *= al0;
            o[nt][2] *= al1; o[nt][3] *= al1;
        }
        __syncwarp();

        // ---- O += P @ V (V in natural [s][dk] via ldmatrix.trans) ----
        {
            const uint32_t pBase = psBase + (uint32_t)(w * 16) * 144 + aRow;
            const uint32_t vTile = vtsBase + (uint32_t)((t & 1) * V_TILE_HALVES) * 2u + vRowT;
            #pragma unroll
            for (int ks = 0; ks < 4; ks++) {
                uint32_t a[4];
                ldmatrix_x4(a, pBase + (uint32_t)(ks * 32));
                const uint32_t vk = vTile + (uint32_t)(ks * 16) * 144;
                #pragma unroll
                for (int p = 0; p < 4; p++) {
                    uint32_t bp[4];
                    ldmatrix_x4_trans(bp, vk + (uint32_t)(p * 32));
                    mma_f16_16x8x16(o[2 * p],     a, bp);
                    mma_f16_16x8x16(o[2 * p + 1], a, bp + 2);
                }
            }
        }
        __syncwarp();
    }

    // ---- epilogue ----
    {
        const float i0 = 1.0f / l0, i1 = 1.0f / l1;
        const int r0 = qt * 128 + w * 16 + g;
        __half* ob0 = out + ((size_t)(b * SEQ + r0)) * DM + h * DK + 2 * tig;
        __half* ob1 = ob0 + 8 * DM;
        #pragma unroll
        for (int nt = 0; nt < 8; nt++) {
            *(uint32_t*)(ob0 + nt * 8) = pack_h2(o[nt][0] * i0, o[nt][1] * i0);
            *(uint32_t*)(ob1 + nt * 8) = pack_h2(o[nt][2] * i1, o[nt][3] * i1);
        }
    }
}

// ---------------- host launcher ----------------
extern "C" void kernel_launch(void* const* d_in, const int* in_sizes, int n_in,
                              void* d_out, int out_size)
{
    (void)in_sizes; (void)n_in; (void)out_size;
    const float* x     = (const float*)d_in[0];
    const float* Wq    = (const float*)d_in[1];
    const float* bq    = (const float*)d_in[2];
    const float* Wk    = (const float*)d_in[3];
    const float* bk    = (const float*)d_in[4];
    const float* Wv    = (const float*)d_in[5];
    const float* bv    = (const float*)d_in[6];
    const float* Wo    = (const float*)d_in[7];
    const float* bo    = (const float*)d_in[8];
    const float* ln1_g = (const float*)d_in[9];
    const float* ln1_b = (const float*)d_in[10];
    const float* W1    = (const float*)d_in[11];
    const float* b1    = (const float*)d_in[12];
    const float* W2    = (const float*)d_in[13];
    const float* b2    = (const float*)d_in[14];
    const float* ln2_g = (const float*)d_in[15];
    const float* ln2_b = (const float*)d_in[16];
    float* out = (float*)d_out;

    __half *h, *qkv, *ctx, *h2, *ff, *wqkvT, *woT, *w1T, *w2T;
    float *x1, *bqkv;
    cudaGetSymbolAddress((void**)&h,     g_h);
    cudaGetSymbolAddress((void**)&qkv,   g_qkv);
    cudaGetSymbolAddress((void**)&ctx,   g_ctx);
    cudaGetSymbolAddress((void**)&x1,    g_x1);
    cudaGetSymbolAddress((void**)&h2,    g_h2);
    cudaGetSymbolAddress((void**)&ff,    g_ff);
    cudaGetSymbolAddress((void**)&wqkvT, g_wqkvT);
    cudaGetSymbolAddress((void**)&bqkv,  g_bqkv);
    cudaGetSymbolAddress((void**)&woT,   g_woT);
    cudaGetSymbolAddress((void**)&w1T,   g_w1T);
    cudaGetSymbolAddress((void**)&w2T,   g_w2T);

    cudaFuncSetAttribute(attn_f16_kernel, cudaFuncAttributeMaxDynamicSharedMemorySize, ATTN_SMEM);
    cudaFuncSetAttribute(gemm_f16<0,1>, cudaFuncAttributeMaxDynamicSharedMemorySize, GEMM_SMEM_BYTES);
    cudaFuncSetAttribute(gemm_f16<1,0>, cudaFuncAttributeMaxDynamicSharedMemorySize, GEMM_SMEM_BYTES);
    cudaFuncSetAttribute(gemm_f16<2,1>, cudaFuncAttributeMaxDynamicSharedMemorySize, GEMM_SMEM_BYTES);

    const dim3 tB(32, 8);
    const dim3 gQKV(QLD / BN, TOK / BM);    // (48, 64)
    const dim3 gProj(DM / BN, TOK / BM);    // (16, 64)
    const dim3 gFF1(DFF / BN, TOK / BM);    // (64, 64)

    // launch 0: prep QKV weights + bias
    prep1_kernel<<<3075, tB>>>(Wq, Wk, Wv, bq, bk, bv, wqkvT, bqkv);
    // launch 1: LN1 -> fp16
    ln_kernel<<<TOK, 256>>>(x, ln1_g, ln1_b, h);
    // launch 2: fused qkv projection (fp16 out)
    gemm_f16<0,1><<<gQKV, 256, GEMM_SMEM_BYTES>>>(h, wqkvT, bqkv, nullptr, qkv, TOK, QLD, DM);
    // launch 3 (ncu capture): flash attention (V consumed via ldmatrix.trans, no vtrans)
    attn_f16_kernel<<<dim3(SEQ / 128, NH, BATCH), 256, ATTN_SMEM>>>(qkv, ctx);
    // launch 4: prep Wo/W1/W2 (no dep on attention; ordered for profiling only)
    prep2_kernel<<<9216, tB>>>(Wo, W1, W2, woT, w1T, w2T);
    // launch 5: x1 = x + ctx @ Wo + bo (fp32 out)
    gemm_f16<1,0><<<gProj, 256, GEMM_SMEM_BYTES>>>(ctx, woT, bo, x, x1, TOK, DM, DM);
    // launch 6: LN2 -> fp16
    ln_kernel<<<TOK, 256>>>(x1, ln2_g, ln2_b, h2);
    // launch 7: ff = gelu(h2 @ W1 + b1) (fp16 out)
    gemm_f16<2,1><<<gFF1, 256, GEMM_SMEM_BYTES>>>(h2, w1T, b1, nullptr, ff, TOK, DFF, DM);
    // launch 8: out = x1 + ff @ W2 + b2 (fp32 out)
    gemm_f16<1,0><<<gProj, 256, GEMM_SMEM_BYTES>>>(ff, w2T, b2, x1, out, TOK, DM, DFF);
}

// round 12
// speedup vs baseline: 7.6456x; 1.0316x over previous
#include <cuda_runtime.h>
#include <cuda_fp16.h>
#include <math.h>
#include <stdint.h>

#define TOK   8192
#define DM    1024
#define DFF   4096
#define NH    16
#define DK    64
#define SEQ   2048
#define BATCH 4
#define QLD   (3 * DM)

// ---------------- scratch ----------------
__device__ __half g_h   [TOK * DM];
__device__ __half g_qkv [TOK * QLD];
__device__ __half g_ctx [TOK * DM];
__device__ float  g_x1  [TOK * DM];
__device__ __half g_h2  [TOK * DM];
__device__ __half g_ff  [TOK * DFF];
// fp16 weights, transposed to [N][K]
__device__ __half g_wqkvT[QLD * DM];
__device__ float  g_bqkv [QLD];
__device__ __half g_woT  [DM * DM];
__device__ __half g_w1T  [DFF * DM];
__device__ __half g_w2T  [DM * DFF];

// ---------------- helpers ----------------
__device__ __forceinline__ uint32_t smem_u32(const void* p) {
    uint32_t a;
    asm("{ .reg .u64 t; cvta.to.shared.u64 t, %1; cvt.u32.u64 %0, t; }" : "=r"(a) : "l"(p));
    return a;
}
__device__ __forceinline__ void cp_async16(uint32_t dst, const void* src) {
    asm volatile("cp.async.cg.shared.global [%0], [%1], 16;" :: "r"(dst), "l"(src));
}
__device__ __forceinline__ void cp_commit() {
    asm volatile("cp.async.commit_group;" ::: "memory");
}
__device__ __forceinline__ void mma_f16_16x8x16(float* d, const uint32_t* a, const uint32_t* b) {
    asm volatile(
        "mma.sync.aligned.m16n8k16.row.col.f32.f16.f16.f32 "
        "{%0,%1,%2,%3}, {%4,%5,%6,%7}, {%8,%9}, {%0,%1,%2,%3};"
        : "+f"(d[0]), "+f"(d[1]), "+f"(d[2]), "+f"(d[3])
        : "r"(a[0]), "r"(a[1]), "r"(a[2]), "r"(a[3]), "r"(b[0]), "r"(b[1]));
}
__device__ __forceinline__ void ldmatrix_x4(uint32_t* r, uint32_t addr) {
    asm volatile("ldmatrix.sync.aligned.m8n8.x4.shared.b16 {%0,%1,%2,%3}, [%4];"
        : "=r"(r[0]), "=r"(r[1]), "=r"(r[2]), "=r"(r[3]) : "r"(addr));
}
__device__ __forceinline__ void ldmatrix_x4_trans(uint32_t* r, uint32_t addr) {
    asm volatile("ldmatrix.sync.aligned.m8n8.x4.trans.shared.b16 {%0,%1,%2,%3}, [%4];"
        : "=r"(r[0]), "=r"(r[1]), "=r"(r[2]), "=r"(r[3]) : "r"(addr));
}
__device__ __forceinline__ uint32_t pack_h2(float x, float y) {
    __half2 h = __floats2half2_rn(x, y);
    return *(uint32_t*)&h;
}

// ---------------- prep part 1: QKV weights + bias ----------------
__global__ void __launch_bounds__(256) prep1_kernel(
    const float* __restrict__ Wq, const float* __restrict__ Wk, const float* __restrict__ Wv,
    const float* __restrict__ bq, const float* __restrict__ bk, const float* __restrict__ bv,
    __half* __restrict__ wqkvT, float* __restrict__ bqkv)
{
    const int id = blockIdx.x;
    const int tx = threadIdx.x, ty = threadIdx.y;
    if (id >= 3072) {
        const int which = id - 3072;
        const float* src = which == 0 ? bq : (which == 1 ? bk : bv);
        const int t = ty * 32 + tx;
        ((float4*)bqkv)[which * 256 + t] = ((const float4*)src)[t];
        return;
    }
    const int m = id >> 10, lid = id & 1023;
    const float* in = m == 0 ? Wq : (m == 1 ? Wk : Wv);
    __half* out = wqkvT + (size_t)m * DM * DM;
    const int c0 = (lid & 31) * 32, r0 = (lid >> 5) * 32;
    __shared__ float tile[32][33];
    #pragma unroll
    for (int i = ty; i < 32; i += 8)
        tile[i][tx] = in[(size_t)(r0 + i) * DM + c0 + tx];
    __syncthreads();
    #pragma unroll
    for (int i = ty; i < 32; i += 8)
        out[(size_t)(c0 + i) * DM + r0 + tx] = __float2half_rn(tile[tx][i]);
}

// ---------------- prep part 2: Wo/W1/W2 ----------------
__global__ void __launch_bounds__(256) prep2_kernel(
    const float* __restrict__ Wo, const float* __restrict__ W1, const float* __restrict__ W2,
    __half* __restrict__ woT, __half* __restrict__ w1T, __half* __restrict__ w2T)
{
    const int id = blockIdx.x;
    const int tx = threadIdx.x, ty = threadIdx.y;
    const float* in; __half* out; int R, C, lid;
    if (id < 1024)      { lid = id;        in = Wo; out = woT; R = DM;  C = DM;  }
    else if (id < 5120) { lid = id - 1024; in = W1; out = w1T; R = DM;  C = DFF; }
    else                { lid = id - 5120; in = W2; out = w2T; R = DFF; C = DM;  }
    const int tilesx = C / 32;
    const int c0 = (lid % tilesx) * 32, r0 = (lid / tilesx) * 32;
    __shared__ float tile[32][33];
    #pragma unroll
    for (int i = ty; i < 32; i += 8)
        tile[i][tx] = in[(size_t)(r0 + i) * C + c0 + tx];
    __syncthreads();
    #pragma unroll
    for (int i = ty; i < 32; i += 8)
        out[(size_t)(c0 + i) * R + r0 + tx] = __float2half_rn(tile[tx][i]);
}

// ---------------- LayerNorm: fp32 in, fp16 out ----------------
__global__ void __launch_bounds__(256) ln_kernel(const float* __restrict__ x,
                                                 const float* __restrict__ g,
                                                 const float* __restrict__ b,
                                                 __half* __restrict__ out)
{
    const int row = blockIdx.x;
    const int tid = threadIdx.x;
    const float4 v = ((const float4*)(x + (size_t)row * DM))[tid];

    float s  = v.x + v.y + v.z + v.w;
    float ss = v.x * v.x + v.y * v.y + v.z * v.z + v.w * v.w;
    #pragma unroll
    for (int o = 16; o; o >>= 1) {
        s  += __shfl_xor_sync(0xffffffffu, s,  o);
        ss += __shfl_xor_sync(0xffffffffu, ss, o);
    }
    __shared__ float sb[8], sb2[8];
    if ((tid & 31) == 0) { sb[tid >> 5] = s; sb2[tid >> 5] = ss; }
    __syncthreads();
    float ts = 0.f, ts2 = 0.f;
    #pragma unroll
    for (int i = 0; i < 8; i++) { ts += sb[i]; ts2 += sb2[i]; }

    const float mu  = ts * (1.0f / DM);
    const float var = ts2 * (1.0f / DM) - mu * mu;
    const float inv = rsqrtf(var + 1e-5f);

    const float4 gg = ((const float4*)g)[tid];
    const float4 bb = ((const float4*)b)[tid];
    uint32_t p0 = pack_h2((v.x - mu) * inv * gg.x + bb.x, (v.y - mu) * inv * gg.y + bb.y);
    uint32_t p1 = pack_h2((v.z - mu) * inv * gg.z + bb.z, (v.w - mu) * inv * gg.w + bb.w);
    uint2 o; o.x = p0; o.y = p1;
    ((uint2*)(out + (size_t)row * DM))[tid] = o;
}

// ---------------- fp16 GEMM: 128x64 tile, warp 32x32, 2-stage, 3 CTAs/SM ----------------
__device__ __forceinline__ float gelu_exact(float v) {
    return 0.5f * v * (1.0f + erff(v * 0.70710678118654752440f));
}

#define BM 128
#define BN 64
#define BKH 64
#define STAGES 2
#define TSH 72                          // halves per smem row = 144 bytes
#define A_TILE_HALVES (BM * TSH)
#define B_TILE_HALVES (BN * TSH)
#define STAGE_BYTES ((A_TILE_HALVES + B_TILE_HALVES) * 2)
#define GEMM_SMEM_BYTES (STAGES * STAGE_BYTES)

template <int EPI, int OUTH>
__global__ void __launch_bounds__(256, 3) gemm_f16(
    const __half* __restrict__ A, const __half* __restrict__ BT,
    const float* __restrict__ bias, const float* __restrict__ res,
    void* __restrict__ Cv, int M, int N, int K)
{
    extern __shared__ __half smh[];
    const uint32_t sbase = smem_u32(smh);

    const int tid = threadIdx.x;
    const int wid = tid >> 5;
    const int lane = tid & 31;
    const int g = lane >> 2;
    const int tig = lane & 3;
    const int wm = wid & 3;
    const int wn = wid >> 2;

    const uint32_t aRow  = (uint32_t)((lane & 15) * 144 + (lane >> 4) * 16);
    const uint32_t bRow2 = (uint32_t)((lane & 7) * 144 + ((lane >> 3) & 1) * 16 + (lane >> 4) * (8 * 144));

    const int n0 = blockIdx.x * BN;
    const int m0 = blockIdx.y * BM;
    const int NT = K / BKH;

    float acc[2][4][4];
    #pragma unroll
    for (int mt = 0; mt < 2; mt++)
        #pragma unroll
        for (int nt = 0; nt < 4; nt++)
            #pragma unroll
            for (int e = 0; e < 4; e++) acc[mt][nt][e] = 0.f;

    auto load_stage = [&](int st, int t) {
        const uint32_t aoff = sbase + (uint32_t)st * STAGE_BYTES;
        const uint32_t boff = aoff + A_TILE_HALVES * 2;
        #pragma unroll
        for (int i = 0; i < 6; i++) {
            const int idx = i * 256 + tid;
            if (idx < 1024) {
                const int row = idx >> 3, ch = idx & 7;
                cp_async16(aoff + (uint32_t)(row * TSH + ch * 8) * 2u,
                           A + (size_t)(m0 + row) * K + (size_t)t * BKH + ch * 8);
            } else {
                const int j = idx - 1024;
                const int row = j >> 3, ch = j & 7;
                cp_async16(boff + (uint32_t)(row * TSH + ch * 8) * 2u,
                           BT + (size_t)(n0 + row) * K + (size_t)t * BKH + ch * 8);
            }
        }
    };

    load_stage(0, 0);
    cp_commit();

    for (int t = 0; t < NT; t++) {
        asm volatile("cp.async.wait_group 0;" ::: "memory");
        __syncthreads();

        if (t + 1 < NT) { load_stage((t + 1) & 1, t + 1); cp_commit(); }

        const int st = t & 1;
        const uint32_t aBase = sbase + (uint32_t)st * STAGE_BYTES + (uint32_t)(wm * 32) * 144 + aRow;
        const uint32_t bBase = sbase + (uint32_t)st * STAGE_BYTES + A_TILE_HALVES * 2
                             + (uint32_t)(wn * 32) * 144 + bRow2;

        #pragma unroll
        for (int ks = 0; ks < 4; ks++) {
            const uint32_t kb = (uint32_t)(ks * 32);
            uint32_t afr[2][4], bfr[2][4];
            #pragma unroll
            for (int mt = 0; mt < 2; mt++)
                ldmatrix_x4(afr[mt], aBase + (uint32_t)(mt * 16) * 144 + kb);
            #pragma unroll
            for (int p = 0; p < 2; p++)
                ldmatrix_x4(bfr[p], bBase + (uint32_t)(p * 16) * 144 + kb);
            #pragma unroll
            for (int mt = 0; mt < 2; mt++)
                #pragma unroll
                for (int nt = 0; nt < 4; nt++)
                    mma_f16_16x8x16(acc[mt][nt], afr[mt], &bfr[nt >> 1][(nt & 1) * 2]);
        }
    }

    #pragma unroll
    for (int mt = 0; mt < 2; mt++) {
        const int r0 = m0 + wm * 32 + mt * 16 + g;
        const float* rr0 = (EPI == 1) ? (res + (size_t)r0 * N) : nullptr;
        const float* rr1 = (EPI == 1) ? (res + (size_t)(r0 + 8) * N) : nullptr;
        #pragma unroll
        for (int nt = 0; nt < 4; nt++) {
            const int col = n0 + wn * 32 + nt * 8 + 2 * tig;
            const float bx = bias[col], by = bias[col + 1];
            float v0 = acc[mt][nt][0] + bx, v1 = acc[mt][nt][1] + by;
            float v2 = acc[mt][nt][2] + bx, v3 = acc[mt][nt][3] + by;
            if (EPI == 2) {
                v0 = gelu_exact(v0); v1 = gelu_exact(v1);
                v2 = gelu_exact(v2); v3 = gelu_exact(v3);
            }
            if (EPI == 1) {
                v0 += rr0[col]; v1 += rr0[col + 1];
                v2 += rr1[col]; v3 += rr1[col + 1];
            }
            if (OUTH) {
                __half* C = (__half*)Cv;
                *(uint32_t*)(C + (size_t)r0 * N + col)       = pack_h2(v0, v1);
                *(uint32_t*)(C + (size_t)(r0 + 8) * N + col) = pack_h2(v2, v3);
            } else {
                float* C = (float*)Cv;
                *(float2*)(C + (size_t)r0 * N + col)       = make_float2(v0, v1);
                *(float2*)(C + (size_t)(r0 + 8) * N + col) = make_float2(v2, v3);
            }
        }
    }
}

// ---------------- fp16 flash attention: register-resident P (FA2 layout trick) ----------------
#define KV 64
#define KSH 72
#define VSH 72
#define K_TILE_HALVES (KV * KSH)
#define V_TILE_HALVES (KV * VSH)
#define ATTN_SMEM ((2 * K_TILE_HALVES + 2 * V_TILE_HALVES) * 2)   // 36864 B

__global__ void __launch_bounds__(256, 2) attn_f16_kernel(const __half* __restrict__ qkv,
                                                          __half* __restrict__ out)
{
    extern __shared__ __half smh[];
    const uint32_t sbase = smem_u32(smh);
    const uint32_t vtsBase = sbase + 2 * K_TILE_HALVES * 2;

    const int tid = threadIdx.x;
    const int w = tid >> 5;
    const int lane = tid & 31;
    const int g = lane >> 2;
    const int tig = lane & 3;

    const uint32_t bRow2 = (uint32_t)((lane & 7) * 144 + ((lane >> 3) & 1) * 16 + (lane >> 4) * (8 * 144));
    // trans-ldmatrix lane address (V consumed in natural [s][dk] layout)
    const uint32_t vRowT = (uint32_t)(((lane & 7) + ((lane >> 3) & 1) * 8) * 144 + (lane >> 4) * 16);

    const int qt = blockIdx.x, h = blockIdx.y, b = blockIdx.z;

    // ---- Q fragments (scaled by 1/8, exact) ----
    uint32_t qa[4][4];
    {
        const __half* qb = qkv + ((size_t)(b * SEQ + qt * 128 + w * 16)) * QLD + h * DK;
        const __half2 sc = __floats2half2_rn(0.125f, 0.125f);
        #pragma unroll
        for (int ks = 0; ks < 4; ks++) {
            const int c = ks * 16 + 2 * tig;
            __half2 a0 = __hmul2(*(const __half2*)(qb + (size_t)g * QLD + c), sc);
            __half2 a1 = __hmul2(*(const __half2*)(qb + (size_t)(g + 8) * QLD + c), sc);
            __half2 a2 = __hmul2(*(const __half2*)(qb + (size_t)g * QLD + c + 8), sc);
            __half2 a3 = __hmul2(*(const __half2*)(qb + (size_t)(g + 8) * QLD + c + 8), sc);
            qa[ks][0] = *(uint32_t*)&a0; qa[ks][1] = *(uint32_t*)&a1;
            qa[ks][2] = *(uint32_t*)&a2; qa[ks][3] = *(uint32_t*)&a3;
        }
    }

    float o[8][4];
    #pragma unroll
    for (int nt = 0; nt < 8; nt++)
        #pragma unroll
        for (int e = 0; e < 4; e++) o[nt][e] = 0.f;
    float m0 = -1e30f, m1 = -1e30f, l0 = 0.f, l1 = 0.f;

    auto load_kv = [&](int t, int buf) {
        const uint32_t kdst = sbase + (uint32_t)(buf * K_TILE_HALVES) * 2u;
        const uint32_t vdst = vtsBase + (uint32_t)(buf * V_TILE_HALVES) * 2u;
        const __half* ksrc = qkv + ((size_t)(b * SEQ + t * KV)) * QLD + DM + h * DK;
        const __half* vsrc = qkv + ((size_t)(b * SEQ + t * KV)) * QLD + 2 * DM + h * DK;
        const int kr0 = tid >> 3, kc = tid & 7;
        cp_async16(kdst + (uint32_t)(kr0 * KSH + kc * 8) * 2u,
                   ksrc + (size_t)kr0 * QLD + kc * 8);
        cp_async16(kdst + (uint32_t)((kr0 + 32) * KSH + kc * 8) * 2u,
                   ksrc + (size_t)(kr0 + 32) * QLD + kc * 8);
        cp_async16(vdst + (uint32_t)(kr0 * VSH + kc * 8) * 2u,
                   vsrc + (size_t)kr0 * QLD + kc * 8);
        cp_async16(vdst + (uint32_t)((kr0 + 32) * VSH + kc * 8) * 2u,
                   vsrc + (size_t)(kr0 + 32) * QLD + kc * 8);
    };

    load_kv(0, 0);
    cp_commit();

    const int NKV = SEQ / KV;
    for (int t = 0; t < NKV; t++) {
        asm volatile("cp.async.wait_group 0;" ::: "memory");
        __syncthreads();
        if (t + 1 < NKV) { load_kv(t + 1, (t + 1) & 1); cp_commit(); }

        // ---- S = Q @ K^T (paired x4 K loads) ----
        float s[8][4];
        #pragma unroll
        for (int nt = 0; nt < 8; nt++)
            #pragma unroll
            for (int e = 0; e < 4; e++) s[nt][e] = 0.f;
        {
            const uint32_t kTile = sbase + (uint32_t)((t & 1) * K_TILE_HALVES) * 2u + bRow2;
            #pragma unroll
            for (int ks = 0; ks < 4; ks++) {
                const uint32_t kb = (uint32_t)(ks * 32);
                #pragma unroll
                for (int p = 0; p < 4; p++) {
                    uint32_t bp[4];
                    ldmatrix_x4(bp, kTile + (uint32_t)(p * 16) * 144 + kb);
                    mma_f16_16x8x16(s[2 * p],     qa[ks], bp);
                    mma_f16_16x8x16(s[2 * p + 1], qa[ks], bp + 2);
                }
            }
        }

        // ---- online softmax; P stays in registers as PV A-fragments ----
        float rmax0 = -1e30f, rmax1 = -1e30f;
        #pragma unroll
        for (int nt = 0; nt < 8; nt++) {
            rmax0 = fmaxf(rmax0, fmaxf(s[nt][0], s[nt][1]));
            rmax1 = fmaxf(rmax1, fmaxf(s[nt][2], s[nt][3]));
        }
        rmax0 = fmaxf(rmax0, __shfl_xor_sync(0xffffffffu, rmax0, 1));
        rmax0 = fmaxf(rmax0, __shfl_xor_sync(0xffffffffu, rmax0, 2));
        rmax1 = fmaxf(rmax1, __shfl_xor_sync(0xffffffffu, rmax1, 1));
        rmax1 = fmaxf(rmax1, __shfl_xor_sync(0xffffffffu, rmax1, 2));

        const float mn0 = fmaxf(m0, rmax0);
        const float mn1 = fmaxf(m1, rmax1);
        const float al0 = __expf(m0 - mn0);
        const float al1 = __expf(m1 - mn1);
        m0 = mn0; m1 = mn1;

        // exp + pack directly into A-fragment registers:
        // acc s[2ks]{0,1}/{2,3} + s[2ks+1]{0,1}/{2,3}  ==  a0/a1/a2/a3 of k-chunk ks
        uint32_t pa[4][4];
        float rs0 = 0.f, rs1 = 0.f;
        #pragma unroll
        for (int ks = 0; ks < 4; ks++) {
            const float p00 = __expf(s[2 * ks][0] - mn0);
            const float p01 = __expf(s[2 * ks][1] - mn0);
            const float p02 = __expf(s[2 * ks][2] - mn1);
            const float p03 = __expf(s[2 * ks][3] - mn1);
            const float p10 = __expf(s[2 * ks + 1][0] - mn0);
            const float p11 = __expf(s[2 * ks + 1][1] - mn0);
            const float p12 = __expf(s[2 * ks + 1][2] - mn1);
            const float p13 = __expf(s[2 * ks + 1][3] - mn1);
            rs0 += (p00 + p01) + (p10 + p11);
            rs1 += (p02 + p03) + (p12 + p13);
            pa[ks][0] = pack_h2(p00, p01);
            pa[ks][1] = pack_h2(p02, p03);
            pa[ks][2] = pack_h2(p10, p11);
            pa[ks][3] = pack_h2(p12, p13);
        }
        rs0 += __shfl_xor_sync(0xffffffffu, rs0, 1);
        rs0 += __shfl_xor_sync(0xffffffffu, rs0, 2);
        rs1 += __shfl_xor_sync(0xffffffffu, rs1, 1);
        rs1 += __shfl_xor_sync(0xffffffffu, rs1, 2);
        l0 = l0 * al0 + rs0;
        l1 = l1 * al1 + rs1;

        #pragma unroll
        for (int nt = 0; nt < 8; nt++) {
            o[nt][0] *= al0; o[nt][1] *= al0;
            o[nt][2] *= al1; o[nt][3] *= al1;
        }

        // ---- O += P @ V (P from registers; V via ldmatrix.trans) ----
        {
            const uint32_t vTile = vtsBase + (uint32_t)((t & 1) * V_TILE_HALVES) * 2u + vRowT;
            #pragma unroll
            for (int ks = 0; ks < 4; ks++) {
                const uint32_t vk = vTile + (uint32_t)(ks * 16) * 144;
                #pragma unroll
                for (int p = 0; p < 4; p++) {
                    uint32_t bp[4];
                    ldmatrix_x4_trans(bp, vk + (uint32_t)(p * 32));
                    mma_f16_16x8x16(o[2 * p],     pa[ks], bp);
                    mma_f16_16x8x16(o[2 * p + 1], pa[ks], bp + 2);
                }
            }
        }
    }

    // ---- epilogue ----
    {
        const float i0 = 1.0f / l0, i1 = 1.0f / l1;
        const int r0 = qt * 128 + w * 16 + g;
        __half* ob0 = out + ((size_t)(b * SEQ + r0)) * DM + h * DK + 2 * tig;
        __half* ob1 = ob0 + 8 * DM;
        #pragma unroll
        for (int nt = 0; nt < 8; nt++) {
            *(uint32_t*)(ob0 + nt * 8) = pack_h2(o[nt][0] * i0, o[nt][1] * i0);
            *(uint32_t*)(ob1 + nt * 8) = pack_h2(o[nt][2] * i1, o[nt][3] * i1);
        }
    }
}

// ---------------- host launcher ----------------
extern "C" void kernel_launch(void* const* d_in, const int* in_sizes, int n_in,
                              void* d_out, int out_size)
{
    (void)in_sizes; (void)n_in; (void)out_size;
    const float* x     = (const float*)d_in[0];
    const float* Wq    = (const float*)d_in[1];
    const float* bq    = (const float*)d_in[2];
    const float* Wk    = (const float*)d_in[3];
    const float* bk    = (const float*)d_in[4];
    const float* Wv    = (const float*)d_in[5];
    const float* bv    = (const float*)d_in[6];
    const float* Wo    = (const float*)d_in[7];
    const float* bo    = (const float*)d_in[8];
    const float* ln1_g = (const float*)d_in[9];
    const float* ln1_b = (const float*)d_in[10];
    const float* W1    = (const float*)d_in[11];
    const float* b1    = (const float*)d_in[12];
    const float* W2    = (const float*)d_in[13];
    const float* b2    = (const float*)d_in[14];
    const float* ln2_g = (const float*)d_in[15];
    const float* ln2_b = (const float*)d_in[16];
    float* out = (float*)d_out;

    __half *h, *qkv, *ctx, *h2, *ff, *wqkvT, *woT, *w1T, *w2T;
    float *x1, *bqkv;
    cudaGetSymbolAddress((void**)&h,     g_h);
    cudaGetSymbolAddress((void**)&qkv,   g_qkv);
    cudaGetSymbolAddress((void**)&ctx,   g_ctx);
    cudaGetSymbolAddress((void**)&x1,    g_x1);
    cudaGetSymbolAddress((void**)&h2,    g_h2);
    cudaGetSymbolAddress((void**)&ff,    g_ff);
    cudaGetSymbolAddress((void**)&wqkvT, g_wqkvT);
    cudaGetSymbolAddress((void**)&bqkv,  g_bqkv);
    cudaGetSymbolAddress((void**)&woT,   g_woT);
    cudaGetSymbolAddress((void**)&w1T,   g_w1T);
    cudaGetSymbolAddress((void**)&w2T,   g_w2T);

    cudaFuncSetAttribute(attn_f16_kernel, cudaFuncAttributeMaxDynamicSharedMemorySize, ATTN_SMEM);
    cudaFuncSetAttribute(gemm_f16<0,1>, cudaFuncAttributeMaxDynamicSharedMemorySize, GEMM_SMEM_BYTES);
    cudaFuncSetAttribute(gemm_f16<1,0>, cudaFuncAttributeMaxDynamicSharedMemorySize, GEMM_SMEM_BYTES);
    cudaFuncSetAttribute(gemm_f16<2,1>, cudaFuncAttributeMaxDynamicSharedMemorySize, GEMM_SMEM_BYTES);

    const dim3 tB(32, 8);
    const dim3 gQKV(QLD / BN, TOK / BM);    // (48, 64)
    const dim3 gProj(DM / BN, TOK / BM);    // (16, 64)
    const dim3 gFF1(DFF / BN, TOK / BM);    // (64, 64)

    // launch 0: prep QKV weights + bias
    prep1_kernel<<<3075, tB>>>(Wq, Wk, Wv, bq, bk, bv, wqkvT, bqkv);
    // launch 1: LN1 -> fp16
    ln_kernel<<<TOK, 256>>>(x, ln1_g, ln1_b, h);
    // launch 2: fused qkv projection (fp16 out)
    gemm_f16<0,1><<<gQKV, 256, GEMM_SMEM_BYTES>>>(h, wqkvT, bqkv, nullptr, qkv, TOK, QLD, DM);
    // launch 3 (ncu capture): flash attention (register-resident P)
    attn_f16_kernel<<<dim3(SEQ / 128, NH, BATCH), 256, ATTN_SMEM>>>(qkv, ctx);
    // launch 4: prep Wo/W1/W2
    prep2_kernel<<<9216, tB>>>(Wo, W1, W2, woT, w1T, w2T);
    // launch 5: x1 = x + ctx @ Wo + bo (fp32 out)
    gemm_f16<1,0><<<gProj, 256, GEMM_SMEM_BYTES>>>(ctx, woT, bo, x, x1, TOK, DM, DM);
    // launch 6: LN2 -> fp16
    ln_kernel<<<TOK, 256>>>(x1, ln2_g, ln2_b, h2);
    // launch 7: ff = gelu(h2 @ W1 + b1) (fp16 out)
    gemm_f16<2,1><<<gFF1, 256, GEMM_SMEM_BYTES>>>(h2, w1T, b1, nullptr, ff, TOK, DFF, DM);
    // launch 8: out = x1 + ff @ W2 + b2 (fp32 out)
    gemm_f16<1,0><<<gProj, 256, GEMM_SMEM_BYTES>>>(ff, w2T, b2, x1, out, TOK, DM, DFF);
}